// round 1
// baseline (speedup 1.0000x reference)
#include <cuda_runtime.h>
#include <cstdint>

// ---------------------------------------------------------------------------
// Qwen2 FP8 MLP (w8a16 dequant): out = (silu(x@Wg^T*sg) * (x@Wu^T*su)) @ Wd^T * sd
// Strategy: tf32 tensor-core GEMMs (mma.sync.m16n8k8) with fp32 accumulation.
//   Kernel 1: gate_up GEMM fused with per-channel scale + SiLU*Mul -> g_h scratch
//   Kernel 2: down GEMM with per-channel scale -> out
// ---------------------------------------------------------------------------

namespace {
constexpr int HIDDEN = 3584;
constexpr int INTER  = 18944;
constexpr int TOKENS = 4096;

constexpr int BM = 128;
constexpr int BN = 128;          // kernel1: 64 gate cols + 64 up cols
constexpr int BK = 32;
constexpr int LDT = BK + 4;      // padded smem tile row (floats) -> conflict-free
constexpr int STAGES = 3;
constexpr int THREADS = 256;
constexpr int STAGE_FLOATS = (BM + BN) * LDT;
constexpr int SMEM_BYTES = STAGES * STAGE_FLOATS * 4;   // 110,592 B
constexpr int LDC = BN + 4;      // epilogue staging pitch
}

// intermediate activations h[TOKENS][INTER] (fp32 scratch, ~310 MB, bss)
__device__ float g_h[(size_t)TOKENS * (size_t)INTER];

// ---------------------------------------------------------------------------
// small PTX helpers
// ---------------------------------------------------------------------------
__device__ __forceinline__ uint32_t f2tf32(float x) {
    uint32_t u;
    asm("cvt.rna.tf32.f32 %0, %1;" : "=r"(u) : "f"(x));
    return u;
}

__device__ __forceinline__ void cp_async16(float* smem_ptr, const float* gptr) {
    uint32_t s = (uint32_t)__cvta_generic_to_shared(smem_ptr);
    asm volatile("cp.async.cg.shared.global [%0], [%1], 16;\n" :: "r"(s), "l"(gptr));
}
__device__ __forceinline__ void cp_commit() {
    asm volatile("cp.async.commit_group;\n");
}
template <int N>
__device__ __forceinline__ void cp_wait() {
    asm volatile("cp.async.wait_group %0;\n" :: "n"(N));
}

__device__ __forceinline__ void mma_tf32(float* c, const uint32_t* a, const uint32_t* b) {
    asm volatile(
        "mma.sync.aligned.m16n8k8.row.col.f32.tf32.tf32.f32 "
        "{%0,%1,%2,%3}, {%4,%5,%6,%7}, {%8,%9}, {%0,%1,%2,%3};\n"
        : "+f"(c[0]), "+f"(c[1]), "+f"(c[2]), "+f"(c[3])
        : "r"(a[0]), "r"(a[1]), "r"(a[2]), "r"(a[3]),
          "r"(b[0]), "r"(b[1]));
}

// ---------------------------------------------------------------------------
// Kernel 1: C = x @ w_gu^T for paired (gate, up) tiles; epilogue fuses
// per-channel dequant scale + SiLU*Mul; writes h to g_h.
// Grid: (TOKENS/BM, INTER/64). B tile rows 0..63 = gate[n0..], 64..127 = up[n0..].
// ---------------------------------------------------------------------------
__global__ void __launch_bounds__(THREADS, 1)
gateup_silu_kernel(const float* __restrict__ x,
                   const float* __restrict__ w_gu,
                   const float* __restrict__ s_gu)
{
    extern __shared__ float smem[];
    const int m0 = blockIdx.x * BM;
    const int n0 = blockIdx.y * (BN / 2);

    const int t    = threadIdx.x;
    const int lane = t & 31;
    const int wm   = (t >> 5) >> 2;   // 0..1
    const int wn   = (t >> 5) & 3;    // 0..3
    const int g    = lane >> 2;       // 0..7
    const int tg   = lane & 3;        // 0..3

    // global->smem load mapping: each thread copies 4 A rows + 4 B rows, 16B each
    const int lr = t >> 3;            // 0..31
    const int lc = (t & 7) << 2;      // k chunk {0,4,...,28}

    const float* aRow[4];
    const float* bRow[4];
    #pragma unroll
    for (int s = 0; s < 4; s++) {
        int row = lr + 32 * s;
        aRow[s] = x + (size_t)(m0 + row) * HIDDEN + lc;
        int wrow = (row < 64) ? (n0 + row) : (INTER + n0 + (row - 64));
        bRow[s] = w_gu + (size_t)wrow * HIDDEN + lc;
    }

    float acc[4][4][4] = {};
    const int KT = HIDDEN / BK;  // 112

    // prologue: fill STAGES-1 buffers
    #pragma unroll
    for (int st = 0; st < STAGES - 1; st++) {
        float* As = smem + st * STAGE_FLOATS;
        float* Bs = As + BM * LDT;
        #pragma unroll
        for (int s = 0; s < 4; s++) {
            int row = lr + 32 * s;
            cp_async16(As + row * LDT + lc, aRow[s] + st * BK);
            cp_async16(Bs + row * LDT + lc, bRow[s] + st * BK);
        }
        cp_commit();
    }

    for (int kt = 0; kt < KT; kt++) {
        const int ldkt = kt + STAGES - 1;
        if (ldkt < KT) {
            float* As = smem + (ldkt % STAGES) * STAGE_FLOATS;
            float* Bs = As + BM * LDT;
            #pragma unroll
            for (int s = 0; s < 4; s++) {
                int row = lr + 32 * s;
                cp_async16(As + row * LDT + lc, aRow[s] + ldkt * BK);
                cp_async16(Bs + row * LDT + lc, bRow[s] + ldkt * BK);
            }
        }
        cp_commit();                    // commit every iter (empty in tail) so
        cp_wait<STAGES - 1>();          // wait<2> always guarantees stage kt done
        __syncthreads();

        const float* As = smem + (kt % STAGES) * STAGE_FLOATS;
        const float* Bs = As + BM * LDT;
        #pragma unroll
        for (int kk = 0; kk < BK; kk += 8) {
            uint32_t af[4][4], bf[4][2];
            #pragma unroll
            for (int i = 0; i < 4; i++) {
                const float* ap = As + (wm * 64 + i * 16 + g) * LDT + kk + tg;
                af[i][0] = f2tf32(ap[0]);
                af[i][1] = f2tf32(ap[8 * LDT]);
                af[i][2] = f2tf32(ap[4]);
                af[i][3] = f2tf32(ap[8 * LDT + 4]);
            }
            #pragma unroll
            for (int j = 0; j < 4; j++) {
                const float* bp = Bs + (wn * 32 + j * 8 + g) * LDT + kk + tg;
                bf[j][0] = f2tf32(bp[0]);
                bf[j][1] = f2tf32(bp[4]);
            }
            #pragma unroll
            for (int i = 0; i < 4; i++)
                #pragma unroll
                for (int j = 0; j < 4; j++)
                    mma_tf32(acc[i][j], af[i], bf[j]);
        }
        __syncthreads();
    }

    // ---- epilogue: stage acc tile in smem, combine gate/up halves ----
    __syncthreads();
    float* Cs = smem;
    #pragma unroll
    for (int i = 0; i < 4; i++) {
        int r = wm * 64 + i * 16 + g;
        #pragma unroll
        for (int j = 0; j < 4; j++) {
            int c = wn * 32 + j * 8 + 2 * tg;
            Cs[r * LDC + c]           = acc[i][j][0];
            Cs[r * LDC + c + 1]       = acc[i][j][1];
            Cs[(r + 8) * LDC + c]     = acc[i][j][2];
            Cs[(r + 8) * LDC + c + 1] = acc[i][j][3];
        }
    }
    __syncthreads();

    const int cc = t & 63;     // column within the 64-wide half tile
    const int r0 = t >> 6;     // 0..3
    const float sg = s_gu[n0 + cc];
    const float su = s_gu[INTER + n0 + cc];
    float* hout = g_h + (size_t)m0 * INTER + n0 + cc;
    #pragma unroll 4
    for (int r = r0; r < BM; r += 4) {
        float gate = Cs[r * LDC + cc] * sg;
        float up   = Cs[r * LDC + 64 + cc] * su;
        float sig  = 1.0f / (1.0f + __expf(-gate));
        hout[(size_t)r * INTER] = gate * sig * up;
    }
}

// ---------------------------------------------------------------------------
// Kernel 2: out = (g_h @ w_d^T) * s_d.  Grid: (TOKENS/BM, HIDDEN/BN).
// ---------------------------------------------------------------------------
__global__ void __launch_bounds__(THREADS, 1)
down_kernel(const float* __restrict__ w_d,
            const float* __restrict__ s_d,
            float* __restrict__ out)
{
    extern __shared__ float smem[];
    const int m0 = blockIdx.x * BM;
    const int n0 = blockIdx.y * BN;

    const int t    = threadIdx.x;
    const int lane = t & 31;
    const int wm   = (t >> 5) >> 2;
    const int wn   = (t >> 5) & 3;
    const int g    = lane >> 2;
    const int tg   = lane & 3;
    const int lr   = t >> 3;
    const int lc   = (t & 7) << 2;

    const float* aRow[4];
    const float* bRow[4];
    #pragma unroll
    for (int s = 0; s < 4; s++) {
        int row = lr + 32 * s;
        aRow[s] = g_h + (size_t)(m0 + row) * INTER + lc;
        bRow[s] = w_d + (size_t)(n0 + row) * INTER + lc;
    }

    float acc[4][4][4] = {};
    const int KT = INTER / BK;  // 592

    #pragma unroll
    for (int st = 0; st < STAGES - 1; st++) {
        float* As = smem + st * STAGE_FLOATS;
        float* Bs = As + BM * LDT;
        #pragma unroll
        for (int s = 0; s < 4; s++) {
            int row = lr + 32 * s;
            cp_async16(As + row * LDT + lc, aRow[s] + st * BK);
            cp_async16(Bs + row * LDT + lc, bRow[s] + st * BK);
        }
        cp_commit();
    }

    for (int kt = 0; kt < KT; kt++) {
        const int ldkt = kt + STAGES - 1;
        if (ldkt < KT) {
            float* As = smem + (ldkt % STAGES) * STAGE_FLOATS;
            float* Bs = As + BM * LDT;
            #pragma unroll
            for (int s = 0; s < 4; s++) {
                int row = lr + 32 * s;
                cp_async16(As + row * LDT + lc, aRow[s] + ldkt * BK);
                cp_async16(Bs + row * LDT + lc, bRow[s] + ldkt * BK);
            }
        }
        cp_commit();
        cp_wait<STAGES - 1>();
        __syncthreads();

        const float* As = smem + (kt % STAGES) * STAGE_FLOATS;
        const float* Bs = As + BM * LDT;
        #pragma unroll
        for (int kk = 0; kk < BK; kk += 8) {
            uint32_t af[4][4], bf[4][2];
            #pragma unroll
            for (int i = 0; i < 4; i++) {
                const float* ap = As + (wm * 64 + i * 16 + g) * LDT + kk + tg;
                af[i][0] = f2tf32(ap[0]);
                af[i][1] = f2tf32(ap[8 * LDT]);
                af[i][2] = f2tf32(ap[4]);
                af[i][3] = f2tf32(ap[8 * LDT + 4]);
            }
            #pragma unroll
            for (int j = 0; j < 4; j++) {
                const float* bp = Bs + (wn * 32 + j * 8 + g) * LDT + kk + tg;
                bf[j][0] = f2tf32(bp[0]);
                bf[j][1] = f2tf32(bp[4]);
            }
            #pragma unroll
            for (int i = 0; i < 4; i++)
                #pragma unroll
                for (int j = 0; j < 4; j++)
                    mma_tf32(acc[i][j], af[i], bf[j]);
        }
        __syncthreads();
    }

    // ---- epilogue: apply per-output-channel scale, direct stores ----
    #pragma unroll
    for (int i = 0; i < 4; i++) {
        int r = m0 + wm * 64 + i * 16 + g;
        #pragma unroll
        for (int j = 0; j < 4; j++) {
            int c = n0 + wn * 32 + j * 8 + 2 * tg;
            float s0 = s_d[c];
            float s1 = s_d[c + 1];
            float2 v0 = make_float2(acc[i][j][0] * s0, acc[i][j][1] * s1);
            float2 v1 = make_float2(acc[i][j][2] * s0, acc[i][j][3] * s1);
            *reinterpret_cast<float2*>(out + (size_t)r * HIDDEN + c)       = v0;
            *reinterpret_cast<float2*>(out + (size_t)(r + 8) * HIDDEN + c) = v1;
        }
    }
}

// ---------------------------------------------------------------------------
// launch
// ---------------------------------------------------------------------------
extern "C" void kernel_launch(void* const* d_in, const int* in_sizes, int n_in,
                              void* d_out, int out_size)
{
    // Bind inputs by element count (robust to metadata ordering).
    const float* x    = nullptr;
    const float* w_gu = nullptr;
    const float* s_gu = nullptr;
    const float* w_d  = nullptr;
    const float* s_d  = nullptr;
    for (int i = 0; i < n_in; i++) {
        long long sz = in_sizes[i];
        const float* p = (const float*)d_in[i];
        if      (sz == (long long)TOKENS * HIDDEN)     x    = p;
        else if (sz == (long long)2 * INTER * HIDDEN)  w_gu = p;
        else if (sz == (long long)2 * INTER)           s_gu = p;
        else if (sz == (long long)HIDDEN * INTER)      w_d  = p;
        else if (sz == (long long)HIDDEN)              s_d  = p;
    }
    float* out = (float*)d_out;

    cudaFuncSetAttribute(gateup_silu_kernel,
                         cudaFuncAttributeMaxDynamicSharedMemorySize, SMEM_BYTES);
    cudaFuncSetAttribute(down_kernel,
                         cudaFuncAttributeMaxDynamicSharedMemorySize, SMEM_BYTES);

    dim3 grid1(TOKENS / BM, INTER / (BN / 2));   // (32, 296)
    gateup_silu_kernel<<<grid1, THREADS, SMEM_BYTES>>>(x, w_gu, s_gu);

    dim3 grid2(TOKENS / BM, HIDDEN / BN);        // (32, 28)
    down_kernel<<<grid2, THREADS, SMEM_BYTES>>>(w_d, s_d, out);
}

// round 3
// speedup vs baseline: 2.6283x; 2.6283x over previous
#include <cuda_runtime.h>
#include <cstdint>

// ---------------------------------------------------------------------------
// Qwen2 FP8 MLP. Dual-body kernels:
//  * sm_103a pass  -> tcgen05 kind::tf32 SS MMA, TMEM accumulators
//  * sm_103 pass   -> mma.sync.m16n8k8 tf32 fallback (no cvt in mainloop)
// Same grid/block/smem for both, so host launch is arch-agnostic.
// ---------------------------------------------------------------------------

#if defined(__CUDA_ARCH_FEAT_SM103_ALL) || defined(__CUDA_ARCH_FEAT_SM100_ALL) || defined(__CUDA_ARCH_SPECIFIC__)
#define USE_TCGEN05 1
#else
#define USE_TCGEN05 0
#endif

namespace {
constexpr int HIDDEN = 3584;
constexpr int INTER  = 18944;
constexpr int TOKENS = 4096;

constexpr int BM      = 128;
constexpr int KC      = 32;     // K elems per stage (128B row)
constexpr int STAGES  = 4;      // tcgen05 path stages
constexpr int THREADS = 256;

// fallback (mma.sync) tiling
constexpr int FB_BK     = 32;
constexpr int FB_LDT    = FB_BK + 4;
constexpr int FB_STAGES = 3;
constexpr int FB_STAGE_FLOATS = (128 + 128) * FB_LDT;
constexpr int FB_LDC    = 132;
}

__device__ float g_xr[(size_t)TOKENS * HIDDEN];
__device__ float g_h [(size_t)TOKENS * INTER];

// ---------------------------------------------------------------------------
// common helpers
// ---------------------------------------------------------------------------
__device__ __forceinline__ float tf32_rna(float x) {
    uint32_t u;
    asm("cvt.rna.tf32.f32 %0, %1;" : "=r"(u) : "f"(x));
    return __uint_as_float(u);
}
__device__ __forceinline__ void cp_async16u(uint32_t smem_u32, const float* gptr) {
    asm volatile("cp.async.cg.shared.global [%0], [%1], 16;\n" :: "r"(smem_u32), "l"(gptr));
}
__device__ __forceinline__ void cp_async16p(float* smem_ptr, const float* gptr) {
    uint32_t s = (uint32_t)__cvta_generic_to_shared(smem_ptr);
    asm volatile("cp.async.cg.shared.global [%0], [%1], 16;\n" :: "r"(s), "l"(gptr));
}
__device__ __forceinline__ void cp_commit() { asm volatile("cp.async.commit_group;\n"); }
template <int N>
__device__ __forceinline__ void cp_wait() { asm volatile("cp.async.wait_group %0;\n" :: "n"(N)); }

#if USE_TCGEN05
// ---------------------------------------------------------------------------
// tcgen05 helpers (only compiled in the arch-specific pass)
// ---------------------------------------------------------------------------
__device__ __forceinline__ bool elect_one() {
    uint32_t p;
    asm volatile("{\n\t.reg .pred p;\n\telect.sync _|p, 0xFFFFFFFF;\n\t"
                 "selp.b32 %0, 1, 0, p;\n\t}" : "=r"(p));
    return p != 0;
}
__device__ __forceinline__ void mbar_init(uint32_t addr, uint32_t count) {
    asm volatile("mbarrier.init.shared.b64 [%0], %1;" :: "r"(addr), "r"(count) : "memory");
}
__device__ __forceinline__ void mbar_wait(uint32_t addr, uint32_t parity) {
    asm volatile(
        "{\n\t.reg .pred P;\n\t"
        "WL_%=:\n\t"
        "mbarrier.try_wait.parity.acquire.cta.shared::cta.b64 P, [%0], %1, 0x989680;\n\t"
        "@P bra.uni WD_%=;\n\t"
        "bra.uni WL_%=;\n\t"
        "WD_%=:\n\t}"
        :: "r"(addr), "r"(parity) : "memory");
}
__device__ __forceinline__ void tc_alloc(uint32_t dst_smem, uint32_t ncols) {
    asm volatile("tcgen05.alloc.cta_group::1.sync.aligned.shared::cta.b32 [%0], %1;"
                 :: "r"(dst_smem), "r"(ncols) : "memory");
}
__device__ __forceinline__ void tc_relinquish() {
    asm volatile("tcgen05.relinquish_alloc_permit.cta_group::1.sync.aligned;");
}
__device__ __forceinline__ void tc_dealloc(uint32_t tmem, uint32_t ncols) {
    asm volatile("tcgen05.dealloc.cta_group::1.sync.aligned.b32 %0, %1;" :: "r"(tmem), "r"(ncols));
}
__device__ __forceinline__ void tc_commit(uint32_t mbar) {
    asm volatile("tcgen05.commit.cta_group::1.mbarrier::arrive::one.shared::cluster.b64 [%0];"
                 :: "r"(mbar) : "memory");
}
__device__ __forceinline__ void tc_wait_ld() {
    asm volatile("tcgen05.wait::ld.sync.aligned;" ::: "memory");
}
__device__ __forceinline__ uint64_t sdesc(uint32_t addr) {
    return ((uint64_t)((addr >> 4) & 0x3FFF))
         | (1ULL  << 16) | (64ULL << 32) | (1ULL << 46) | (2ULL << 61);  // SW128 K-major
}
__device__ __forceinline__ void mma_tf32_ss(uint32_t d_tmem, uint64_t ad, uint64_t bd,
                                            uint32_t idesc, uint32_t enable_d) {
    asm volatile(
        "{\n\t.reg .pred p;\n\t"
        "setp.ne.u32 p, %4, 0;\n\t"
        "tcgen05.mma.cta_group::1.kind::tf32 [%0], %1, %2, %3, p;\n\t}"
        :: "r"(d_tmem), "l"(ad), "l"(bd), "r"(idesc), "r"(enable_d) : "memory");
}
__device__ __forceinline__ void ldtm32(uint32_t* r, uint32_t ta) {
    asm volatile(
        "tcgen05.ld.sync.aligned.32x32b.x32.b32 "
        "{%0,%1,%2,%3,%4,%5,%6,%7,%8,%9,%10,%11,%12,%13,%14,%15,"
        "%16,%17,%18,%19,%20,%21,%22,%23,%24,%25,%26,%27,%28,%29,%30,%31}, [%32];"
        : "=r"(r[0]),  "=r"(r[1]),  "=r"(r[2]),  "=r"(r[3]),
          "=r"(r[4]),  "=r"(r[5]),  "=r"(r[6]),  "=r"(r[7]),
          "=r"(r[8]),  "=r"(r[9]),  "=r"(r[10]), "=r"(r[11]),
          "=r"(r[12]), "=r"(r[13]), "=r"(r[14]), "=r"(r[15]),
          "=r"(r[16]), "=r"(r[17]), "=r"(r[18]), "=r"(r[19]),
          "=r"(r[20]), "=r"(r[21]), "=r"(r[22]), "=r"(r[23]),
          "=r"(r[24]), "=r"(r[25]), "=r"(r[26]), "=r"(r[27]),
          "=r"(r[28]), "=r"(r[29]), "=r"(r[30]), "=r"(r[31])
        : "r"(ta));
}
#else
// ---------------------------------------------------------------------------
// fallback helper: mma.sync tf32 (inputs pre-rounded; raw fp32 bit patterns)
// ---------------------------------------------------------------------------
__device__ __forceinline__ void mma_fb(float* c, const uint32_t* a, const uint32_t* b) {
    asm volatile(
        "mma.sync.aligned.m16n8k8.row.col.f32.tf32.tf32.f32 "
        "{%0,%1,%2,%3}, {%4,%5,%6,%7}, {%8,%9}, {%0,%1,%2,%3};\n"
        : "+f"(c[0]), "+f"(c[1]), "+f"(c[2]), "+f"(c[3])
        : "r"(a[0]), "r"(a[1]), "r"(a[2]), "r"(a[3]), "r"(b[0]), "r"(b[1]));
}
#endif

// ---------------------------------------------------------------------------
// pre-round x to tf32 (RNA): tensor-core RZ truncation then exact
// ---------------------------------------------------------------------------
__global__ void __launch_bounds__(256) round_x_kernel(const float* __restrict__ x) {
    size_t i = ((size_t)blockIdx.x * 256 + threadIdx.x) * 4;
    float4 v = *reinterpret_cast<const float4*>(x + i);
    v.x = tf32_rna(v.x); v.y = tf32_rna(v.y);
    v.z = tf32_rna(v.z); v.w = tf32_rna(v.w);
    *reinterpret_cast<float4*>(g_xr + i) = v;
}

// ---------------------------------------------------------------------------
// MODE 0: gate_up + SiLU*Mul -> g_h.  grid (TOKENS/128, INTER/128)
// MODE 1: down + scale -> out.        grid (TOKENS/128, HIDDEN/128)
// ---------------------------------------------------------------------------
template <int MODE>
__global__ void __launch_bounds__(THREADS, 1)
mlp_gemm(const float* __restrict__ W, const float* __restrict__ S,
         float* __restrict__ Out)
{
    extern __shared__ float smemf[];
    const int t    = threadIdx.x;
    const int wid  = t >> 5;
    const int lane = t & 31;
    const int m0   = blockIdx.x * BM;
    const float* A = (MODE == 0) ? g_xr : g_h;
    constexpr int KTOT = (MODE == 0) ? HIDDEN : INTER;

#if USE_TCGEN05
    // =======================================================================
    // tcgen05 path
    // =======================================================================
    constexpr int NB   = (MODE == 0) ? 256 : 128;   // B rows == MMA N
    constexpr int KT   = KTOT / KC;
    constexpr uint32_t IDESC =
        (1u << 4) | (2u << 7) | (2u << 10)          // d=F32, a=b=TF32
        | ((uint32_t)(NB / 8) << 17) | ((uint32_t)(BM / 16) << 24);
    constexpr int A_BYTES = BM * KC * 4;
    constexpr int B_BYTES = NB * KC * 4;
    constexpr int STAGE_BYTES = A_BYTES + B_BYTES;
    constexpr int NAL = (BM * 8) / THREADS;
    constexpr int NBL = (NB * 8) / THREADS;

    const uint32_t sbase     = (uint32_t)__cvta_generic_to_shared(smemf);
    const uint32_t tptr_addr = sbase;
    const uint32_t bar_empty = sbase + 8;
    const uint32_t bar_done  = sbase + 8 + STAGES * 8;
    const uint32_t data_u    = (sbase + 64 + 1023) & ~1023u;  // 1KB-align tiles

    const int n0 = blockIdx.y * 128;

    if (wid == 0) { tc_alloc(tptr_addr, NB); tc_relinquish(); }
    if (t == 0) {
        for (int s = 0; s < STAGES; s++) mbar_init(bar_empty + s * 8, 1);
        mbar_init(bar_done, 1);
    }
    __syncthreads();
    uint32_t tmem;
    asm volatile("ld.shared.b32 %0, [%1];" : "=r"(tmem) : "r"(tptr_addr));

    const float* aptr[NAL]; uint32_t asw[NAL];
    const float* bptr[NBL]; uint32_t bsw[NBL];
    #pragma unroll
    for (int i = 0; i < NAL; i++) {
        int idx = t + THREADS * i;
        int row = idx >> 3, ch = idx & 7;
        aptr[i] = A + (size_t)(m0 + row) * KTOT + ch * 4;
        uint32_t off = row * 128 + ch * 16;
        asw[i] = off ^ ((off >> 3) & 0x70);
    }
    #pragma unroll
    for (int i = 0; i < NBL; i++) {
        int idx = t + THREADS * i;
        int row = idx >> 3, ch = idx & 7;
        int grow = (MODE == 0) ? ((row < 128) ? (n0 + row) : (INTER + n0 + row - 128))
                               : (n0 + row);
        bptr[i] = W + (size_t)grow * KTOT + ch * 4;
        uint32_t off = row * 128 + ch * 16;
        bsw[i] = off ^ ((off >> 3) & 0x70);
    }

    #pragma unroll
    for (int st = 0; st < STAGES - 1; st++) {
        uint32_t As = data_u + st * STAGE_BYTES;
        uint32_t Bs = As + A_BYTES;
        #pragma unroll
        for (int i = 0; i < NAL; i++) cp_async16u(As + asw[i], aptr[i] + st * KC);
        #pragma unroll
        for (int i = 0; i < NBL; i++) cp_async16u(Bs + bsw[i], bptr[i] + st * KC);
        cp_commit();
    }

    #pragma unroll 1
    for (int kt = 0; kt < KT; kt++) {
        const int ldkt = kt + STAGES - 1;
        if (ldkt < KT) {
            const int s = ldkt % STAGES;
            if (ldkt >= STAGES) {
                uint32_t ph = ((uint32_t)(ldkt / STAGES) - 1) & 1;
                mbar_wait(bar_empty + s * 8, ph);
            }
            uint32_t As = data_u + s * STAGE_BYTES;
            uint32_t Bs = As + A_BYTES;
            #pragma unroll
            for (int i = 0; i < NAL; i++) cp_async16u(As + asw[i], aptr[i] + ldkt * KC);
            #pragma unroll
            for (int i = 0; i < NBL; i++) cp_async16u(Bs + bsw[i], bptr[i] + ldkt * KC);
        }
        cp_commit();
        cp_wait<STAGES - 1>();
        asm volatile("fence.proxy.async.shared::cta;" ::: "memory");
        __syncthreads();

        if (wid == 1) {
            if (elect_one()) {
                const int s = kt % STAGES;
                uint32_t a_u = data_u + s * STAGE_BYTES;
                uint64_t ad = sdesc(a_u);
                uint64_t bd = sdesc(a_u + A_BYTES);
                #pragma unroll
                for (int kk = 0; kk < 4; kk++) {          // 4 x K=8 == KC
                    uint32_t en = !(kt == 0 && kk == 0);
                    mma_tf32_ss(tmem, ad + kk * 2, bd + kk * 2, IDESC, en);
                }
                tc_commit(bar_empty + s * 8);
            }
        }
    }

    if (wid == 1) { if (elect_one()) tc_commit(bar_done); }
    mbar_wait(bar_done, 0);
    asm volatile("tcgen05.fence::after_thread_sync;" ::: "memory");

    const int sp   = wid & 3;
    const int half = wid >> 2;
    const size_t mrow = (size_t)m0 + sp * 32 + lane;

    if (MODE == 0) {
        #pragma unroll
        for (int chunk = 0; chunk < 2; chunk++) {
            const int cb = half * 64 + chunk * 32;
            uint32_t gr[32], ur[32];
            ldtm32(gr, tmem + cb);
            ldtm32(ur, tmem + 128 + cb);
            tc_wait_ld();
            float4* op = reinterpret_cast<float4*>(g_h + mrow * INTER + n0 + cb);
            #pragma unroll
            for (int q = 0; q < 8; q++) {
                float r[4];
                #pragma unroll
                for (int j = 0; j < 4; j++) {
                    int i = q * 4 + j;
                    int n = n0 + cb + i;
                    float gate = __uint_as_float(gr[i]) * __ldg(S + n);
                    float up   = __uint_as_float(ur[i]) * __ldg(S + INTER + n);
                    float sig  = 1.0f / (1.0f + __expf(-gate));
                    r[j] = tf32_rna(gate * sig * up);
                }
                op[q] = make_float4(r[0], r[1], r[2], r[3]);
            }
        }
    } else {
        #pragma unroll
        for (int chunk = 0; chunk < 2; chunk++) {
            const int cb = half * 64 + chunk * 32;
            uint32_t dr[32];
            ldtm32(dr, tmem + cb);
            tc_wait_ld();
            float4* op = reinterpret_cast<float4*>(Out + mrow * HIDDEN + n0 + cb);
            #pragma unroll
            for (int q = 0; q < 8; q++) {
                float r[4];
                #pragma unroll
                for (int j = 0; j < 4; j++) {
                    int i = q * 4 + j;
                    r[j] = __uint_as_float(dr[i]) * __ldg(S + n0 + cb + i);
                }
                op[q] = make_float4(r[0], r[1], r[2], r[3]);
            }
        }
    }

    __syncthreads();
    if (wid == 0) tc_dealloc(tmem, NB);

#else
    // =======================================================================
    // fallback path: mma.sync.m16n8k8.tf32, pre-rounded inputs (no cvt)
    // =======================================================================
    const int wm = (t >> 5) >> 2, wn = (t >> 5) & 3;
    const int g  = lane >> 2,     tg = lane & 3;
    const int lr = t >> 3,        lc = (t & 7) << 2;
    constexpr int NSUB = (MODE == 0) ? 2 : 1;   // MODE0: two 64-col halves

    #pragma unroll 1
    for (int sub = 0; sub < NSUB; sub++) {
        const int n0 = blockIdx.y * 128 + ((MODE == 0) ? sub * 64 : 0);

        const float* aRow[4]; const float* bRow[4];
        #pragma unroll
        for (int s = 0; s < 4; s++) {
            int row = lr + 32 * s;
            aRow[s] = A + (size_t)(m0 + row) * KTOT + lc;
            int wrow;
            if (MODE == 0) wrow = (row < 64) ? (n0 + row) : (INTER + n0 + (row - 64));
            else           wrow = n0 + row;
            bRow[s] = W + (size_t)wrow * KTOT + lc;
        }

        float acc[4][4][4] = {};
        const int KT = KTOT / FB_BK;

        __syncthreads();
        #pragma unroll
        for (int st = 0; st < FB_STAGES - 1; st++) {
            float* As = smemf + st * FB_STAGE_FLOATS;
            float* Bs = As + 128 * FB_LDT;
            #pragma unroll
            for (int s = 0; s < 4; s++) {
                int row = lr + 32 * s;
                cp_async16p(As + row * FB_LDT + lc, aRow[s] + st * FB_BK);
                cp_async16p(Bs + row * FB_LDT + lc, bRow[s] + st * FB_BK);
            }
            cp_commit();
        }

        #pragma unroll 1
        for (int kt = 0; kt < KT; kt++) {
            const int ldkt = kt + FB_STAGES - 1;
            if (ldkt < KT) {
                float* As = smemf + (ldkt % FB_STAGES) * FB_STAGE_FLOATS;
                float* Bs = As + 128 * FB_LDT;
                #pragma unroll
                for (int s = 0; s < 4; s++) {
                    int row = lr + 32 * s;
                    cp_async16p(As + row * FB_LDT + lc, aRow[s] + ldkt * FB_BK);
                    cp_async16p(Bs + row * FB_LDT + lc, bRow[s] + ldkt * FB_BK);
                }
            }
            cp_commit();
            cp_wait<FB_STAGES - 1>();
            __syncthreads();

            const float* As = smemf + (kt % FB_STAGES) * FB_STAGE_FLOATS;
            const float* Bs = As + 128 * FB_LDT;
            #pragma unroll
            for (int kk = 0; kk < FB_BK; kk += 8) {
                uint32_t af[4][4], bf[4][2];
                #pragma unroll
                for (int i = 0; i < 4; i++) {
                    const float* ap = As + (wm * 64 + i * 16 + g) * FB_LDT + kk + tg;
                    af[i][0] = __float_as_uint(ap[0]);
                    af[i][1] = __float_as_uint(ap[8 * FB_LDT]);
                    af[i][2] = __float_as_uint(ap[4]);
                    af[i][3] = __float_as_uint(ap[8 * FB_LDT + 4]);
                }
                #pragma unroll
                for (int j = 0; j < 4; j++) {
                    const float* bp = Bs + (wn * 32 + j * 8 + g) * FB_LDT + kk + tg;
                    bf[j][0] = __float_as_uint(bp[0]);
                    bf[j][1] = __float_as_uint(bp[4]);
                }
                #pragma unroll
                for (int i = 0; i < 4; i++)
                    #pragma unroll
                    for (int j = 0; j < 4; j++)
                        mma_fb(acc[i][j], af[i], bf[j]);
            }
            __syncthreads();
        }

        if (MODE == 0) {
            // stage C in smem, fuse scales + SiLU*Mul
            __syncthreads();
            float* Cs = smemf;
            #pragma unroll
            for (int i = 0; i < 4; i++) {
                int r = wm * 64 + i * 16 + g;
                #pragma unroll
                for (int j = 0; j < 4; j++) {
                    int c = wn * 32 + j * 8 + 2 * tg;
                    Cs[r * FB_LDC + c]           = acc[i][j][0];
                    Cs[r * FB_LDC + c + 1]       = acc[i][j][1];
                    Cs[(r + 8) * FB_LDC + c]     = acc[i][j][2];
                    Cs[(r + 8) * FB_LDC + c + 1] = acc[i][j][3];
                }
            }
            __syncthreads();
            const int cc = t & 63;
            const int r0 = t >> 6;
            const float sg = S[n0 + cc];
            const float su = S[INTER + n0 + cc];
            float* hout = g_h + (size_t)m0 * INTER + n0 + cc;
            #pragma unroll 4
            for (int r = r0; r < BM; r += 4) {
                float gate = Cs[r * FB_LDC + cc] * sg;
                float up   = Cs[r * FB_LDC + 64 + cc] * su;
                float sig  = 1.0f / (1.0f + __expf(-gate));
                hout[(size_t)r * INTER] = tf32_rna(gate * sig * up);
            }
            __syncthreads();
        } else {
            #pragma unroll
            for (int i = 0; i < 4; i++) {
                int r = m0 + wm * 64 + i * 16 + g;
                #pragma unroll
                for (int j = 0; j < 4; j++) {
                    int c = n0 + wn * 32 + j * 8 + 2 * tg;
                    float s0 = S[c], s1 = S[c + 1];
                    float2 v0 = make_float2(acc[i][j][0] * s0, acc[i][j][1] * s1);
                    float2 v1 = make_float2(acc[i][j][2] * s0, acc[i][j][3] * s1);
                    *reinterpret_cast<float2*>(Out + (size_t)r * HIDDEN + c)       = v0;
                    *reinterpret_cast<float2*>(Out + (size_t)(r + 8) * HIDDEN + c) = v1;
                }
            }
        }
    }
#endif
}

// ---------------------------------------------------------------------------
// launch
// ---------------------------------------------------------------------------
extern "C" void kernel_launch(void* const* d_in, const int* in_sizes, int n_in,
                              void* d_out, int out_size)
{
    const float* x = nullptr; const float* w_gu = nullptr; const float* s_gu = nullptr;
    const float* w_d = nullptr; const float* s_d = nullptr;
    for (int i = 0; i < n_in; i++) {
        long long sz = in_sizes[i];
        const float* p = (const float*)d_in[i];
        if      (sz == (long long)TOKENS * HIDDEN)    x    = p;
        else if (sz == (long long)2 * INTER * HIDDEN) w_gu = p;
        else if (sz == (long long)2 * INTER)          s_gu = p;
        else if (sz == (long long)HIDDEN * INTER)     w_d  = p;
        else if (sz == (long long)HIDDEN)             s_d  = p;
    }
    float* out = (float*)d_out;

    // smem: max(tcgen05 needs, fallback needs)
    constexpr int SMEM0 = 2048 + STAGES * (128 * KC * 4 + 256 * KC * 4); // 198,656
    constexpr int SMEM1 = 2048 + STAGES * (128 * KC * 4 + 128 * KC * 4); // 133,120

    cudaFuncSetAttribute(mlp_gemm<0>, cudaFuncAttributeMaxDynamicSharedMemorySize, SMEM0);
    cudaFuncSetAttribute(mlp_gemm<1>, cudaFuncAttributeMaxDynamicSharedMemorySize, SMEM1);

    round_x_kernel<<<(TOKENS * HIDDEN) / (256 * 4), 256>>>(x);

    dim3 g1(TOKENS / BM, INTER / 128);      // (32, 148)
    mlp_gemm<0><<<g1, THREADS, SMEM0>>>(w_gu, s_gu, nullptr);

    dim3 g2(TOKENS / BM, HIDDEN / 128);     // (32, 28)
    mlp_gemm<1><<<g2, THREADS, SMEM1>>>(w_d, s_d, out);
}

// round 4
// speedup vs baseline: 3.7235x; 1.4167x over previous
#include <cuda_runtime.h>
#include <cuda_bf16.h>
#include <cstdint>

// ---------------------------------------------------------------------------
// Qwen2 FP8 MLP, bf16-split tcgen05 version.
//   Weights (fp8-grid values) are EXACT in bf16  -> convert once to bf16.
//   Activations split: x = x_hi(bf16) + x_lo(bf16 residual), err <= 2^-16 rel.
//   Each GEMM = two kind::f16 MMA accumulations into one fp32 TMEM acc.
//   This halves B-side L2 traffic (the R3 bottleneck) at equal tensor time.
// ---------------------------------------------------------------------------

#if defined(__CUDA_ARCH_FEAT_SM103_ALL) || defined(__CUDA_ARCH_FEAT_SM100_ALL) || defined(__CUDA_ARCH_SPECIFIC__)
#define USE_TCGEN05 1
#else
#define USE_TCGEN05 0
#endif

namespace {
constexpr int HIDDEN = 3584;
constexpr int INTER  = 18944;
constexpr int TOKENS = 4096;

constexpr int BM      = 128;
constexpr int KC      = 64;      // K elems per stage (64 bf16 = 128B SW128 row)
constexpr int THREADS = 256;
}

__device__ __nv_bfloat16 g_xh[(size_t)TOKENS * HIDDEN];
__device__ __nv_bfloat16 g_xl[(size_t)TOKENS * HIDDEN];
__device__ __nv_bfloat16 g_wgu[(size_t)2 * INTER * HIDDEN];
__device__ __nv_bfloat16 g_wd [(size_t)HIDDEN * INTER];
__device__ __nv_bfloat16 g_hh[(size_t)TOKENS * INTER];
__device__ __nv_bfloat16 g_hl[(size_t)TOKENS * INTER];

// ---------------------------------------------------------------------------
// helpers
// ---------------------------------------------------------------------------
__device__ __forceinline__ void cp_async16u(uint32_t smem_u32, const void* gptr) {
    asm volatile("cp.async.cg.shared.global [%0], [%1], 16;\n" :: "r"(smem_u32), "l"(gptr));
}
__device__ __forceinline__ void cp_commit() { asm volatile("cp.async.commit_group;\n"); }
template <int N>
__device__ __forceinline__ void cp_wait() { asm volatile("cp.async.wait_group %0;\n" :: "n"(N)); }

#if USE_TCGEN05
__device__ __forceinline__ bool elect_one() {
    uint32_t p;
    asm volatile("{\n\t.reg .pred p;\n\telect.sync _|p, 0xFFFFFFFF;\n\t"
                 "selp.b32 %0, 1, 0, p;\n\t}" : "=r"(p));
    return p != 0;
}
__device__ __forceinline__ void mbar_init(uint32_t addr, uint32_t count) {
    asm volatile("mbarrier.init.shared.b64 [%0], %1;" :: "r"(addr), "r"(count) : "memory");
}
__device__ __forceinline__ void mbar_wait(uint32_t addr, uint32_t parity) {
    asm volatile(
        "{\n\t.reg .pred P;\n\t"
        "WL_%=:\n\t"
        "mbarrier.try_wait.parity.acquire.cta.shared::cta.b64 P, [%0], %1, 0x989680;\n\t"
        "@P bra.uni WD_%=;\n\t"
        "bra.uni WL_%=;\n\t"
        "WD_%=:\n\t}"
        :: "r"(addr), "r"(parity) : "memory");
}
__device__ __forceinline__ void tc_alloc(uint32_t dst_smem, uint32_t ncols) {
    asm volatile("tcgen05.alloc.cta_group::1.sync.aligned.shared::cta.b32 [%0], %1;"
                 :: "r"(dst_smem), "r"(ncols) : "memory");
}
__device__ __forceinline__ void tc_relinquish() {
    asm volatile("tcgen05.relinquish_alloc_permit.cta_group::1.sync.aligned;");
}
__device__ __forceinline__ void tc_dealloc(uint32_t tmem, uint32_t ncols) {
    asm volatile("tcgen05.dealloc.cta_group::1.sync.aligned.b32 %0, %1;" :: "r"(tmem), "r"(ncols));
}
__device__ __forceinline__ void tc_commit(uint32_t mbar) {
    asm volatile("tcgen05.commit.cta_group::1.mbarrier::arrive::one.shared::cluster.b64 [%0];"
                 :: "r"(mbar) : "memory");
}
__device__ __forceinline__ void tc_wait_ld() {
    asm volatile("tcgen05.wait::ld.sync.aligned;" ::: "memory");
}
__device__ __forceinline__ uint64_t sdesc(uint32_t addr) {
    return ((uint64_t)((addr >> 4) & 0x3FFF))
         | (1ULL  << 16) | (64ULL << 32) | (1ULL << 46) | (2ULL << 61);  // SW128 K-major
}
// kind::f16 SS MMA, bf16 x bf16 -> fp32
__device__ __forceinline__ void mma_bf16_ss(uint32_t d_tmem, uint64_t ad, uint64_t bd,
                                            uint32_t idesc, uint32_t enable_d) {
    asm volatile(
        "{\n\t.reg .pred p;\n\t"
        "setp.ne.u32 p, %4, 0;\n\t"
        "tcgen05.mma.cta_group::1.kind::f16 [%0], %1, %2, %3, p;\n\t}"
        :: "r"(d_tmem), "l"(ad), "l"(bd), "r"(idesc), "r"(enable_d) : "memory");
}
__device__ __forceinline__ void ldtm32(uint32_t* r, uint32_t ta) {
    asm volatile(
        "tcgen05.ld.sync.aligned.32x32b.x32.b32 "
        "{%0,%1,%2,%3,%4,%5,%6,%7,%8,%9,%10,%11,%12,%13,%14,%15,"
        "%16,%17,%18,%19,%20,%21,%22,%23,%24,%25,%26,%27,%28,%29,%30,%31}, [%32];"
        : "=r"(r[0]),  "=r"(r[1]),  "=r"(r[2]),  "=r"(r[3]),
          "=r"(r[4]),  "=r"(r[5]),  "=r"(r[6]),  "=r"(r[7]),
          "=r"(r[8]),  "=r"(r[9]),  "=r"(r[10]), "=r"(r[11]),
          "=r"(r[12]), "=r"(r[13]), "=r"(r[14]), "=r"(r[15]),
          "=r"(r[16]), "=r"(r[17]), "=r"(r[18]), "=r"(r[19]),
          "=r"(r[20]), "=r"(r[21]), "=r"(r[22]), "=r"(r[23]),
          "=r"(r[24]), "=r"(r[25]), "=r"(r[26]), "=r"(r[27]),
          "=r"(r[28]), "=r"(r[29]), "=r"(r[30]), "=r"(r[31])
        : "r"(ta));
}
#endif

// ---------------------------------------------------------------------------
// prep: fp32 weights -> bf16 (exact, weights live on fp8 grid)
// ---------------------------------------------------------------------------
__global__ void __launch_bounds__(256) conv_w_kernel(const float* __restrict__ src,
                                                     __nv_bfloat16* __restrict__ dst) {
    size_t i = ((size_t)blockIdx.x * 256 + threadIdx.x) * 8;
    float4 a = *reinterpret_cast<const float4*>(src + i);
    float4 b = *reinterpret_cast<const float4*>(src + i + 4);
    __nv_bfloat162 p0 = __floats2bfloat162_rn(a.x, a.y);
    __nv_bfloat162 p1 = __floats2bfloat162_rn(a.z, a.w);
    __nv_bfloat162 p2 = __floats2bfloat162_rn(b.x, b.y);
    __nv_bfloat162 p3 = __floats2bfloat162_rn(b.z, b.w);
    uint4 v = make_uint4(*reinterpret_cast<uint32_t*>(&p0), *reinterpret_cast<uint32_t*>(&p1),
                         *reinterpret_cast<uint32_t*>(&p2), *reinterpret_cast<uint32_t*>(&p3));
    *reinterpret_cast<uint4*>(dst + i) = v;
}

// prep: x -> (hi, lo) bf16 pair
__global__ void __launch_bounds__(256) split_x_kernel(const float* __restrict__ x) {
    size_t i = ((size_t)blockIdx.x * 256 + threadIdx.x) * 4;
    float4 v = *reinterpret_cast<const float4*>(x + i);
    __nv_bfloat16 h0 = __float2bfloat16_rn(v.x), h1 = __float2bfloat16_rn(v.y);
    __nv_bfloat16 h2 = __float2bfloat16_rn(v.z), h3 = __float2bfloat16_rn(v.w);
    __nv_bfloat16 l0 = __float2bfloat16_rn(v.x - __bfloat162float(h0));
    __nv_bfloat16 l1 = __float2bfloat16_rn(v.y - __bfloat162float(h1));
    __nv_bfloat16 l2 = __float2bfloat16_rn(v.z - __bfloat162float(h2));
    __nv_bfloat16 l3 = __float2bfloat16_rn(v.w - __bfloat162float(h3));
    __nv_bfloat162 hh0 = __halves2bfloat162(h0, h1), hh1 = __halves2bfloat162(h2, h3);
    __nv_bfloat162 ll0 = __halves2bfloat162(l0, l1), ll1 = __halves2bfloat162(l2, l3);
    *reinterpret_cast<uint2*>(g_xh + i) =
        make_uint2(*reinterpret_cast<uint32_t*>(&hh0), *reinterpret_cast<uint32_t*>(&hh1));
    *reinterpret_cast<uint2*>(g_xl + i) =
        make_uint2(*reinterpret_cast<uint32_t*>(&ll0), *reinterpret_cast<uint32_t*>(&ll1));
}

// ---------------------------------------------------------------------------
// MODE 0: gate_up (512 B rows = 256 gate + 256 up; D0/D1 in TMEM) + SiLU*Mul
//         -> h split into (g_hh, g_hl).   grid (32, 74), 2 stages.
// MODE 1: down (256 B rows) -> out fp32.  grid (32, 14), 3 stages.
// ---------------------------------------------------------------------------
template <int MODE>
__global__ void __launch_bounds__(THREADS, 1)
mlp_gemm(const float* __restrict__ S, float* __restrict__ Out)
{
    constexpr int KTOT = (MODE == 0) ? HIDDEN : INTER;
    extern __shared__ char smem[];
    const int t    = threadIdx.x;
    const int wid  = t >> 5;
    const int lane = t & 31;
    const int m0   = blockIdx.x * BM;
    const int n0   = blockIdx.y * 256;

#if USE_TCGEN05
    constexpr int NB   = (MODE == 0) ? 512 : 256;   // B rows in smem
    constexpr int NSTG = (MODE == 0) ? 2 : 3;
    constexpr int KT   = KTOT / KC;
    constexpr int A_BYTES     = 2 * BM * 128;        // hi + lo, 128B/row
    constexpr int B_BYTES     = NB * 128;
    constexpr int STAGE_BYTES = A_BYTES + B_BYTES;
    constexpr int NDCOLS = (MODE == 0) ? 512 : 256;
    constexpr uint32_t IDESC =
        (1u << 4) | (1u << 7) | (1u << 10)           // d=F32, a=b=BF16
        | (32u << 17) | (8u << 24);                  // N=256, M=128

    const uint32_t sbase     = (uint32_t)__cvta_generic_to_shared(smem);
    const uint32_t tptr_addr = sbase;
    const uint32_t bar_empty = sbase + 8;
    const uint32_t bar_done  = bar_empty + NSTG * 8;
    const uint32_t data_u    = (sbase + 64 + 1023) & ~1023u;

    if (wid == 0) { tc_alloc(tptr_addr, NDCOLS); tc_relinquish(); }
    if (t == 0) {
        for (int s = 0; s < NSTG; s++) mbar_init(bar_empty + s * 8, 1);
        mbar_init(bar_done, 1);
    }
    __syncthreads();
    uint32_t tmem;
    asm volatile("ld.shared.b32 %0, [%1];" : "=r"(tmem) : "r"(tptr_addr));

    // per-thread load bases: row r0 + 32*i, fixed 16B chunk ch
    const int r0 = t >> 3;
    const int ch = t & 7;
    uint32_t sw0 = (uint32_t)(r0 * 128 + ch * 16);
    sw0 ^= (sw0 >> 3) & 0x70;

    const __nv_bfloat16* ah = g_xh;
    const __nv_bfloat16* al = g_xl;
    if (MODE == 1) { ah = g_hh; al = g_hl; }
    ah += (size_t)(m0 + r0) * KTOT + ch * 8;
    al += (size_t)(m0 + r0) * KTOT + ch * 8;
    const __nv_bfloat16* b0p;
    const __nv_bfloat16* b1p = nullptr;
    if (MODE == 0) {
        b0p = g_wgu + (size_t)(n0 + r0) * KTOT + ch * 8;          // gate rows
        b1p = g_wgu + (size_t)(INTER + n0 + r0) * KTOT + ch * 8;  // up rows
    } else {
        b0p = g_wd + (size_t)(n0 + r0) * KTOT + ch * 8;
    }

    auto load_stage = [&](int s, int kt) {
        const uint32_t As = data_u + s * STAGE_BYTES;
        const uint32_t Bs = As + A_BYTES;
        const size_t ko = (size_t)kt * KC;
        #pragma unroll
        for (int i = 0; i < 4; i++)
            cp_async16u(As + sw0 + 4096u * i, ah + (size_t)i * 32 * KTOT + ko);
        #pragma unroll
        for (int i = 0; i < 4; i++)
            cp_async16u(As + 16384 + sw0 + 4096u * i, al + (size_t)i * 32 * KTOT + ko);
        #pragma unroll
        for (int i = 0; i < 8; i++)
            cp_async16u(Bs + sw0 + 4096u * i, b0p + (size_t)i * 32 * KTOT + ko);
        if (MODE == 0) {
            #pragma unroll
            for (int i = 0; i < 8; i++)
                cp_async16u(Bs + 32768 + sw0 + 4096u * i, b1p + (size_t)i * 32 * KTOT + ko);
        }
    };

    #pragma unroll
    for (int st = 0; st < NSTG - 1; st++) { load_stage(st, st); cp_commit(); }

    #pragma unroll 1
    for (int kt = 0; kt < KT; kt++) {
        const int ldkt = kt + NSTG - 1;
        if (ldkt < KT) {
            const int s = ldkt % NSTG;
            if (ldkt >= NSTG) {
                uint32_t ph = ((uint32_t)(ldkt / NSTG) - 1) & 1;
                mbar_wait(bar_empty + s * 8, ph);
            }
            load_stage(s, ldkt);
        }
        cp_commit();
        cp_wait<NSTG - 1>();
        asm volatile("fence.proxy.async.shared::cta;" ::: "memory");
        __syncthreads();

        if (wid == 1) {
            if (elect_one()) {
                const int s = kt % NSTG;
                const uint32_t a_u = data_u + s * STAGE_BYTES;
                const uint64_t adh = sdesc(a_u);
                const uint64_t adl = sdesc(a_u + 16384);
                const uint64_t bd  = sdesc(a_u + A_BYTES);
                #pragma unroll
                for (int kk = 0; kk < 4; kk++) {       // 4 x K=16 == KC
                    const uint32_t en = (kt > 0 || kk > 0) ? 1u : 0u;
                    mma_bf16_ss(tmem,       adh + 2 * kk, bd + 2 * kk,        IDESC, en);
                    mma_bf16_ss(tmem,       adl + 2 * kk, bd + 2 * kk,        IDESC, 1);
                    if (MODE == 0) {
                        mma_bf16_ss(tmem + 256, adh + 2 * kk, bd + 2048 + 2 * kk, IDESC, en);
                        mma_bf16_ss(tmem + 256, adl + 2 * kk, bd + 2048 + 2 * kk, IDESC, 1);
                    }
                }
                tc_commit(bar_empty + s * 8);
            }
        }
    }

    if (wid == 1) { if (elect_one()) tc_commit(bar_done); }
    mbar_wait(bar_done, 0);
    asm volatile("tcgen05.fence::after_thread_sync;" ::: "memory");

    // ---- epilogue: warp (sp, half); rows sp*32+lane, col half*128 + c*32 ----
    const int sp   = wid & 3;
    const int half = wid >> 2;
    const size_t mrow = (size_t)m0 + sp * 32 + lane;

    #pragma unroll
    for (int c = 0; c < 4; c++) {
        const int cb = half * 128 + c * 32;
        if (MODE == 0) {
            uint32_t gr[32], ur[32];
            ldtm32(gr, tmem + cb);          // gate: D0
            ldtm32(ur, tmem + 256 + cb);    // up:   D1
            tc_wait_ld();
            uint32_t oh[16], ol[16];
            #pragma unroll
            for (int p = 0; p < 16; p++) {
                const int i = 2 * p;
                const int n = n0 + cb + i;
                float g0 = __uint_as_float(gr[i])     * __ldg(S + n);
                float g1 = __uint_as_float(gr[i + 1]) * __ldg(S + n + 1);
                float u0 = __uint_as_float(ur[i])     * __ldg(S + INTER + n);
                float u1 = __uint_as_float(ur[i + 1]) * __ldg(S + INTER + n + 1);
                float h0 = g0 * (1.0f / (1.0f + __expf(-g0))) * u0;
                float h1 = g1 * (1.0f / (1.0f + __expf(-g1))) * u1;
                __nv_bfloat16 bh0 = __float2bfloat16_rn(h0);
                __nv_bfloat16 bh1 = __float2bfloat16_rn(h1);
                __nv_bfloat16 bl0 = __float2bfloat16_rn(h0 - __bfloat162float(bh0));
                __nv_bfloat16 bl1 = __float2bfloat16_rn(h1 - __bfloat162float(bh1));
                __nv_bfloat162 ph = __halves2bfloat162(bh0, bh1);
                __nv_bfloat162 pl = __halves2bfloat162(bl0, bl1);
                oh[p] = *reinterpret_cast<uint32_t*>(&ph);
                ol[p] = *reinterpret_cast<uint32_t*>(&pl);
            }
            const size_t off = mrow * INTER + n0 + cb;
            #pragma unroll
            for (int q = 0; q < 4; q++) {
                reinterpret_cast<uint4*>(g_hh + off)[q] =
                    make_uint4(oh[4 * q], oh[4 * q + 1], oh[4 * q + 2], oh[4 * q + 3]);
                reinterpret_cast<uint4*>(g_hl + off)[q] =
                    make_uint4(ol[4 * q], ol[4 * q + 1], ol[4 * q + 2], ol[4 * q + 3]);
            }
        } else {
            uint32_t dr[32];
            ldtm32(dr, tmem + cb);
            tc_wait_ld();
            float* op = Out + mrow * HIDDEN + n0 + cb;
            #pragma unroll
            for (int q = 0; q < 8; q++) {
                float r[4];
                #pragma unroll
                for (int j = 0; j < 4; j++) {
                    const int i = q * 4 + j;
                    r[j] = __uint_as_float(dr[i]) * __ldg(S + n0 + cb + i);
                }
                reinterpret_cast<float4*>(op)[q] = make_float4(r[0], r[1], r[2], r[3]);
            }
        }
    }

    __syncthreads();
    if (wid == 0) tc_dealloc(tmem, NDCOLS);

#else
    // -----------------------------------------------------------------------
    // non-103a compile pass only (never selected at runtime on GB300):
    // correct scalar fallback.
    // -----------------------------------------------------------------------
    (void)smem; (void)wid; (void)lane;
    for (int o = t; o < BM * 256; o += THREADS) {
        const int r = o >> 8, c = o & 255;
        if (MODE == 0) {
            const __nv_bfloat16* arh = g_xh + (size_t)(m0 + r) * KTOT;
            const __nv_bfloat16* arl = g_xl + (size_t)(m0 + r) * KTOT;
            const __nv_bfloat16* wg  = g_wgu + (size_t)(n0 + c) * KTOT;
            const __nv_bfloat16* wu  = g_wgu + (size_t)(INTER + n0 + c) * KTOT;
            float accg = 0.f, accu = 0.f;
            for (int k = 0; k < KTOT; k++) {
                float a = __bfloat162float(arh[k]) + __bfloat162float(arl[k]);
                accg += a * __bfloat162float(wg[k]);
                accu += a * __bfloat162float(wu[k]);
            }
            float g = accg * S[n0 + c], u = accu * S[INTER + n0 + c];
            float h = g * (1.0f / (1.0f + __expf(-g))) * u;
            __nv_bfloat16 bh = __float2bfloat16_rn(h);
            g_hh[(size_t)(m0 + r) * INTER + n0 + c] = bh;
            g_hl[(size_t)(m0 + r) * INTER + n0 + c] =
                __float2bfloat16_rn(h - __bfloat162float(bh));
        } else {
            const __nv_bfloat16* arh = g_hh + (size_t)(m0 + r) * KTOT;
            const __nv_bfloat16* arl = g_hl + (size_t)(m0 + r) * KTOT;
            const __nv_bfloat16* wr  = g_wd + (size_t)(n0 + c) * KTOT;
            float acc = 0.f;
            for (int k = 0; k < KTOT; k++) {
                float a = __bfloat162float(arh[k]) + __bfloat162float(arl[k]);
                acc += a * __bfloat162float(wr[k]);
            }
            Out[(size_t)(m0 + r) * HIDDEN + n0 + c] = acc * S[n0 + c];
        }
    }
#endif
}

// ---------------------------------------------------------------------------
// launch
// ---------------------------------------------------------------------------
extern "C" void kernel_launch(void* const* d_in, const int* in_sizes, int n_in,
                              void* d_out, int out_size)
{
    const float* x = nullptr; const float* w_gu = nullptr; const float* s_gu = nullptr;
    const float* w_d = nullptr; const float* s_d = nullptr;
    for (int i = 0; i < n_in; i++) {
        long long sz = in_sizes[i];
        const float* p = (const float*)d_in[i];
        if      (sz == (long long)TOKENS * HIDDEN)    x    = p;
        else if (sz == (long long)2 * INTER * HIDDEN) w_gu = p;
        else if (sz == (long long)2 * INTER)          s_gu = p;
        else if (sz == (long long)HIDDEN * INTER)     w_d  = p;
        else if (sz == (long long)HIDDEN)             s_d  = p;
    }
    float* out = (float*)d_out;

    __nv_bfloat16* d_wgu = nullptr;
    __nv_bfloat16* d_wd  = nullptr;
    cudaGetSymbolAddress((void**)&d_wgu, g_wgu);
    cudaGetSymbolAddress((void**)&d_wd,  g_wd);

    constexpr int SMEM = 2048 + 2 * (2 * 128 * 128 + 512 * 128);   // 198,656 (both modes)
    cudaFuncSetAttribute(mlp_gemm<0>, cudaFuncAttributeMaxDynamicSharedMemorySize, SMEM);
    cudaFuncSetAttribute(mlp_gemm<1>, cudaFuncAttributeMaxDynamicSharedMemorySize, SMEM);

    // prep: weights -> bf16 (exact), x -> hi/lo bf16
    conv_w_kernel<<<(2LL * INTER * HIDDEN) / (256 * 8), 256>>>(w_gu, d_wgu);
    conv_w_kernel<<<((long long)HIDDEN * INTER) / (256 * 8), 256>>>(w_d, d_wd);
    split_x_kernel<<<(TOKENS * HIDDEN) / (256 * 4), 256>>>(x);

    // GEMM1: gate_up + SiLU*Mul -> (g_hh, g_hl)
    dim3 g1(TOKENS / BM, INTER / 256);     // (32, 74) = 2368 CTAs = 16 exact waves
    mlp_gemm<0><<<g1, THREADS, SMEM>>>(s_gu, nullptr);

    // GEMM2: down -> out
    dim3 g2(TOKENS / BM, HIDDEN / 256);    // (32, 14)
    mlp_gemm<1><<<g2, THREADS, SMEM>>>(s_d, out);
}

// round 5
// speedup vs baseline: 5.5859x; 1.5002x over previous
#include <cuda_runtime.h>
#include <cuda_fp16.h>
#include <cstdint>

// ---------------------------------------------------------------------------
// Qwen2 FP8 MLP, all-fp16 single-pass tcgen05 version.
//   e4m3-grid weights are EXACT in fp16; fp16 mantissa (11 bit) == tf32, so
//   numerics match the validated R1 tf32 run (rel_err 3.7e-4).
//   BM=256 (two M=128 MMAs, TMEM cols [0,256)+[256,512)) halves B traffic.
//   GEMM1: x16 @ w_gu^T (128 gate + 128 up = N256) + SiLU*Mul -> h fp16
//   GEMM2: h16 @ w_d^T (N=256) -> out fp32
// ---------------------------------------------------------------------------

#if defined(__CUDA_ARCH_FEAT_SM103_ALL) || defined(__CUDA_ARCH_FEAT_SM100_ALL) || defined(__CUDA_ARCH_SPECIFIC__)
#define USE_TCGEN05 1
#else
#define USE_TCGEN05 0
#endif

namespace {
constexpr int HIDDEN = 3584;
constexpr int INTER  = 18944;
constexpr int TOKENS = 4096;

constexpr int BM      = 256;
constexpr int KC      = 64;      // 64 fp16 = 128B SW128 row
constexpr int NSTG    = 3;
constexpr int THREADS = 256;
constexpr int STAGE_BYTES = 65536;   // A 32KB + B 32KB
}

__device__ __half g_x16[(size_t)TOKENS * HIDDEN];
__device__ __half g_wgu[(size_t)2 * INTER * HIDDEN];
__device__ __half g_wd [(size_t)HIDDEN * INTER];
__device__ __half g_h16[(size_t)TOKENS * INTER];

// ---------------------------------------------------------------------------
// helpers
// ---------------------------------------------------------------------------
__device__ __forceinline__ void cp_async16u(uint32_t smem_u32, const void* gptr) {
    asm volatile("cp.async.cg.shared.global [%0], [%1], 16;\n" :: "r"(smem_u32), "l"(gptr));
}
__device__ __forceinline__ void cp_commit() { asm volatile("cp.async.commit_group;\n"); }
template <int N>
__device__ __forceinline__ void cp_wait() { asm volatile("cp.async.wait_group %0;\n" :: "n"(N)); }

#if USE_TCGEN05
__device__ __forceinline__ bool elect_one() {
    uint32_t p;
    asm volatile("{\n\t.reg .pred p;\n\telect.sync _|p, 0xFFFFFFFF;\n\t"
                 "selp.b32 %0, 1, 0, p;\n\t}" : "=r"(p));
    return p != 0;
}
__device__ __forceinline__ void mbar_init(uint32_t addr, uint32_t count) {
    asm volatile("mbarrier.init.shared.b64 [%0], %1;" :: "r"(addr), "r"(count) : "memory");
}
__device__ __forceinline__ void mbar_wait(uint32_t addr, uint32_t parity) {
    asm volatile(
        "{\n\t.reg .pred P;\n\t"
        "WL_%=:\n\t"
        "mbarrier.try_wait.parity.acquire.cta.shared::cta.b64 P, [%0], %1, 0x989680;\n\t"
        "@P bra.uni WD_%=;\n\t"
        "bra.uni WL_%=;\n\t"
        "WD_%=:\n\t}"
        :: "r"(addr), "r"(parity) : "memory");
}
__device__ __forceinline__ void tc_alloc(uint32_t dst_smem, uint32_t ncols) {
    asm volatile("tcgen05.alloc.cta_group::1.sync.aligned.shared::cta.b32 [%0], %1;"
                 :: "r"(dst_smem), "r"(ncols) : "memory");
}
__device__ __forceinline__ void tc_relinquish() {
    asm volatile("tcgen05.relinquish_alloc_permit.cta_group::1.sync.aligned;");
}
__device__ __forceinline__ void tc_dealloc(uint32_t tmem, uint32_t ncols) {
    asm volatile("tcgen05.dealloc.cta_group::1.sync.aligned.b32 %0, %1;" :: "r"(tmem), "r"(ncols));
}
__device__ __forceinline__ void tc_commit(uint32_t mbar) {
    asm volatile("tcgen05.commit.cta_group::1.mbarrier::arrive::one.shared::cluster.b64 [%0];"
                 :: "r"(mbar) : "memory");
}
__device__ __forceinline__ void tc_wait_ld() {
    asm volatile("tcgen05.wait::ld.sync.aligned;" ::: "memory");
}
__device__ __forceinline__ uint64_t sdesc(uint32_t addr) {
    return ((uint64_t)((addr >> 4) & 0x3FFF))
         | (1ULL  << 16) | (64ULL << 32) | (1ULL << 46) | (2ULL << 61);  // SW128 K-major
}
// kind::f16 SS MMA, fp16 x fp16 -> fp32  (atype=btype=F16=0)
__device__ __forceinline__ void mma_f16_ss(uint32_t d_tmem, uint64_t ad, uint64_t bd,
                                           uint32_t idesc, uint32_t enable_d) {
    asm volatile(
        "{\n\t.reg .pred p;\n\t"
        "setp.ne.u32 p, %4, 0;\n\t"
        "tcgen05.mma.cta_group::1.kind::f16 [%0], %1, %2, %3, p;\n\t}"
        :: "r"(d_tmem), "l"(ad), "l"(bd), "r"(idesc), "r"(enable_d) : "memory");
}
__device__ __forceinline__ void ldtm32(uint32_t* r, uint32_t ta) {
    asm volatile(
        "tcgen05.ld.sync.aligned.32x32b.x32.b32 "
        "{%0,%1,%2,%3,%4,%5,%6,%7,%8,%9,%10,%11,%12,%13,%14,%15,"
        "%16,%17,%18,%19,%20,%21,%22,%23,%24,%25,%26,%27,%28,%29,%30,%31}, [%32];"
        : "=r"(r[0]),  "=r"(r[1]),  "=r"(r[2]),  "=r"(r[3]),
          "=r"(r[4]),  "=r"(r[5]),  "=r"(r[6]),  "=r"(r[7]),
          "=r"(r[8]),  "=r"(r[9]),  "=r"(r[10]), "=r"(r[11]),
          "=r"(r[12]), "=r"(r[13]), "=r"(r[14]), "=r"(r[15]),
          "=r"(r[16]), "=r"(r[17]), "=r"(r[18]), "=r"(r[19]),
          "=r"(r[20]), "=r"(r[21]), "=r"(r[22]), "=r"(r[23]),
          "=r"(r[24]), "=r"(r[25]), "=r"(r[26]), "=r"(r[27]),
          "=r"(r[28]), "=r"(r[29]), "=r"(r[30]), "=r"(r[31])
        : "r"(ta));
}
#endif

// ---------------------------------------------------------------------------
// prep: fp32 -> fp16 (weights exact on e4m3 grid; x RN-rounded, 2^-11)
// ---------------------------------------------------------------------------
__global__ void __launch_bounds__(256) conv16_kernel(const float* __restrict__ src,
                                                     __half* __restrict__ dst) {
    size_t i = ((size_t)blockIdx.x * 256 + threadIdx.x) * 8;
    float4 a = *reinterpret_cast<const float4*>(src + i);
    float4 b = *reinterpret_cast<const float4*>(src + i + 4);
    __half2 p0 = __floats2half2_rn(a.x, a.y);
    __half2 p1 = __floats2half2_rn(a.z, a.w);
    __half2 p2 = __floats2half2_rn(b.x, b.y);
    __half2 p3 = __floats2half2_rn(b.z, b.w);
    uint4 v = make_uint4(*reinterpret_cast<uint32_t*>(&p0), *reinterpret_cast<uint32_t*>(&p1),
                         *reinterpret_cast<uint32_t*>(&p2), *reinterpret_cast<uint32_t*>(&p3));
    *reinterpret_cast<uint4*>(dst + i) = v;
}

// ---------------------------------------------------------------------------
// MODE 0: gate_up + SiLU*Mul -> g_h16.  grid (16, 148)  [n0 = y*128 h-cols]
// MODE 1: down -> out fp32.             grid (16, 14)   [n0 = y*256 out-cols]
// Both: BM=256, B tile 256 rows, two M=128 MMAs -> TMEM 512 cols.
// ---------------------------------------------------------------------------
template <int MODE>
__global__ void __launch_bounds__(THREADS, 1)
mlp_gemm(const float* __restrict__ S, float* __restrict__ Out)
{
    constexpr int KTOT = (MODE == 0) ? HIDDEN : INTER;
    extern __shared__ char smem[];
    const int t    = threadIdx.x;
    const int wid  = t >> 5;
    const int lane = t & 31;
    const int m0   = blockIdx.x * BM;
    const int n0   = blockIdx.y * ((MODE == 0) ? 128 : 256);

#if USE_TCGEN05
    constexpr int KT = KTOT / KC;
    constexpr uint32_t IDESC =
        (1u << 4)                     // d = F32; atype=btype=F16 (0)
        | (32u << 17) | (8u << 24);   // N=256, M=128

    const uint32_t sbase     = (uint32_t)__cvta_generic_to_shared(smem);
    const uint32_t tptr_addr = sbase;
    const uint32_t bar_empty = sbase + 8;
    const uint32_t bar_done  = bar_empty + NSTG * 8;
    const uint32_t data_u    = (sbase + 64 + 1023) & ~1023u;

    if (wid == 0) { tc_alloc(tptr_addr, 512); tc_relinquish(); }
    if (t == 0) {
        for (int s = 0; s < NSTG; s++) mbar_init(bar_empty + s * 8, 1);
        mbar_init(bar_done, 1);
    }
    __syncthreads();
    uint32_t tmem;
    asm volatile("ld.shared.b32 %0, [%1];" : "=r"(tmem) : "r"(tptr_addr));

    // per-thread load slots: rows r0+32i (i<8), fixed 16B chunk ch
    const int r0 = t >> 3;
    const int ch = t & 7;
    uint32_t sw0 = (uint32_t)(r0 * 128 + ch * 16);
    sw0 ^= (sw0 >> 3) & 0x70;

    const __half* ap = ((MODE == 0) ? g_x16 : g_h16)
                     + (size_t)(m0 + r0) * KTOT + ch * 8;
    const __half* bp[8];
    #pragma unroll
    for (int i = 0; i < 8; i++) {
        int row = r0 + 32 * i;
        int grow;
        if (MODE == 0) grow = (row < 128) ? (n0 + row) : (INTER + n0 + (row - 128));
        else           grow = n0 + row;
        bp[i] = ((MODE == 0) ? g_wgu : g_wd) + (size_t)grow * KTOT + ch * 8;
    }

    auto load_stage = [&](int s, int kt) {
        const uint32_t As = data_u + s * STAGE_BYTES;
        const uint32_t Bs = As + 32768;
        const size_t ko = (size_t)kt * KC;
        #pragma unroll
        for (int i = 0; i < 8; i++)
            cp_async16u(As + sw0 + 4096u * i, ap + (size_t)(32 * i) * KTOT + ko);
        #pragma unroll
        for (int i = 0; i < 8; i++)
            cp_async16u(Bs + sw0 + 4096u * i, bp[i] + ko);
    };

    #pragma unroll
    for (int st = 0; st < NSTG - 1; st++) { load_stage(st, st); cp_commit(); }

    #pragma unroll 1
    for (int kt = 0; kt < KT; kt++) {
        const int ldkt = kt + NSTG - 1;
        if (ldkt < KT) {
            const int s = ldkt % NSTG;
            if (ldkt >= NSTG) {
                uint32_t ph = ((uint32_t)(ldkt / NSTG) - 1) & 1;
                mbar_wait(bar_empty + s * 8, ph);
            }
            load_stage(s, ldkt);
        }
        cp_commit();
        cp_wait<NSTG - 1>();
        asm volatile("fence.proxy.async.shared::cta;" ::: "memory");
        __syncthreads();

        if (wid == 1) {
            if (elect_one()) {
                const int s = kt % NSTG;
                const uint32_t a_u = data_u + s * STAGE_BYTES;
                const uint64_t ad0 = sdesc(a_u);            // M rows   0..127
                const uint64_t ad1 = sdesc(a_u + 16384);    // M rows 128..255
                const uint64_t bd  = sdesc(a_u + 32768);
                #pragma unroll
                for (int kk = 0; kk < 4; kk++) {            // 4 x K=16 == KC
                    const uint32_t en = (kt > 0 || kk > 0) ? 1u : 0u;
                    mma_f16_ss(tmem,       ad0 + 2 * kk, bd + 2 * kk, IDESC, en);
                    mma_f16_ss(tmem + 256, ad1 + 2 * kk, bd + 2 * kk, IDESC, en);
                }
                tc_commit(bar_empty + s * 8);
            }
        }
    }

    if (wid == 1) { if (elect_one()) tc_commit(bar_done); }
    mbar_wait(bar_done, 0);
    asm volatile("tcgen05.fence::after_thread_sync;" ::: "memory");

    // ---- epilogue: warp = (mhalf, subpartition) ----
    const int mh = wid >> 2;                 // 0,1 -> TMEM tile 0/1
    const int sp = wid & 3;
    const size_t mrow = (size_t)m0 + mh * 128 + sp * 32 + lane;
    const uint32_t tbase = tmem + mh * 256;

    if (MODE == 0) {
        #pragma unroll
        for (int c = 0; c < 4; c++) {
            const int cb = c * 32;
            uint32_t gr[32], ur[32];
            ldtm32(gr, tbase + cb);            // gate: D cols [0,128)
            ldtm32(ur, tbase + 128 + cb);      // up:   D cols [128,256)
            tc_wait_ld();
            uint32_t oh[16];
            #pragma unroll
            for (int p = 0; p < 16; p++) {
                const int i = 2 * p;
                const int n = n0 + cb + i;
                float g0 = __uint_as_float(gr[i])     * __ldg(S + n);
                float g1 = __uint_as_float(gr[i + 1]) * __ldg(S + n + 1);
                float u0 = __uint_as_float(ur[i])     * __ldg(S + INTER + n);
                float u1 = __uint_as_float(ur[i + 1]) * __ldg(S + INTER + n + 1);
                float h0 = g0 * (1.0f / (1.0f + __expf(-g0))) * u0;
                float h1 = g1 * (1.0f / (1.0f + __expf(-g1))) * u1;
                __half2 ph = __floats2half2_rn(h0, h1);
                oh[p] = *reinterpret_cast<uint32_t*>(&ph);
            }
            const size_t off = mrow * INTER + n0 + cb;
            #pragma unroll
            for (int q = 0; q < 4; q++)
                reinterpret_cast<uint4*>(g_h16 + off)[q] =
                    make_uint4(oh[4 * q], oh[4 * q + 1], oh[4 * q + 2], oh[4 * q + 3]);
        }
    } else {
        #pragma unroll
        for (int c = 0; c < 8; c++) {
            const int cb = c * 32;
            uint32_t dr[32];
            ldtm32(dr, tbase + cb);
            tc_wait_ld();
            float* op = Out + mrow * HIDDEN + n0 + cb;
            #pragma unroll
            for (int q = 0; q < 8; q++) {
                float r[4];
                #pragma unroll
                for (int j = 0; j < 4; j++) {
                    const int i = q * 4 + j;
                    r[j] = __uint_as_float(dr[i]) * __ldg(S + n0 + cb + i);
                }
                reinterpret_cast<float4*>(op)[q] = make_float4(r[0], r[1], r[2], r[3]);
            }
        }
    }

    __syncthreads();
    if (wid == 0) tc_dealloc(tmem, 512);

#else
    // non-103a compile pass only (never selected at runtime on GB300)
    (void)smem; (void)wid; (void)lane;
    constexpr int NCOL = (MODE == 0) ? 128 : 256;
    for (int o = t; o < BM * NCOL; o += THREADS) {
        const int r = o / NCOL, c = o % NCOL;
        if (MODE == 0) {
            const __half* ar = g_x16 + (size_t)(m0 + r) * KTOT;
            const __half* wg = g_wgu + (size_t)(n0 + c) * KTOT;
            const __half* wu = g_wgu + (size_t)(INTER + n0 + c) * KTOT;
            float accg = 0.f, accu = 0.f;
            for (int k = 0; k < KTOT; k++) {
                float a = __half2float(ar[k]);
                accg += a * __half2float(wg[k]);
                accu += a * __half2float(wu[k]);
            }
            float g = accg * S[n0 + c], u = accu * S[INTER + n0 + c];
            float h = g * (1.0f / (1.0f + __expf(-g))) * u;
            g_h16[(size_t)(m0 + r) * INTER + n0 + c] = __float2half_rn(h);
        } else {
            const __half* ar = g_h16 + (size_t)(m0 + r) * KTOT;
            const __half* wr = g_wd + (size_t)(n0 + c) * KTOT;
            float acc = 0.f;
            for (int k = 0; k < KTOT; k++)
                acc += __half2float(ar[k]) * __half2float(wr[k]);
            Out[(size_t)(m0 + r) * HIDDEN + n0 + c] = acc * S[n0 + c];
        }
    }
#endif
}

// ---------------------------------------------------------------------------
// launch
// ---------------------------------------------------------------------------
extern "C" void kernel_launch(void* const* d_in, const int* in_sizes, int n_in,
                              void* d_out, int out_size)
{
    const float* x = nullptr; const float* w_gu = nullptr; const float* s_gu = nullptr;
    const float* w_d = nullptr; const float* s_d = nullptr;
    for (int i = 0; i < n_in; i++) {
        long long sz = in_sizes[i];
        const float* p = (const float*)d_in[i];
        if      (sz == (long long)TOKENS * HIDDEN)    x    = p;
        else if (sz == (long long)2 * INTER * HIDDEN) w_gu = p;
        else if (sz == (long long)2 * INTER)          s_gu = p;
        else if (sz == (long long)HIDDEN * INTER)     w_d  = p;
        else if (sz == (long long)HIDDEN)             s_d  = p;
    }
    float* out = (float*)d_out;

    __half* d_x16 = nullptr; __half* d_wgu = nullptr; __half* d_wd = nullptr;
    cudaGetSymbolAddress((void**)&d_x16, g_x16);
    cudaGetSymbolAddress((void**)&d_wgu, g_wgu);
    cudaGetSymbolAddress((void**)&d_wd,  g_wd);

    constexpr int SMEM = 2048 + NSTG * STAGE_BYTES;   // 198,656
    cudaFuncSetAttribute(mlp_gemm<0>, cudaFuncAttributeMaxDynamicSharedMemorySize, SMEM);
    cudaFuncSetAttribute(mlp_gemm<1>, cudaFuncAttributeMaxDynamicSharedMemorySize, SMEM);

    // prep: fp32 -> fp16
    conv16_kernel<<<(2LL * INTER * HIDDEN) / (256 * 8), 256>>>(w_gu, d_wgu);
    conv16_kernel<<<((long long)HIDDEN * INTER) / (256 * 8), 256>>>(w_d, d_wd);
    conv16_kernel<<<((long long)TOKENS * HIDDEN) / (256 * 8), 256>>>(x, d_x16);

    // GEMM1: gate_up + SiLU*Mul -> g_h16
    dim3 g1(TOKENS / BM, INTER / 128);     // (16, 148) = 2368 CTAs = 16 waves
    mlp_gemm<0><<<g1, THREADS, SMEM>>>(s_gu, nullptr);

    // GEMM2: down -> out
    dim3 g2(TOKENS / BM, HIDDEN / 256);    // (16, 14) = 224 CTAs
    mlp_gemm<1><<<g2, THREADS, SMEM>>>(s_d, out);
}

// round 6
// speedup vs baseline: 7.8145x; 1.3990x over previous
#include <cuda_runtime.h>
#include <cuda_fp16.h>
#include <cstdint>

// ---------------------------------------------------------------------------
// Qwen2 FP8 MLP, fp16 tcgen05 with PRE-SWIZZLED GLOBAL TILES + bulk-async
// warp-specialized pipeline.
//   All operands stored in global memory as exact 32KB SMEM tile images
//   (256 rows x 128B, SW128). Stage load = one cp.async.bulk per operand,
//   completion via mbarrier complete_tx. Producer thread + MMA thread only;
//   no __syncthreads / cp.async.wait_group in the mainloop.
// ---------------------------------------------------------------------------

#if defined(__CUDA_ARCH_FEAT_SM103_ALL) || defined(__CUDA_ARCH_FEAT_SM100_ALL) || defined(__CUDA_ARCH_SPECIFIC__)
#define USE_TCGEN05 1
#else
#define USE_TCGEN05 0
#endif

namespace {
constexpr int HIDDEN = 3584;
constexpr int INTER  = 18944;
constexpr int TOKENS = 4096;

constexpr int BM      = 256;
constexpr int KC      = 64;                  // 64 fp16 = 128B row
constexpr int NSTG    = 3;
constexpr int THREADS = 256;
constexpr int TILE_BYTES  = 32768;           // 256 rows x 128B
constexpr int STAGE_BYTES = 2 * TILE_BYTES;  // A + B

constexpr int KT1 = HIDDEN / KC;             // 56
constexpr int KT2 = INTER  / KC;             // 296
constexpr int NB1 = INTER / 128;             // 148 (gate_up col-blocks)
constexpr int NB2 = HIDDEN / 256;            // 14
constexpr int MB  = TOKENS / BM;             // 16
}

// tiled global buffers (each tile = 32KB SMEM image)
__device__ __half g_x16[(size_t)MB  * KT1 * 16384];   // x tiles
__device__ __half g_wgu[(size_t)NB1 * KT1 * 16384];   // gate_up weight tiles
__device__ __half g_wd [(size_t)NB2 * KT2 * 16384];   // down weight tiles
__device__ __half g_h16[(size_t)MB  * KT2 * 16384];   // h tiles

__host__ __device__ __forceinline__ uint32_t swz(uint32_t off) {
    return off ^ ((off >> 3) & 0x70);
}

// ---------------------------------------------------------------------------
// prep: convert fp32 -> fp16 into swizzled tile images.
// WHICH: 0 = w_gu (gate/up row mapping), 1 = w_d, 2 = x
// ---------------------------------------------------------------------------
template <int WHICH>
__global__ void __launch_bounds__(256) conv_tiled(const float* __restrict__ src) {
    constexpr int KTOT = (WHICH == 1) ? INTER : HIDDEN;
    constexpr int KT   = KTOT / KC;
    const int gid  = blockIdx.x * 256 + threadIdx.x;
    const int tile = gid >> 11;          // 2048 chunks of 16B per tile
    const int c    = gid & 2047;
    const int tr   = c >> 3;             // tile row 0..255
    const int ch   = c & 7;              // 16B chunk 0..7
    const int kt   = tile % KT;
    const int bb   = tile / KT;

    int grow;
    if (WHICH == 0) grow = (tr < 128) ? (bb * 128 + tr) : (INTER + bb * 128 + (tr - 128));
    else            grow = bb * 256 + tr;

    const float* s = src + (size_t)grow * KTOT + kt * KC + ch * 8;
    float4 a = *reinterpret_cast<const float4*>(s);
    float4 b = *reinterpret_cast<const float4*>(s + 4);
    __half2 p0 = __floats2half2_rn(a.x, a.y);
    __half2 p1 = __floats2half2_rn(a.z, a.w);
    __half2 p2 = __floats2half2_rn(b.x, b.y);
    __half2 p3 = __floats2half2_rn(b.z, b.w);
    uint4 v = make_uint4(*reinterpret_cast<uint32_t*>(&p0), *reinterpret_cast<uint32_t*>(&p1),
                         *reinterpret_cast<uint32_t*>(&p2), *reinterpret_cast<uint32_t*>(&p3));

    __half* dstbuf = (WHICH == 0) ? g_wgu : (WHICH == 1) ? g_wd : g_x16;
    char* dst = reinterpret_cast<char*>(dstbuf) + (size_t)tile * TILE_BYTES
              + swz((uint32_t)(tr * 128 + ch * 16));
    *reinterpret_cast<uint4*>(dst) = v;
}

// ---------------------------------------------------------------------------
// device helpers
// ---------------------------------------------------------------------------
#if USE_TCGEN05
__device__ __forceinline__ bool elect_one() {
    uint32_t p;
    asm volatile("{\n\t.reg .pred p;\n\telect.sync _|p, 0xFFFFFFFF;\n\t"
                 "selp.b32 %0, 1, 0, p;\n\t}" : "=r"(p));
    return p != 0;
}
__device__ __forceinline__ void mbar_init(uint32_t addr, uint32_t count) {
    asm volatile("mbarrier.init.shared.b64 [%0], %1;" :: "r"(addr), "r"(count) : "memory");
}
__device__ __forceinline__ void mbar_wait(uint32_t addr, uint32_t parity) {
    asm volatile(
        "{\n\t.reg .pred P;\n\t"
        "WL_%=:\n\t"
        "mbarrier.try_wait.parity.acquire.cta.shared::cta.b64 P, [%0], %1, 0x989680;\n\t"
        "@P bra.uni WD_%=;\n\t"
        "bra.uni WL_%=;\n\t"
        "WD_%=:\n\t}"
        :: "r"(addr), "r"(parity) : "memory");
}
__device__ __forceinline__ void mbar_expect_tx(uint32_t addr, uint32_t bytes) {
    asm volatile("mbarrier.arrive.expect_tx.shared.b64 _, [%0], %1;"
                 :: "r"(addr), "r"(bytes) : "memory");
}
__device__ __forceinline__ void bulk_g2s(uint32_t dst, const void* src, uint32_t bytes,
                                         uint32_t mbar) {
    asm volatile(
        "cp.async.bulk.shared::cluster.global.mbarrier::complete_tx::bytes "
        "[%0], [%1], %2, [%3];"
        :: "r"(dst), "l"(src), "r"(bytes), "r"(mbar) : "memory");
}
__device__ __forceinline__ void tc_alloc(uint32_t dst_smem, uint32_t ncols) {
    asm volatile("tcgen05.alloc.cta_group::1.sync.aligned.shared::cta.b32 [%0], %1;"
                 :: "r"(dst_smem), "r"(ncols) : "memory");
}
__device__ __forceinline__ void tc_relinquish() {
    asm volatile("tcgen05.relinquish_alloc_permit.cta_group::1.sync.aligned;");
}
__device__ __forceinline__ void tc_dealloc(uint32_t tmem, uint32_t ncols) {
    asm volatile("tcgen05.dealloc.cta_group::1.sync.aligned.b32 %0, %1;" :: "r"(tmem), "r"(ncols));
}
__device__ __forceinline__ void tc_commit(uint32_t mbar) {
    asm volatile("tcgen05.commit.cta_group::1.mbarrier::arrive::one.shared::cluster.b64 [%0];"
                 :: "r"(mbar) : "memory");
}
__device__ __forceinline__ void tc_wait_ld() {
    asm volatile("tcgen05.wait::ld.sync.aligned;" ::: "memory");
}
__device__ __forceinline__ uint64_t sdesc(uint32_t addr) {
    return ((uint64_t)((addr >> 4) & 0x3FFF))
         | (1ULL  << 16) | (64ULL << 32) | (1ULL << 46) | (2ULL << 61);  // SW128 K-major
}
__device__ __forceinline__ void mma_f16_ss(uint32_t d_tmem, uint64_t ad, uint64_t bd,
                                           uint32_t idesc, uint32_t enable_d) {
    asm volatile(
        "{\n\t.reg .pred p;\n\t"
        "setp.ne.u32 p, %4, 0;\n\t"
        "tcgen05.mma.cta_group::1.kind::f16 [%0], %1, %2, %3, p;\n\t}"
        :: "r"(d_tmem), "l"(ad), "l"(bd), "r"(idesc), "r"(enable_d) : "memory");
}
__device__ __forceinline__ void ldtm32(uint32_t* r, uint32_t ta) {
    asm volatile(
        "tcgen05.ld.sync.aligned.32x32b.x32.b32 "
        "{%0,%1,%2,%3,%4,%5,%6,%7,%8,%9,%10,%11,%12,%13,%14,%15,"
        "%16,%17,%18,%19,%20,%21,%22,%23,%24,%25,%26,%27,%28,%29,%30,%31}, [%32];"
        : "=r"(r[0]),  "=r"(r[1]),  "=r"(r[2]),  "=r"(r[3]),
          "=r"(r[4]),  "=r"(r[5]),  "=r"(r[6]),  "=r"(r[7]),
          "=r"(r[8]),  "=r"(r[9]),  "=r"(r[10]), "=r"(r[11]),
          "=r"(r[12]), "=r"(r[13]), "=r"(r[14]), "=r"(r[15]),
          "=r"(r[16]), "=r"(r[17]), "=r"(r[18]), "=r"(r[19]),
          "=r"(r[20]), "=r"(r[21]), "=r"(r[22]), "=r"(r[23]),
          "=r"(r[24]), "=r"(r[25]), "=r"(r[26]), "=r"(r[27]),
          "=r"(r[28]), "=r"(r[29]), "=r"(r[30]), "=r"(r[31])
        : "r"(ta));
}
#endif

// read helper for the scalar fallback (tiled layout)
__device__ __forceinline__ float rd_tile(const __half* buf, size_t tile, int row, int k) {
    const char* p = reinterpret_cast<const char*>(buf) + tile * TILE_BYTES
                  + swz((uint32_t)(row * 128 + (k >> 3) * 16)) + (k & 7) * 2;
    return __half2float(*reinterpret_cast<const __half*>(p));
}

// ---------------------------------------------------------------------------
// MODE 0: gate_up + SiLU*Mul -> g_h16 tiles.  grid (16, 148), n0 = y*128
// MODE 1: down -> out fp32.                   grid (16, 14),  n0 = y*256
// ---------------------------------------------------------------------------
template <int MODE>
__global__ void __launch_bounds__(THREADS, 1)
mlp_gemm(const float* __restrict__ S, float* __restrict__ Out)
{
    constexpr int KT = (MODE == 0) ? KT1 : KT2;
    extern __shared__ char smem[];
    const int t    = threadIdx.x;
    const int wid  = t >> 5;
    const int lane = t & 31;
    const int mb   = blockIdx.x;
    const int m0   = mb * BM;
    const int n0   = blockIdx.y * ((MODE == 0) ? 128 : 256);

#if USE_TCGEN05
    constexpr uint32_t IDESC = (1u << 4) | (32u << 17) | (8u << 24);  // F32, f16, N=256, M=128

    const uint32_t sbase     = (uint32_t)__cvta_generic_to_shared(smem);
    const uint32_t tptr_addr = sbase;
    const uint32_t bar_full  = sbase + 8;
    const uint32_t bar_empty = bar_full + NSTG * 8;
    const uint32_t bar_done  = bar_empty + NSTG * 8;
    const uint32_t data_u    = (sbase + 128 + 1023) & ~1023u;

    if (wid == 0) { tc_alloc(tptr_addr, 512); tc_relinquish(); }
    if (t == 0) {
        for (int s = 0; s < NSTG; s++) {
            mbar_init(bar_full  + s * 8, 1);
            mbar_init(bar_empty + s * 8, 1);
        }
        mbar_init(bar_done, 1);
    }
    __syncthreads();
    uint32_t tmem;
    asm volatile("ld.shared.b32 %0, [%1];" : "=r"(tmem) : "r"(tptr_addr));

    // tile sources
    const char* a_base = reinterpret_cast<const char*>((MODE == 0) ? g_x16 : g_h16)
                       + (size_t)mb * KT * TILE_BYTES;
    const char* b_base = reinterpret_cast<const char*>((MODE == 0) ? g_wgu : g_wd)
                       + (size_t)blockIdx.y * KT * TILE_BYTES;

    if (t == 32) {
        // ---------------- producer ----------------
        #pragma unroll 1
        for (int kt = 0; kt < KT; kt++) {
            const int s = kt % NSTG;
            if (kt >= NSTG) mbar_wait(bar_empty + s * 8, ((uint32_t)(kt / NSTG) - 1) & 1);
            const uint32_t As = data_u + s * STAGE_BYTES;
            mbar_expect_tx(bar_full + s * 8, STAGE_BYTES);
            bulk_g2s(As,              a_base + (size_t)kt * TILE_BYTES, TILE_BYTES,
                     bar_full + s * 8);
            bulk_g2s(As + TILE_BYTES, b_base + (size_t)kt * TILE_BYTES, TILE_BYTES,
                     bar_full + s * 8);
        }
    } else if (wid == 0) {
        // ---------------- MMA issuer ----------------
        if (elect_one()) {
            #pragma unroll 1
            for (int kt = 0; kt < KT; kt++) {
                const int s = kt % NSTG;
                mbar_wait(bar_full + s * 8, (uint32_t)(kt / NSTG) & 1);
                const uint32_t As = data_u + s * STAGE_BYTES;
                const uint64_t ad0 = sdesc(As);
                const uint64_t ad1 = sdesc(As + 16384);
                const uint64_t bd  = sdesc(As + TILE_BYTES);
                #pragma unroll
                for (int kk = 0; kk < 4; kk++) {          // 4 x K=16 == KC
                    const uint32_t en = (kt > 0 || kk > 0) ? 1u : 0u;
                    mma_f16_ss(tmem,       ad0 + 2 * kk, bd + 2 * kk, IDESC, en);
                    mma_f16_ss(tmem + 256, ad1 + 2 * kk, bd + 2 * kk, IDESC, en);
                }
                tc_commit(bar_empty + s * 8);
            }
            tc_commit(bar_done);
        }
    }

    mbar_wait(bar_done, 0);
    asm volatile("tcgen05.fence::after_thread_sync;" ::: "memory");

    // ---- epilogue: warp = (m-half, subpartition) ----
    const int mh = wid >> 2;
    const int sp = wid & 3;
    const int tr = mh * 128 + sp * 32 + lane;            // row within 256-tile
    const uint32_t tbase = tmem + mh * 256;

    if (MODE == 0) {
        const size_t tA = (size_t)mb * KT2 + (n0 >> 6);  // h tile index (first of 2)
        #pragma unroll
        for (int c = 0; c < 4; c++) {
            const int cb = c * 32;
            uint32_t gr[32], ur[32];
            ldtm32(gr, tbase + cb);            // gate: D cols [0,128)
            ldtm32(ur, tbase + 128 + cb);      // up:   D cols [128,256)
            tc_wait_ld();
            uint32_t oh[16];
            #pragma unroll
            for (int p = 0; p < 16; p++) {
                const int i = 2 * p;
                const int n = n0 + cb + i;
                float g0 = __uint_as_float(gr[i])     * __ldg(S + n);
                float g1 = __uint_as_float(gr[i + 1]) * __ldg(S + n + 1);
                float u0 = __uint_as_float(ur[i])     * __ldg(S + INTER + n);
                float u1 = __uint_as_float(ur[i + 1]) * __ldg(S + INTER + n + 1);
                float h0 = g0 * (1.0f / (1.0f + __expf(-g0))) * u0;
                float h1 = g1 * (1.0f / (1.0f + __expf(-g1))) * u1;
                __half2 ph = __floats2half2_rn(h0, h1);
                oh[p] = *reinterpret_cast<uint32_t*>(&ph);
            }
            // write into swizzled h tile image
            char* tb = reinterpret_cast<char*>(g_h16) + (tA + (c >> 1)) * TILE_BYTES;
            #pragma unroll
            for (int q = 0; q < 4; q++) {
                const uint32_t off = swz((uint32_t)(tr * 128 + ((c & 1) * 4 + q) * 16));
                *reinterpret_cast<uint4*>(tb + off) =
                    make_uint4(oh[4 * q], oh[4 * q + 1], oh[4 * q + 2], oh[4 * q + 3]);
            }
        }
    } else {
        const size_t mrow = (size_t)m0 + tr;
        #pragma unroll
        for (int c = 0; c < 8; c++) {
            const int cb = c * 32;
            uint32_t dr[32];
            ldtm32(dr, tbase + cb);
            tc_wait_ld();
            float* op = Out + mrow * HIDDEN + n0 + cb;
            #pragma unroll
            for (int q = 0; q < 8; q++) {
                float r[4];
                #pragma unroll
                for (int j = 0; j < 4; j++) {
                    const int i = q * 4 + j;
                    r[j] = __uint_as_float(dr[i]) * __ldg(S + n0 + cb + i);
                }
                reinterpret_cast<float4*>(op)[q] = make_float4(r[0], r[1], r[2], r[3]);
            }
        }
    }

    __syncthreads();
    if (wid == 0) tc_dealloc(tmem, 512);

#else
    // non-103a compile pass only (never selected at runtime on GB300)
    (void)smem; (void)wid; (void)lane;
    constexpr int NCOL = (MODE == 0) ? 128 : 256;
    constexpr int KTOT = (MODE == 0) ? HIDDEN : INTER;
    for (int o = t; o < BM * NCOL; o += THREADS) {
        const int r = o / NCOL, cc = o % NCOL;
        if (MODE == 0) {
            float accg = 0.f, accu = 0.f;
            for (int k = 0; k < KTOT; k++) {
                const size_t at = (size_t)mb * KT1 + k / KC;
                const size_t bt = (size_t)blockIdx.y * KT1 + k / KC;
                float a = rd_tile(g_x16, at, r, k % KC);
                accg += a * rd_tile(g_wgu, bt, cc, k % KC);
                accu += a * rd_tile(g_wgu, bt, 128 + cc, k % KC);
            }
            float g = accg * S[n0 + cc], u = accu * S[INTER + n0 + cc];
            float h = g * (1.0f / (1.0f + __expf(-g))) * u;
            __half hv = __float2half_rn(h);
            // write into h tile image
            const size_t tile = (size_t)mb * KT2 + (n0 + cc) / KC;
            const int k = (n0 + cc) % KC;
            char* p = reinterpret_cast<char*>(g_h16) + tile * TILE_BYTES
                    + swz((uint32_t)(r * 128 + (k >> 3) * 16)) + (k & 7) * 2;
            *reinterpret_cast<__half*>(p) = hv;
        } else {
            float acc = 0.f;
            for (int k = 0; k < KTOT; k++) {
                const size_t at = (size_t)mb * KT2 + k / KC;
                const size_t bt = (size_t)blockIdx.y * KT2 + k / KC;
                acc += rd_tile(g_h16, at, r, k % KC) * rd_tile(g_wd, bt, cc, k % KC);
            }
            Out[(size_t)(m0 + r) * HIDDEN + n0 + cc] = acc * S[n0 + cc];
        }
    }
#endif
}

// ---------------------------------------------------------------------------
// launch
// ---------------------------------------------------------------------------
extern "C" void kernel_launch(void* const* d_in, const int* in_sizes, int n_in,
                              void* d_out, int out_size)
{
    const float* x = nullptr; const float* w_gu = nullptr; const float* s_gu = nullptr;
    const float* w_d = nullptr; const float* s_d = nullptr;
    for (int i = 0; i < n_in; i++) {
        long long sz = in_sizes[i];
        const float* p = (const float*)d_in[i];
        if      (sz == (long long)TOKENS * HIDDEN)    x    = p;
        else if (sz == (long long)2 * INTER * HIDDEN) w_gu = p;
        else if (sz == (long long)2 * INTER)          s_gu = p;
        else if (sz == (long long)HIDDEN * INTER)     w_d  = p;
        else if (sz == (long long)HIDDEN)             s_d  = p;
    }
    float* out = (float*)d_out;

    constexpr int SMEM = 2048 + NSTG * STAGE_BYTES;   // 198,656
    cudaFuncSetAttribute(mlp_gemm<0>, cudaFuncAttributeMaxDynamicSharedMemorySize, SMEM);
    cudaFuncSetAttribute(mlp_gemm<1>, cudaFuncAttributeMaxDynamicSharedMemorySize, SMEM);

    // prep: fp32 -> fp16 swizzled tiles
    conv_tiled<0><<<(NB1 * KT1 * 2048) / 256, 256>>>(w_gu);
    conv_tiled<1><<<(NB2 * KT2 * 2048) / 256, 256>>>(w_d);
    conv_tiled<2><<<(MB  * KT1 * 2048) / 256, 256>>>(x);

    // GEMM1: gate_up + SiLU*Mul -> g_h16 tiles
    dim3 g1(MB, NB1);                      // (16, 148) = 2368 CTAs = 16 waves
    mlp_gemm<0><<<g1, THREADS, SMEM>>>(s_gu, nullptr);

    // GEMM2: down -> out
    dim3 g2(MB, NB2);                      // (16, 14)
    mlp_gemm<1><<<g2, THREADS, SMEM>>>(s_d, out);
}

// round 7
// speedup vs baseline: 7.8289x; 1.0018x over previous
#include <cuda_runtime.h>
#include <cuda_fp16.h>
#include <cstdint>

// ---------------------------------------------------------------------------
// Qwen2 FP8 MLP, fp16 tcgen05 + pre-swizzled global tiles + bulk-async
// pipeline + 2-CTA cluster TMA MULTICAST on the weight tile.
//   CTA pair (2x,y)/(2x+1,y) shares the B (weight) tile: rank0 multicasts it
//   to both CTAs' SMEM -> B-side L2 traffic halved (the R6 bottleneck).
//   Stage reuse across the pair is gated by empty[s] (count=2) armed via
//   tcgen05.commit.multicast from both CTAs' MMA threads.
// ---------------------------------------------------------------------------

#if defined(__CUDA_ARCH_FEAT_SM103_ALL) || defined(__CUDA_ARCH_FEAT_SM100_ALL) || defined(__CUDA_ARCH_SPECIFIC__)
#define USE_TCGEN05 1
#else
#define USE_TCGEN05 0
#endif

namespace {
constexpr int HIDDEN = 3584;
constexpr int INTER  = 18944;
constexpr int TOKENS = 4096;

constexpr int BM      = 256;
constexpr int KC      = 64;                  // 64 fp16 = 128B row
constexpr int NSTG    = 3;
constexpr int THREADS = 256;
constexpr int TILE_BYTES  = 32768;           // 256 rows x 128B
constexpr int STAGE_BYTES = 2 * TILE_BYTES;  // A + B

constexpr int KT1 = HIDDEN / KC;             // 56
constexpr int KT2 = INTER  / KC;             // 296
constexpr int NB1 = INTER / 128;             // 148
constexpr int NB2 = HIDDEN / 256;            // 14
constexpr int MB  = TOKENS / BM;             // 16
}

// tiled global buffers (each tile = 32KB SMEM image, SW128)
__device__ __half g_x16[(size_t)MB  * KT1 * 16384];
__device__ __half g_wgu[(size_t)NB1 * KT1 * 16384];
__device__ __half g_wd [(size_t)NB2 * KT2 * 16384];
__device__ __half g_h16[(size_t)MB  * KT2 * 16384];

__host__ __device__ __forceinline__ uint32_t swz(uint32_t off) {
    return off ^ ((off >> 3) & 0x70);
}

// ---------------------------------------------------------------------------
// prep: convert fp32 -> fp16 into swizzled tile images.
// WHICH: 0 = w_gu (gate/up rows), 1 = w_d, 2 = x
// ---------------------------------------------------------------------------
template <int WHICH>
__global__ void __launch_bounds__(256) conv_tiled(const float* __restrict__ src) {
    constexpr int KTOT = (WHICH == 1) ? INTER : HIDDEN;
    constexpr int KT   = KTOT / KC;
    const int gid  = blockIdx.x * 256 + threadIdx.x;
    const int tile = gid >> 11;
    const int c    = gid & 2047;
    const int tr   = c >> 3;
    const int ch   = c & 7;
    const int kt   = tile % KT;
    const int bb   = tile / KT;

    int grow;
    if (WHICH == 0) grow = (tr < 128) ? (bb * 128 + tr) : (INTER + bb * 128 + (tr - 128));
    else            grow = bb * 256 + tr;

    const float* s = src + (size_t)grow * KTOT + kt * KC + ch * 8;
    float4 a = *reinterpret_cast<const float4*>(s);
    float4 b = *reinterpret_cast<const float4*>(s + 4);
    __half2 p0 = __floats2half2_rn(a.x, a.y);
    __half2 p1 = __floats2half2_rn(a.z, a.w);
    __half2 p2 = __floats2half2_rn(b.x, b.y);
    __half2 p3 = __floats2half2_rn(b.z, b.w);
    uint4 v = make_uint4(*reinterpret_cast<uint32_t*>(&p0), *reinterpret_cast<uint32_t*>(&p1),
                         *reinterpret_cast<uint32_t*>(&p2), *reinterpret_cast<uint32_t*>(&p3));

    __half* dstbuf = (WHICH == 0) ? g_wgu : (WHICH == 1) ? g_wd : g_x16;
    char* dst = reinterpret_cast<char*>(dstbuf) + (size_t)tile * TILE_BYTES
              + swz((uint32_t)(tr * 128 + ch * 16));
    *reinterpret_cast<uint4*>(dst) = v;
}

// ---------------------------------------------------------------------------
// device helpers
// ---------------------------------------------------------------------------
#if USE_TCGEN05
__device__ __forceinline__ bool elect_one() {
    uint32_t p;
    asm volatile("{\n\t.reg .pred p;\n\telect.sync _|p, 0xFFFFFFFF;\n\t"
                 "selp.b32 %0, 1, 0, p;\n\t}" : "=r"(p));
    return p != 0;
}
__device__ __forceinline__ uint32_t ctarank() {
    uint32_t r;
    asm("mov.u32 %0, %%cluster_ctarank;" : "=r"(r));
    return r;
}
__device__ __forceinline__ void mbar_init(uint32_t addr, uint32_t count) {
    asm volatile("mbarrier.init.shared.b64 [%0], %1;" :: "r"(addr), "r"(count) : "memory");
}
__device__ __forceinline__ void mbar_wait(uint32_t addr, uint32_t parity) {
    asm volatile(
        "{\n\t.reg .pred P;\n\t"
        "WL_%=:\n\t"
        "mbarrier.try_wait.parity.acquire.cta.shared::cta.b64 P, [%0], %1, 0x989680;\n\t"
        "@P bra.uni WD_%=;\n\t"
        "bra.uni WL_%=;\n\t"
        "WD_%=:\n\t}"
        :: "r"(addr), "r"(parity) : "memory");
}
__device__ __forceinline__ void mbar_expect_tx(uint32_t addr, uint32_t bytes) {
    asm volatile("mbarrier.arrive.expect_tx.shared.b64 _, [%0], %1;"
                 :: "r"(addr), "r"(bytes) : "memory");
}
__device__ __forceinline__ void bulk_g2s(uint32_t dst, const void* src, uint32_t bytes,
                                         uint32_t mbar) {
    asm volatile(
        "cp.async.bulk.shared::cluster.global.mbarrier::complete_tx::bytes "
        "[%0], [%1], %2, [%3];"
        :: "r"(dst), "l"(src), "r"(bytes), "r"(mbar) : "memory");
}
__device__ __forceinline__ void bulk_g2s_mc(uint32_t dst, const void* src, uint32_t bytes,
                                            uint32_t mbar, uint16_t mask) {
    asm volatile(
        "cp.async.bulk.shared::cluster.global.mbarrier::complete_tx::bytes.multicast::cluster "
        "[%0], [%1], %2, [%3], %4;"
        :: "r"(dst), "l"(src), "r"(bytes), "r"(mbar), "h"(mask) : "memory");
}
__device__ __forceinline__ void tc_alloc(uint32_t dst_smem, uint32_t ncols) {
    asm volatile("tcgen05.alloc.cta_group::1.sync.aligned.shared::cta.b32 [%0], %1;"
                 :: "r"(dst_smem), "r"(ncols) : "memory");
}
__device__ __forceinline__ void tc_relinquish() {
    asm volatile("tcgen05.relinquish_alloc_permit.cta_group::1.sync.aligned;");
}
__device__ __forceinline__ void tc_dealloc(uint32_t tmem, uint32_t ncols) {
    asm volatile("tcgen05.dealloc.cta_group::1.sync.aligned.b32 %0, %1;" :: "r"(tmem), "r"(ncols));
}
__device__ __forceinline__ void tc_commit(uint32_t mbar) {
    asm volatile("tcgen05.commit.cta_group::1.mbarrier::arrive::one.shared::cluster.b64 [%0];"
                 :: "r"(mbar) : "memory");
}
__device__ __forceinline__ void tc_commit_mc(uint32_t mbar, uint16_t mask) {
    asm volatile(
        "tcgen05.commit.cta_group::1.mbarrier::arrive::one.shared::cluster.multicast::cluster.b64 "
        "[%0], %1;"
        :: "r"(mbar), "h"(mask) : "memory");
}
__device__ __forceinline__ void tc_wait_ld() {
    asm volatile("tcgen05.wait::ld.sync.aligned;" ::: "memory");
}
__device__ __forceinline__ uint64_t sdesc(uint32_t addr) {
    return ((uint64_t)((addr >> 4) & 0x3FFF))
         | (1ULL  << 16) | (64ULL << 32) | (1ULL << 46) | (2ULL << 61);  // SW128 K-major
}
__device__ __forceinline__ void mma_f16_ss(uint32_t d_tmem, uint64_t ad, uint64_t bd,
                                           uint32_t idesc, uint32_t enable_d) {
    asm volatile(
        "{\n\t.reg .pred p;\n\t"
        "setp.ne.u32 p, %4, 0;\n\t"
        "tcgen05.mma.cta_group::1.kind::f16 [%0], %1, %2, %3, p;\n\t}"
        :: "r"(d_tmem), "l"(ad), "l"(bd), "r"(idesc), "r"(enable_d) : "memory");
}
__device__ __forceinline__ void ldtm32(uint32_t* r, uint32_t ta) {
    asm volatile(
        "tcgen05.ld.sync.aligned.32x32b.x32.b32 "
        "{%0,%1,%2,%3,%4,%5,%6,%7,%8,%9,%10,%11,%12,%13,%14,%15,"
        "%16,%17,%18,%19,%20,%21,%22,%23,%24,%25,%26,%27,%28,%29,%30,%31}, [%32];"
        : "=r"(r[0]),  "=r"(r[1]),  "=r"(r[2]),  "=r"(r[3]),
          "=r"(r[4]),  "=r"(r[5]),  "=r"(r[6]),  "=r"(r[7]),
          "=r"(r[8]),  "=r"(r[9]),  "=r"(r[10]), "=r"(r[11]),
          "=r"(r[12]), "=r"(r[13]), "=r"(r[14]), "=r"(r[15]),
          "=r"(r[16]), "=r"(r[17]), "=r"(r[18]), "=r"(r[19]),
          "=r"(r[20]), "=r"(r[21]), "=r"(r[22]), "=r"(r[23]),
          "=r"(r[24]), "=r"(r[25]), "=r"(r[26]), "=r"(r[27]),
          "=r"(r[28]), "=r"(r[29]), "=r"(r[30]), "=r"(r[31])
        : "r"(ta));
}
#endif

// read helper for the scalar fallback (tiled layout)
__device__ __forceinline__ float rd_tile(const __half* buf, size_t tile, int row, int k) {
    const char* p = reinterpret_cast<const char*>(buf) + tile * TILE_BYTES
                  + swz((uint32_t)(row * 128 + (k >> 3) * 16)) + (k & 7) * 2;
    return __half2float(*reinterpret_cast<const __half*>(p));
}

// ---------------------------------------------------------------------------
// MODE 0: gate_up + SiLU*Mul -> g_h16 tiles.  grid (16, 148), cluster (2,1)
// MODE 1: down -> out fp32.                   grid (16, 14),  cluster (2,1)
// Cluster pair shares the B (weight) tile via TMA multicast from rank 0.
// ---------------------------------------------------------------------------
template <int MODE>
__global__ void __launch_bounds__(THREADS, 1) __cluster_dims__(2, 1, 1)
mlp_gemm(const float* __restrict__ S, float* __restrict__ Out)
{
    constexpr int KT = (MODE == 0) ? KT1 : KT2;
    extern __shared__ char smem[];
    const int t    = threadIdx.x;
    const int wid  = t >> 5;
    const int lane = t & 31;
    const int mb   = blockIdx.x;
    const int m0   = mb * BM;
    const int n0   = blockIdx.y * ((MODE == 0) ? 128 : 256);

#if USE_TCGEN05
    constexpr uint32_t IDESC = (1u << 4) | (32u << 17) | (8u << 24);  // F32, f16, N=256, M=128

    const uint32_t sbase     = (uint32_t)__cvta_generic_to_shared(smem);
    const uint32_t tptr_addr = sbase;
    const uint32_t bar_full  = sbase + 8;
    const uint32_t bar_empty = bar_full + NSTG * 8;
    const uint32_t bar_done  = bar_empty + NSTG * 8;
    const uint32_t data_u    = (sbase + 128 + 1023) & ~1023u;
    const uint32_t rank      = ctarank();

    if (wid == 0) { tc_alloc(tptr_addr, 512); tc_relinquish(); }
    if (t == 0) {
        for (int s = 0; s < NSTG; s++) {
            mbar_init(bar_full  + s * 8, 1);
            mbar_init(bar_empty + s * 8, 2);   // freed by BOTH CTAs' MMA commits
        }
        mbar_init(bar_done, 1);
    }
    __syncthreads();
    // all mbarriers must be visible cluster-wide before any multicast targets them
    asm volatile("barrier.cluster.arrive.aligned;" ::: "memory");
    asm volatile("barrier.cluster.wait.aligned;"   ::: "memory");

    uint32_t tmem;
    asm volatile("ld.shared.b32 %0, [%1];" : "=r"(tmem) : "r"(tptr_addr));

    const char* a_base = reinterpret_cast<const char*>((MODE == 0) ? g_x16 : g_h16)
                       + (size_t)mb * KT * TILE_BYTES;
    const char* b_base = reinterpret_cast<const char*>((MODE == 0) ? g_wgu : g_wd)
                       + (size_t)blockIdx.y * KT * TILE_BYTES;

    if (t == 32) {
        // ---------------- producer ----------------
        #pragma unroll 1
        for (int kt = 0; kt < KT; kt++) {
            const int s = kt % NSTG;
            if (kt >= NSTG) mbar_wait(bar_empty + s * 8, ((uint32_t)(kt / NSTG) - 1) & 1);
            const uint32_t As = data_u + s * STAGE_BYTES;
            mbar_expect_tx(bar_full + s * 8, STAGE_BYTES);
            // A: per-CTA local load
            bulk_g2s(As, a_base + (size_t)kt * TILE_BYTES, TILE_BYTES, bar_full + s * 8);
            // B: rank 0 multicasts the shared weight tile to both CTAs
            if (rank == 0)
                bulk_g2s_mc(As + TILE_BYTES, b_base + (size_t)kt * TILE_BYTES, TILE_BYTES,
                            bar_full + s * 8, (uint16_t)0x3);
        }
    } else if (wid == 0) {
        // ---------------- MMA issuer ----------------
        if (elect_one()) {
            #pragma unroll 1
            for (int kt = 0; kt < KT; kt++) {
                const int s = kt % NSTG;
                mbar_wait(bar_full + s * 8, (uint32_t)(kt / NSTG) & 1);
                const uint32_t As = data_u + s * STAGE_BYTES;
                const uint64_t ad0 = sdesc(As);
                const uint64_t ad1 = sdesc(As + 16384);
                const uint64_t bd  = sdesc(As + TILE_BYTES);
                #pragma unroll
                for (int kk = 0; kk < 4; kk++) {
                    const uint32_t en = (kt > 0 || kk > 0) ? 1u : 0u;
                    mma_f16_ss(tmem,       ad0 + 2 * kk, bd + 2 * kk, IDESC, en);
                    mma_f16_ss(tmem + 256, ad1 + 2 * kk, bd + 2 * kk, IDESC, en);
                }
                // free stage s in BOTH CTAs (B producer must see partner done)
                tc_commit_mc(bar_empty + s * 8, (uint16_t)0x3);
            }
            tc_commit(bar_done);
        }
    }

    mbar_wait(bar_done, 0);
    asm volatile("tcgen05.fence::after_thread_sync;" ::: "memory");

    // ---- epilogue: warp = (m-half, subpartition) ----
    const int mh = wid >> 2;
    const int sp = wid & 3;
    const int tr = mh * 128 + sp * 32 + lane;
    const uint32_t tbase = tmem + mh * 256;

    if (MODE == 0) {
        const size_t tA = (size_t)mb * KT2 + (n0 >> 6);
        #pragma unroll
        for (int c = 0; c < 4; c++) {
            const int cb = c * 32;
            uint32_t gr[32], ur[32];
            ldtm32(gr, tbase + cb);
            ldtm32(ur, tbase + 128 + cb);
            tc_wait_ld();
            uint32_t oh[16];
            #pragma unroll
            for (int p = 0; p < 16; p++) {
                const int i = 2 * p;
                const int n = n0 + cb + i;
                float g0 = __uint_as_float(gr[i])     * __ldg(S + n);
                float g1 = __uint_as_float(gr[i + 1]) * __ldg(S + n + 1);
                float u0 = __uint_as_float(ur[i])     * __ldg(S + INTER + n);
                float u1 = __uint_as_float(ur[i + 1]) * __ldg(S + INTER + n + 1);
                float h0 = g0 * (1.0f / (1.0f + __expf(-g0))) * u0;
                float h1 = g1 * (1.0f / (1.0f + __expf(-g1))) * u1;
                __half2 ph = __floats2half2_rn(h0, h1);
                oh[p] = *reinterpret_cast<uint32_t*>(&ph);
            }
            char* tb = reinterpret_cast<char*>(g_h16) + (tA + (c >> 1)) * TILE_BYTES;
            #pragma unroll
            for (int q = 0; q < 4; q++) {
                const uint32_t off = swz((uint32_t)(tr * 128 + ((c & 1) * 4 + q) * 16));
                *reinterpret_cast<uint4*>(tb + off) =
                    make_uint4(oh[4 * q], oh[4 * q + 1], oh[4 * q + 2], oh[4 * q + 3]);
            }
        }
    } else {
        const size_t mrow = (size_t)m0 + tr;
        #pragma unroll
        for (int c = 0; c < 8; c++) {
            const int cb = c * 32;
            uint32_t dr[32];
            ldtm32(dr, tbase + cb);
            tc_wait_ld();
            float* op = Out + mrow * HIDDEN + n0 + cb;
            #pragma unroll
            for (int q = 0; q < 8; q++) {
                float r[4];
                #pragma unroll
                for (int j = 0; j < 4; j++) {
                    const int i = q * 4 + j;
                    r[j] = __uint_as_float(dr[i]) * __ldg(S + n0 + cb + i);
                }
                reinterpret_cast<float4*>(op)[q] = make_float4(r[0], r[1], r[2], r[3]);
            }
        }
    }

    __syncthreads();
    if (wid == 0) tc_dealloc(tmem, 512);
    // no CTA may exit while the partner might still multicast into its SMEM
    asm volatile("barrier.cluster.arrive.aligned;" ::: "memory");
    asm volatile("barrier.cluster.wait.aligned;"   ::: "memory");

#else
    // non-103a compile pass only (never selected at runtime on GB300)
    (void)smem; (void)wid; (void)lane;
    constexpr int NCOL = (MODE == 0) ? 128 : 256;
    constexpr int KTOT = (MODE == 0) ? HIDDEN : INTER;
    for (int o = t; o < BM * NCOL; o += THREADS) {
        const int r = o / NCOL, cc = o % NCOL;
        if (MODE == 0) {
            float accg = 0.f, accu = 0.f;
            for (int k = 0; k < KTOT; k++) {
                const size_t at = (size_t)mb * KT1 + k / KC;
                const size_t bt = (size_t)blockIdx.y * KT1 + k / KC;
                float a = rd_tile(g_x16, at, r, k % KC);
                accg += a * rd_tile(g_wgu, bt, cc, k % KC);
                accu += a * rd_tile(g_wgu, bt, 128 + cc, k % KC);
            }
            float g = accg * S[n0 + cc], u = accu * S[INTER + n0 + cc];
            float h = g * (1.0f / (1.0f + __expf(-g))) * u;
            __half hv = __float2half_rn(h);
            const size_t tile = (size_t)mb * KT2 + (n0 + cc) / KC;
            const int k = (n0 + cc) % KC;
            char* p = reinterpret_cast<char*>(g_h16) + tile * TILE_BYTES
                    + swz((uint32_t)(r * 128 + (k >> 3) * 16)) + (k & 7) * 2;
            *reinterpret_cast<__half*>(p) = hv;
        } else {
            float acc = 0.f;
            for (int k = 0; k < KTOT; k++) {
                const size_t at = (size_t)mb * KT2 + k / KC;
                const size_t bt = (size_t)blockIdx.y * KT2 + k / KC;
                acc += rd_tile(g_h16, at, r, k % KC) * rd_tile(g_wd, bt, cc, k % KC);
            }
            Out[(size_t)(m0 + r) * HIDDEN + n0 + cc] = acc * S[n0 + cc];
        }
    }
#endif
}

// ---------------------------------------------------------------------------
// launch
// ---------------------------------------------------------------------------
extern "C" void kernel_launch(void* const* d_in, const int* in_sizes, int n_in,
                              void* d_out, int out_size)
{
    const float* x = nullptr; const float* w_gu = nullptr; const float* s_gu = nullptr;
    const float* w_d = nullptr; const float* s_d = nullptr;
    for (int i = 0; i < n_in; i++) {
        long long sz = in_sizes[i];
        const float* p = (const float*)d_in[i];
        if      (sz == (long long)TOKENS * HIDDEN)    x    = p;
        else if (sz == (long long)2 * INTER * HIDDEN) w_gu = p;
        else if (sz == (long long)2 * INTER)          s_gu = p;
        else if (sz == (long long)HIDDEN * INTER)     w_d  = p;
        else if (sz == (long long)HIDDEN)             s_d  = p;
    }
    float* out = (float*)d_out;

    constexpr int SMEM = 2048 + NSTG * STAGE_BYTES;   // 198,656
    cudaFuncSetAttribute(mlp_gemm<0>, cudaFuncAttributeMaxDynamicSharedMemorySize, SMEM);
    cudaFuncSetAttribute(mlp_gemm<1>, cudaFuncAttributeMaxDynamicSharedMemorySize, SMEM);

    // prep: fp32 -> fp16 swizzled tiles
    conv_tiled<0><<<(NB1 * KT1 * 2048) / 256, 256>>>(w_gu);
    conv_tiled<1><<<(NB2 * KT2 * 2048) / 256, 256>>>(w_d);
    conv_tiled<2><<<(MB  * KT1 * 2048) / 256, 256>>>(x);

    // GEMM1: gate_up + SiLU*Mul -> g_h16 tiles
    dim3 g1(MB, NB1);                      // (16, 148), cluster (2,1)
    mlp_gemm<0><<<g1, THREADS, SMEM>>>(s_gu, nullptr);

    // GEMM2: down -> out
    dim3 g2(MB, NB2);                      // (16, 14), cluster (2,1)
    mlp_gemm<1><<<g2, THREADS, SMEM>>>(s_d, out);
}

// round 8
// speedup vs baseline: 7.9002x; 1.0091x over previous
#include <cuda_runtime.h>
#include <cuda_fp16.h>
#include <cstdint>

// ---------------------------------------------------------------------------
// Qwen2 FP8 MLP, fp16 tcgen05 cta_group::2 version.
//   R7 finding: LTS cap binds on bytes DELIVERED into SMEM (multicast no-op).
//   Fix: cg2 pair computes M=512 x N=256 (two M=256 cg2 blocks). Per CTA per
//   stage: A 32KB + B 16KB = 48KB (was 64KB) at unchanged tensor rate.
//   B rows split 128/CTA (hardware reads both CTAs' SMEM at same offset).
// ---------------------------------------------------------------------------

#if defined(__CUDA_ARCH_FEAT_SM103_ALL) || defined(__CUDA_ARCH_FEAT_SM100_ALL) || defined(__CUDA_ARCH_SPECIFIC__)
#define USE_TCGEN05 1
#else
#define USE_TCGEN05 0
#endif

namespace {
constexpr int HIDDEN = 3584;
constexpr int INTER  = 18944;
constexpr int TOKENS = 4096;

constexpr int KC      = 64;                   // 64 fp16 = 128B row
constexpr int NSTG    = 4;
constexpr int THREADS = 256;
constexpr int A_BYTES = 32768;                // 256 rows (2 x 128-row halves)
constexpr int B_BYTES = 16384;                // 128 rows (this CTA's N-half)
constexpr int STAGE_BYTES = A_BYTES + B_BYTES;          // 48KB
constexpr int ATILE = 65536;                  // global A tile: 512 rows (both ranks)
constexpr int BTILE = 32768;                  // global B tile: 256 rows (both ranks)

constexpr int KT1 = HIDDEN / KC;              // 56
constexpr int KT2 = INTER  / KC;              // 296
constexpr int NB1 = INTER / 128;              // 148 (128 h-cols per pair)
constexpr int NB2 = HIDDEN / 256;             // 14
constexpr int MB  = TOKENS / 512;             // 8  (512 m-rows per pair)
}

// global tile buffers
__device__ __half g_x16[(size_t)MB  * KT1 * (ATILE / 2)];   // x: (mb,kt) 64KB tiles
__device__ __half g_wgu[(size_t)NB1 * KT1 * (BTILE / 2)];   // w_gu: (nb,kt) 32KB tiles
__device__ __half g_wd [(size_t)NB2 * KT2 * (BTILE / 2)];   // w_d:  (nb,kt) 32KB tiles
__device__ __half g_h16[(size_t)MB  * KT2 * (ATILE / 2)];   // h: (mb,kt) 64KB tiles

__host__ __device__ __forceinline__ uint32_t swz(uint32_t off) {
    return off ^ ((off >> 3) & 0x70);
}

// ---------------------------------------------------------------------------
// prep kernels
// ---------------------------------------------------------------------------
// weights: tile (bb, kt) = 32KB, rows 0-127 -> rank0 half, 128-255 -> rank1 half
template <int WHICH>   // 0 = w_gu (row<128: gate, else up), 1 = w_d
__global__ void __launch_bounds__(256) conv_w(const float* __restrict__ src) {
    constexpr int KTOT = (WHICH == 1) ? INTER : HIDDEN;
    constexpr int KT   = KTOT / KC;
    const int gid  = blockIdx.x * 256 + threadIdx.x;
    const int tile = gid >> 11;          // 2048 x 16B chunks per 32KB tile
    const int c    = gid & 2047;
    const int tr   = c >> 3;
    const int ch   = c & 7;
    const int kt   = tile % KT;
    const int bb   = tile / KT;

    int grow;
    if (WHICH == 0) grow = (tr < 128) ? (bb * 128 + tr) : (INTER + bb * 128 + (tr - 128));
    else            grow = bb * 256 + tr;

    const float* s = src + (size_t)grow * KTOT + kt * KC + ch * 8;
    float4 a = *reinterpret_cast<const float4*>(s);
    float4 b = *reinterpret_cast<const float4*>(s + 4);
    __half2 p0 = __floats2half2_rn(a.x, a.y);
    __half2 p1 = __floats2half2_rn(a.z, a.w);
    __half2 p2 = __floats2half2_rn(b.x, b.y);
    __half2 p3 = __floats2half2_rn(b.z, b.w);
    uint4 v = make_uint4(*reinterpret_cast<uint32_t*>(&p0), *reinterpret_cast<uint32_t*>(&p1),
                         *reinterpret_cast<uint32_t*>(&p2), *reinterpret_cast<uint32_t*>(&p3));
    __half* dstbuf = (WHICH == 0) ? g_wgu : g_wd;
    char* dst = reinterpret_cast<char*>(dstbuf) + (size_t)tile * BTILE
              + ((tr >> 7) * 16384)                       // rank half
              + swz((uint32_t)((tr & 127) * 128 + ch * 16));
    *reinterpret_cast<uint4*>(dst) = v;
}

// x: tile (mb, kt) = 64KB = [rank0: half0 128 rows, half1 128][rank1: ...]
// token m = mb*512 + half*256 + rank*128 + r
__global__ void __launch_bounds__(256) conv_x(const float* __restrict__ src) {
    const int gid  = blockIdx.x * 256 + threadIdx.x;
    const int tile = gid >> 12;          // 4096 x 16B chunks per 64KB tile
    const int c    = gid & 4095;
    const int sr   = c >> 3;             // storage row 0..511
    const int ch   = c & 7;
    const int kt   = tile % KT1;
    const int mb   = tile / KT1;
    const int rank = sr >> 8;
    const int wr   = sr & 255;           // row within rank block
    const int half = wr >> 7;
    const int r    = wr & 127;
    const int m    = mb * 512 + half * 256 + rank * 128 + r;

    const float* s = src + (size_t)m * HIDDEN + kt * KC + ch * 8;
    float4 a = *reinterpret_cast<const float4*>(s);
    float4 b = *reinterpret_cast<const float4*>(s + 4);
    __half2 p0 = __floats2half2_rn(a.x, a.y);
    __half2 p1 = __floats2half2_rn(a.z, a.w);
    __half2 p2 = __floats2half2_rn(b.x, b.y);
    __half2 p3 = __floats2half2_rn(b.z, b.w);
    uint4 v = make_uint4(*reinterpret_cast<uint32_t*>(&p0), *reinterpret_cast<uint32_t*>(&p1),
                         *reinterpret_cast<uint32_t*>(&p2), *reinterpret_cast<uint32_t*>(&p3));
    char* dst = reinterpret_cast<char*>(g_x16) + (size_t)tile * ATILE
              + rank * 32768 + swz((uint32_t)(wr * 128 + ch * 16));
    *reinterpret_cast<uint4*>(dst) = v;
}

// ---------------------------------------------------------------------------
// device helpers
// ---------------------------------------------------------------------------
#if USE_TCGEN05
__device__ __forceinline__ bool elect_one() {
    uint32_t p;
    asm volatile("{\n\t.reg .pred p;\n\telect.sync _|p, 0xFFFFFFFF;\n\t"
                 "selp.b32 %0, 1, 0, p;\n\t}" : "=r"(p));
    return p != 0;
}
__device__ __forceinline__ uint32_t ctarank() {
    uint32_t r;
    asm("mov.u32 %0, %%cluster_ctarank;" : "=r"(r));
    return r;
}
__device__ __forceinline__ void mbar_init(uint32_t addr, uint32_t count) {
    asm volatile("mbarrier.init.shared.b64 [%0], %1;" :: "r"(addr), "r"(count) : "memory");
}
__device__ __forceinline__ void mbar_wait(uint32_t addr, uint32_t parity) {
    asm volatile(
        "{\n\t.reg .pred P;\n\t"
        "WL_%=:\n\t"
        "mbarrier.try_wait.parity.acquire.cta.shared::cta.b64 P, [%0], %1, 0x989680;\n\t"
        "@P bra.uni WD_%=;\n\t"
        "bra.uni WL_%=;\n\t"
        "WD_%=:\n\t}"
        :: "r"(addr), "r"(parity) : "memory");
}
__device__ __forceinline__ void mbar_expect_tx(uint32_t addr, uint32_t bytes) {
    asm volatile("mbarrier.arrive.expect_tx.shared.b64 _, [%0], %1;"
                 :: "r"(addr), "r"(bytes) : "memory");
}
__device__ __forceinline__ void mbar_arrive_remote(uint32_t local_addr, uint32_t target_rank) {
    asm volatile(
        "{\n\t.reg .b32 ra;\n\t"
        "mapa.shared::cluster.u32 ra, %0, %1;\n\t"
        "mbarrier.arrive.shared::cluster.b64 _, [ra];\n\t}"
        :: "r"(local_addr), "r"(target_rank) : "memory");
}
__device__ __forceinline__ void bulk_g2s(uint32_t dst, const void* src, uint32_t bytes,
                                         uint32_t mbar) {
    asm volatile(
        "cp.async.bulk.shared::cluster.global.mbarrier::complete_tx::bytes "
        "[%0], [%1], %2, [%3];"
        :: "r"(dst), "l"(src), "r"(bytes), "r"(mbar) : "memory");
}
__device__ __forceinline__ void tc_alloc_cg2(uint32_t dst_smem, uint32_t ncols) {
    asm volatile("tcgen05.alloc.cta_group::2.sync.aligned.shared::cta.b32 [%0], %1;"
                 :: "r"(dst_smem), "r"(ncols) : "memory");
}
__device__ __forceinline__ void tc_relinquish_cg2() {
    asm volatile("tcgen05.relinquish_alloc_permit.cta_group::2.sync.aligned;");
}
__device__ __forceinline__ void tc_dealloc_cg2(uint32_t tmem, uint32_t ncols) {
    asm volatile("tcgen05.dealloc.cta_group::2.sync.aligned.b32 %0, %1;"
                 :: "r"(tmem), "r"(ncols));
}
__device__ __forceinline__ void tc_commit_mc_cg2(uint32_t mbar, uint16_t mask) {
    asm volatile(
        "tcgen05.commit.cta_group::2.mbarrier::arrive::one.shared::cluster.multicast::cluster.b64 "
        "[%0], %1;"
        :: "r"(mbar), "h"(mask) : "memory");
}
__device__ __forceinline__ void tc_wait_ld() {
    asm volatile("tcgen05.wait::ld.sync.aligned;" ::: "memory");
}
__device__ __forceinline__ uint64_t sdesc(uint32_t addr) {
    return ((uint64_t)((addr >> 4) & 0x3FFF))
         | (1ULL  << 16) | (64ULL << 32) | (1ULL << 46) | (2ULL << 61);  // SW128 K-major
}
// cg2 kind::f16 SS MMA (fp16 x fp16 -> fp32), M=256 per dispatch
__device__ __forceinline__ void mma_f16_ss_cg2(uint32_t d_tmem, uint64_t ad, uint64_t bd,
                                               uint32_t idesc, uint32_t enable_d) {
    asm volatile(
        "{\n\t.reg .pred p;\n\t"
        "setp.ne.u32 p, %4, 0;\n\t"
        "tcgen05.mma.cta_group::2.kind::f16 [%0], %1, %2, %3, "
        "{%5,%5,%5,%5,%5,%5,%5,%5}, p;\n\t}"
        :: "r"(d_tmem), "l"(ad), "l"(bd), "r"(idesc), "r"(enable_d), "r"(0u)
        : "memory");
}
__device__ __forceinline__ void ldtm32(uint32_t* r, uint32_t ta) {
    asm volatile(
        "tcgen05.ld.sync.aligned.32x32b.x32.b32 "
        "{%0,%1,%2,%3,%4,%5,%6,%7,%8,%9,%10,%11,%12,%13,%14,%15,"
        "%16,%17,%18,%19,%20,%21,%22,%23,%24,%25,%26,%27,%28,%29,%30,%31}, [%32];"
        : "=r"(r[0]),  "=r"(r[1]),  "=r"(r[2]),  "=r"(r[3]),
          "=r"(r[4]),  "=r"(r[5]),  "=r"(r[6]),  "=r"(r[7]),
          "=r"(r[8]),  "=r"(r[9]),  "=r"(r[10]), "=r"(r[11]),
          "=r"(r[12]), "=r"(r[13]), "=r"(r[14]), "=r"(r[15]),
          "=r"(r[16]), "=r"(r[17]), "=r"(r[18]), "=r"(r[19]),
          "=r"(r[20]), "=r"(r[21]), "=r"(r[22]), "=r"(r[23]),
          "=r"(r[24]), "=r"(r[25]), "=r"(r[26]), "=r"(r[27]),
          "=r"(r[28]), "=r"(r[29]), "=r"(r[30]), "=r"(r[31])
        : "r"(ta));
}
#endif

// fallback read helpers (tiled layouts)
__device__ __forceinline__ float rd_a(const __half* buf, int KT, int m, int k) {
    const int mb = m >> 9, mm = m & 511;
    const int rank = (mm >> 7) & 1;
    const int wr = ((mm >> 8) << 7) | (mm & 127);
    const char* p = reinterpret_cast<const char*>(buf)
                  + ((size_t)mb * KT + (k >> 6)) * ATILE + rank * 32768
                  + swz((uint32_t)(wr * 128 + ((k & 63) >> 3) * 16)) + (k & 7) * 2;
    return __half2float(*reinterpret_cast<const __half*>(p));
}
__device__ __forceinline__ float rd_b(const __half* buf, int KT, int tile_b, int tr, int k) {
    const char* p = reinterpret_cast<const char*>(buf)
                  + ((size_t)tile_b * KT + (k >> 6)) * BTILE + (tr >> 7) * 16384
                  + swz((uint32_t)((tr & 127) * 128 + ((k & 63) >> 3) * 16)) + (k & 7) * 2;
    return __half2float(*reinterpret_cast<const __half*>(p));
}

// ---------------------------------------------------------------------------
// MODE 0: gate_up + SiLU*Mul -> g_h16 tiles.  grid (16, 148), cluster (2,1,1)
//         pair: M=512 tokens x (128 gate + 128 up cols)
// MODE 1: down -> out fp32.  grid (16, 14): pair M=512 x 256 out cols
// ---------------------------------------------------------------------------
template <int MODE>
__global__ void __launch_bounds__(THREADS, 1) __cluster_dims__(2, 1, 1)
mlp_gemm(const float* __restrict__ S, float* __restrict__ Out)
{
    constexpr int KT = (MODE == 0) ? KT1 : KT2;
    extern __shared__ char smem[];
    const int t    = threadIdx.x;
    const int wid  = t >> 5;
    const int lane = t & 31;
    const int mb   = blockIdx.x >> 1;
    const int nb   = blockIdx.y;
    const int n0   = nb * ((MODE == 0) ? 128 : 256);

#if USE_TCGEN05
    // idesc: dtype F32, atype=btype=F16, N=256, M=256
    constexpr uint32_t IDESC = (1u << 4) | (32u << 17) | (16u << 24);

    const uint32_t sbase     = (uint32_t)__cvta_generic_to_shared(smem);
    const uint32_t tptr_addr = sbase;
    const uint32_t bar_full  = sbase + 8;
    const uint32_t bar_empty = bar_full + NSTG * 8;
    const uint32_t bar_done  = bar_empty + NSTG * 8;
    const uint32_t data_u    = (sbase + 128 + 1023) & ~1023u;
    const uint32_t rank      = ctarank();

    if (wid == 0) { tc_alloc_cg2(tptr_addr, 512); tc_relinquish_cg2(); }
    if (t == 0) {
        for (int s = 0; s < NSTG; s++) {
            // rank0 full: expect_tx arrive (1) + rank1 relay arrive (1)
            mbar_init(bar_full  + s * 8, (rank == 0) ? 2u : 1u);
            mbar_init(bar_empty + s * 8, 1);
        }
        mbar_init(bar_done, 1);
    }
    __syncthreads();
    asm volatile("barrier.cluster.arrive.aligned;" ::: "memory");
    asm volatile("barrier.cluster.wait.aligned;"   ::: "memory");

    uint32_t tmem;
    asm volatile("ld.shared.b32 %0, [%1];" : "=r"(tmem) : "r"(tptr_addr));

    const char* a_base = reinterpret_cast<const char*>((MODE == 0) ? g_x16 : g_h16)
                       + (size_t)mb * KT * ATILE + rank * 32768;
    const char* b_base = reinterpret_cast<const char*>((MODE == 0) ? g_wgu : g_wd)
                       + (size_t)nb * KT * BTILE + rank * 16384;

    if (t == 32) {
        // ---------------- producer (both ranks) ----------------
        #pragma unroll 1
        for (int kt = 0; kt < KT; kt++) {
            const int s = kt % NSTG;
            if (kt >= NSTG) mbar_wait(bar_empty + s * 8, ((uint32_t)(kt / NSTG) - 1) & 1);
            const uint32_t As = data_u + s * STAGE_BYTES;
            mbar_expect_tx(bar_full + s * 8, STAGE_BYTES);
            bulk_g2s(As,           a_base + (size_t)kt * ATILE, A_BYTES, bar_full + s * 8);
            bulk_g2s(As + A_BYTES, b_base + (size_t)kt * BTILE, B_BYTES, bar_full + s * 8);
        }
    } else if (t == 64 && rank == 1) {
        // ---------------- relay: signal leader when our stage is resident ----
        #pragma unroll 1
        for (int kt = 0; kt < KT; kt++) {
            const int s = kt % NSTG;
            mbar_wait(bar_full + s * 8, (uint32_t)(kt / NSTG) & 1);
            mbar_arrive_remote(bar_full + s * 8, 0);
        }
    } else if (wid == 0 && rank == 0) {
        // ---------------- MMA issuer (leader) ----------------
        if (elect_one()) {
            #pragma unroll 1
            for (int kt = 0; kt < KT; kt++) {
                const int s = kt % NSTG;
                mbar_wait(bar_full + s * 8, (uint32_t)(kt / NSTG) & 1);
                const uint32_t As = data_u + s * STAGE_BYTES;
                const uint64_t ad0 = sdesc(As);            // M-half 0 (A rows 0-127/CTA)
                const uint64_t ad1 = sdesc(As + 16384);    // M-half 1
                const uint64_t bd  = sdesc(As + A_BYTES);
                #pragma unroll
                for (int kk = 0; kk < 4; kk++) {           // 4 x K=16 == KC
                    const uint32_t en = (kt > 0 || kk > 0) ? 1u : 0u;
                    mma_f16_ss_cg2(tmem,       ad0 + 2 * kk, bd + 2 * kk, IDESC, en);
                    mma_f16_ss_cg2(tmem + 256, ad1 + 2 * kk, bd + 2 * kk, IDESC, en);
                }
                tc_commit_mc_cg2(bar_empty + s * 8, (uint16_t)0x3);
            }
            tc_commit_mc_cg2(bar_done, (uint16_t)0x3);
        }
    }

    mbar_wait(bar_done, 0);
    asm volatile("tcgen05.fence::after_thread_sync;" ::: "memory");

    // ---- epilogue: warp (h = wid>>2, sp = wid&3); this CTA holds 128 rows/half
    const int h  = wid >> 2;
    const int sp = wid & 3;
    const int m  = mb * 512 + h * 256 + (int)rank * 128 + sp * 32 + lane;  // token/out row
    const uint32_t tbase = tmem + h * 256;

    if (MODE == 0) {
        const int mm    = m & 511;
        const int rank2 = (mm >> 7) & 1;
        const int wr2   = ((mm >> 8) << 7) | (mm & 127);
        char* hb = reinterpret_cast<char*>(g_h16)
                 + (size_t)(m >> 9) * KT2 * ATILE + rank2 * 32768;
        #pragma unroll
        for (int c = 0; c < 4; c++) {
            const int cb = c * 32;
            uint32_t gr[32], ur[32];
            ldtm32(gr, tbase + cb);            // gate: D cols [0,128)
            ldtm32(ur, tbase + 128 + cb);      // up:   D cols [128,256)
            tc_wait_ld();
            uint32_t oh[16];
            #pragma unroll
            for (int p = 0; p < 16; p++) {
                const int i = 2 * p;
                const int n = n0 + cb + i;
                float g0 = __uint_as_float(gr[i])     * __ldg(S + n);
                float g1 = __uint_as_float(gr[i + 1]) * __ldg(S + n + 1);
                float u0 = __uint_as_float(ur[i])     * __ldg(S + INTER + n);
                float u1 = __uint_as_float(ur[i + 1]) * __ldg(S + INTER + n + 1);
                float h0 = g0 * (1.0f / (1.0f + __expf(-g0))) * u0;
                float h1 = g1 * (1.0f / (1.0f + __expf(-g1))) * u1;
                __half2 ph = __floats2half2_rn(h0, h1);
                oh[p] = *reinterpret_cast<uint32_t*>(&ph);
            }
            #pragma unroll
            for (int q = 0; q < 4; q++) {
                const int col = n0 + cb + q * 8;
                char* tb = hb + (size_t)(col >> 6) * ATILE;
                const uint32_t off = swz((uint32_t)(wr2 * 128 + ((col & 63) >> 3) * 16));
                *reinterpret_cast<uint4*>(tb + off) =
                    make_uint4(oh[4 * q], oh[4 * q + 1], oh[4 * q + 2], oh[4 * q + 3]);
            }
        }
    } else {
        #pragma unroll
        for (int c = 0; c < 8; c++) {
            const int cb = c * 32;
            uint32_t dr[32];
            ldtm32(dr, tbase + cb);
            tc_wait_ld();
            float* op = Out + (size_t)m * HIDDEN + n0 + cb;
            #pragma unroll
            for (int q = 0; q < 8; q++) {
                float r[4];
                #pragma unroll
                for (int j = 0; j < 4; j++) {
                    const int i = q * 4 + j;
                    r[j] = __uint_as_float(dr[i]) * __ldg(S + n0 + cb + i);
                }
                reinterpret_cast<float4*>(op)[q] = make_float4(r[0], r[1], r[2], r[3]);
            }
        }
    }

    __syncthreads();
    if (wid == 0) tc_dealloc_cg2(tmem, 512);
    asm volatile("barrier.cluster.arrive.aligned;" ::: "memory");
    asm volatile("barrier.cluster.wait.aligned;"   ::: "memory");

#else
    // non-103a compile pass only (never selected at runtime on GB300)
    (void)smem; (void)wid; (void)lane;
    const int rankf = blockIdx.x & 1;
    constexpr int KTOT = (MODE == 0) ? HIDDEN : INTER;
    constexpr int NCOL = (MODE == 0) ? 128 : 256;
    // this CTA covers its 256 rows (2 halves x 128) and all NCOL output cols
    for (int o = t; o < 256 * NCOL; o += THREADS) {
        const int rr = o / NCOL, cc = o % NCOL;
        const int m = mb * 512 + (rr >> 7) * 256 + rankf * 128 + (rr & 127);
        if (MODE == 0) {
            float accg = 0.f, accu = 0.f;
            for (int k = 0; k < KTOT; k++) {
                float a = rd_a(g_x16, KT1, m, k);
                accg += a * rd_b(g_wgu, KT1, nb, cc, k);         // gate rows 0-127
                accu += a * rd_b(g_wgu, KT1, nb, 128 + cc, k);   // up rows 128-255
            }
            float g = accg * S[n0 + cc], u = accu * S[INTER + n0 + cc];
            float hv = g * (1.0f / (1.0f + __expf(-g))) * u;
            // write into h tile image
            const int col = n0 + cc;
            const int mm = m & 511;
            const int rank2 = (mm >> 7) & 1;
            const int wr2 = ((mm >> 8) << 7) | (mm & 127);
            char* p = reinterpret_cast<char*>(g_h16)
                    + ((size_t)(m >> 9) * KT2 + (col >> 6)) * ATILE + rank2 * 32768
                    + swz((uint32_t)(wr2 * 128 + ((col & 63) >> 3) * 16)) + (col & 7) * 2;
            *reinterpret_cast<__half*>(p) = __float2half_rn(hv);
        } else {
            float acc = 0.f;
            for (int k = 0; k < KTOT; k++)
                acc += rd_a(g_h16, KT2, m, k) * rd_b(g_wd, KT2, nb, cc, k);
            Out[(size_t)m * HIDDEN + n0 + cc] = acc * S[n0 + cc];
        }
    }
#endif
}

// ---------------------------------------------------------------------------
// launch
// ---------------------------------------------------------------------------
extern "C" void kernel_launch(void* const* d_in, const int* in_sizes, int n_in,
                              void* d_out, int out_size)
{
    const float* x = nullptr; const float* w_gu = nullptr; const float* s_gu = nullptr;
    const float* w_d = nullptr; const float* s_d = nullptr;
    for (int i = 0; i < n_in; i++) {
        long long sz = in_sizes[i];
        const float* p = (const float*)d_in[i];
        if      (sz == (long long)TOKENS * HIDDEN)    x    = p;
        else if (sz == (long long)2 * INTER * HIDDEN) w_gu = p;
        else if (sz == (long long)2 * INTER)          s_gu = p;
        else if (sz == (long long)HIDDEN * INTER)     w_d  = p;
        else if (sz == (long long)HIDDEN)             s_d  = p;
    }
    float* out = (float*)d_out;

    constexpr int SMEM = 2048 + NSTG * STAGE_BYTES;   // 198,656
    cudaFuncSetAttribute(mlp_gemm<0>, cudaFuncAttributeMaxDynamicSharedMemorySize, SMEM);
    cudaFuncSetAttribute(mlp_gemm<1>, cudaFuncAttributeMaxDynamicSharedMemorySize, SMEM);

    // prep
    conv_w<0><<<(NB1 * KT1 * 2048) / 256, 256>>>(w_gu);
    conv_w<1><<<(NB2 * KT2 * 2048) / 256, 256>>>(w_d);
    conv_x<<<(MB * KT1 * 4096) / 256, 256>>>(x);

    // GEMM1: gate_up + SiLU*Mul -> g_h16 tiles
    dim3 g1(2 * MB, NB1);                  // (16, 148) CTAs, clusters of 2 on x
    mlp_gemm<0><<<g1, THREADS, SMEM>>>(s_gu, nullptr);

    // GEMM2: down -> out
    dim3 g2(2 * MB, NB2);                  // (16, 14)
    mlp_gemm<1><<<g2, THREADS, SMEM>>>(s_d, out);
}

// round 10
// speedup vs baseline: 8.6992x; 1.1011x over previous
#include <cuda_runtime.h>
#include <cuda_fp16.h>
#include <cstdint>

// ---------------------------------------------------------------------------
// Qwen2 FP8 MLP, fp16 tcgen05 cta_group::2 PERSISTENT version (R9 + fix).
//   R9 crash root-cause: epilogue mbar_arrive_remote executed by all 32 lanes
//   (mbarrier over-arrive = UB). Now lane-guarded via elect_one().
//   74 persistent CTA pairs; one TMEM alloc / cluster sync; TMA producer
//   streams across tiles; epilogue warps overlap LDTM/stores with next tile's
//   MMAs (split elo/ehi TMEM-free gating). GEMM2 uses N=224 tiles.
// ---------------------------------------------------------------------------

#if defined(__CUDA_ARCH_FEAT_SM103_ALL) || defined(__CUDA_ARCH_FEAT_SM100_ALL) || defined(__CUDA_ARCH_SPECIFIC__)
#define USE_TCGEN05 1
#else
#define USE_TCGEN05 0
#endif

namespace {
constexpr int HIDDEN = 3584;
constexpr int INTER  = 18944;
constexpr int TOKENS = 4096;

constexpr int KC      = 64;                   // 64 fp16 = 128B row
constexpr int NSTG    = 4;
constexpr int THREADS = 384;                  // warps 0-3 control, 4-11 epilogue
constexpr int NPAIRS  = 74;

constexpr int A_BYTES = 32768;                // per CTA: 256 A rows
constexpr int ATILE   = 65536;                // global A tile (512 rows, both ranks)

constexpr int KT1 = HIDDEN / KC;              // 56
constexpr int KT2 = INTER  / KC;              // 296

// GEMM1: pair tile M=512 x 128 h-cols (MMA N=256: 128 gate + 128 up)
constexpr int NB1     = INTER / 128;          // 148
constexpr int BTILE1  = 32768;                // 256 B rows
constexpr int BB1     = 16384;                // per-CTA B bytes (128 rows)
constexpr int NT1     = (TOKENS / 512) * NB1; // 1184 tiles = 74 * 16

// GEMM2: pair tile M=512 x N=224
constexpr int N2      = 224;
constexpr int NB2     = HIDDEN / N2;          // 16
constexpr int BTILE2  = N2 * 128;             // 28672 (224 rows)
constexpr int BB2     = BTILE2 / 2;           // 14336 (112 rows per CTA)
constexpr int NT2     = (TOKENS / 512) * NB2; // 128 tiles
}

// global tile buffers
__device__ __half g_x16[(size_t)(TOKENS / 512) * KT1 * (ATILE / 2)];
__device__ __half g_wgu[(size_t)NB1 * KT1 * (BTILE1 / 2)];
__device__ __half g_wd [(size_t)NB2 * KT2 * (BTILE2 / 2)];
__device__ __half g_h16[(size_t)(TOKENS / 512) * KT2 * (ATILE / 2)];

__host__ __device__ __forceinline__ uint32_t swz(uint32_t off) {
    return off ^ ((off >> 3) & 0x70);
}

// ---------------------------------------------------------------------------
// prep kernels
// ---------------------------------------------------------------------------
__global__ void __launch_bounds__(256) conv_wgu(const float* __restrict__ src) {
    const int gid  = blockIdx.x * 256 + threadIdx.x;
    const int tile = gid >> 11;
    const int c    = gid & 2047;
    const int tr   = c >> 3;
    const int ch   = c & 7;
    const int kt   = tile % KT1;
    const int bb   = tile / KT1;
    const int grow = (tr < 128) ? (bb * 128 + tr) : (INTER + bb * 128 + (tr - 128));

    const float* s = src + (size_t)grow * HIDDEN + kt * KC + ch * 8;
    float4 a = *reinterpret_cast<const float4*>(s);
    float4 b = *reinterpret_cast<const float4*>(s + 4);
    __half2 p0 = __floats2half2_rn(a.x, a.y);
    __half2 p1 = __floats2half2_rn(a.z, a.w);
    __half2 p2 = __floats2half2_rn(b.x, b.y);
    __half2 p3 = __floats2half2_rn(b.z, b.w);
    uint4 v = make_uint4(*reinterpret_cast<uint32_t*>(&p0), *reinterpret_cast<uint32_t*>(&p1),
                         *reinterpret_cast<uint32_t*>(&p2), *reinterpret_cast<uint32_t*>(&p3));
    char* dst = reinterpret_cast<char*>(g_wgu) + (size_t)tile * BTILE1
              + ((tr >> 7) * 16384) + swz((uint32_t)((tr & 127) * 128 + ch * 16));
    *reinterpret_cast<uint4*>(dst) = v;
}

__global__ void __launch_bounds__(256) conv_wd(const float* __restrict__ src) {
    const int gid  = blockIdx.x * 256 + threadIdx.x;
    const int tile = gid / 1792;
    const int c    = gid % 1792;
    const int tr   = c >> 3;              // 0..223
    const int ch   = c & 7;
    const int kt   = tile % KT2;
    const int bb   = tile / KT2;
    const int grow = bb * N2 + tr;

    const float* s = src + (size_t)grow * INTER + kt * KC + ch * 8;
    float4 a = *reinterpret_cast<const float4*>(s);
    float4 b = *reinterpret_cast<const float4*>(s + 4);
    __half2 p0 = __floats2half2_rn(a.x, a.y);
    __half2 p1 = __floats2half2_rn(a.z, a.w);
    __half2 p2 = __floats2half2_rn(b.x, b.y);
    __half2 p3 = __floats2half2_rn(b.z, b.w);
    uint4 v = make_uint4(*reinterpret_cast<uint32_t*>(&p0), *reinterpret_cast<uint32_t*>(&p1),
                         *reinterpret_cast<uint32_t*>(&p2), *reinterpret_cast<uint32_t*>(&p3));
    const int half = tr / 112;
    const int wr   = tr - half * 112;
    char* dst = reinterpret_cast<char*>(g_wd) + (size_t)tile * BTILE2
              + half * BB2 + swz((uint32_t)(wr * 128 + ch * 16));
    *reinterpret_cast<uint4*>(dst) = v;
}

__global__ void __launch_bounds__(256) conv_x(const float* __restrict__ src) {
    const int gid  = blockIdx.x * 256 + threadIdx.x;
    const int tile = gid >> 12;
    const int c    = gid & 4095;
    const int sr   = c >> 3;
    const int ch   = c & 7;
    const int kt   = tile % KT1;
    const int mb   = tile / KT1;
    const int rank = sr >> 8;
    const int wr   = sr & 255;
    const int m    = mb * 512 + (wr >> 7) * 256 + rank * 128 + (wr & 127);

    const float* s = src + (size_t)m * HIDDEN + kt * KC + ch * 8;
    float4 a = *reinterpret_cast<const float4*>(s);
    float4 b = *reinterpret_cast<const float4*>(s + 4);
    __half2 p0 = __floats2half2_rn(a.x, a.y);
    __half2 p1 = __floats2half2_rn(a.z, a.w);
    __half2 p2 = __floats2half2_rn(b.x, b.y);
    __half2 p3 = __floats2half2_rn(b.z, b.w);
    uint4 v = make_uint4(*reinterpret_cast<uint32_t*>(&p0), *reinterpret_cast<uint32_t*>(&p1),
                         *reinterpret_cast<uint32_t*>(&p2), *reinterpret_cast<uint32_t*>(&p3));
    char* dst = reinterpret_cast<char*>(g_x16) + (size_t)tile * ATILE
              + rank * 32768 + swz((uint32_t)(wr * 128 + ch * 16));
    *reinterpret_cast<uint4*>(dst) = v;
}

// ---------------------------------------------------------------------------
// device helpers
// ---------------------------------------------------------------------------
#if USE_TCGEN05
__device__ __forceinline__ bool elect_one() {
    uint32_t p;
    asm volatile("{\n\t.reg .pred p;\n\telect.sync _|p, 0xFFFFFFFF;\n\t"
                 "selp.b32 %0, 1, 0, p;\n\t}" : "=r"(p));
    return p != 0;
}
__device__ __forceinline__ uint32_t ctarank() {
    uint32_t r;
    asm("mov.u32 %0, %%cluster_ctarank;" : "=r"(r));
    return r;
}
__device__ __forceinline__ void mbar_init(uint32_t addr, uint32_t count) {
    asm volatile("mbarrier.init.shared.b64 [%0], %1;" :: "r"(addr), "r"(count) : "memory");
}
__device__ __forceinline__ void mbar_wait(uint32_t addr, uint32_t parity) {
    asm volatile(
        "{\n\t.reg .pred P;\n\t"
        "WL_%=:\n\t"
        "mbarrier.try_wait.parity.acquire.cta.shared::cta.b64 P, [%0], %1, 0x989680;\n\t"
        "@P bra.uni WD_%=;\n\t"
        "bra.uni WL_%=;\n\t"
        "WD_%=:\n\t}"
        :: "r"(addr), "r"(parity) : "memory");
}
__device__ __forceinline__ void mbar_expect_tx(uint32_t addr, uint32_t bytes) {
    asm volatile("mbarrier.arrive.expect_tx.shared.b64 _, [%0], %1;"
                 :: "r"(addr), "r"(bytes) : "memory");
}
__device__ __forceinline__ void mbar_arrive_remote(uint32_t local_addr, uint32_t target_rank) {
    asm volatile(
        "{\n\t.reg .b32 ra;\n\t"
        "mapa.shared::cluster.u32 ra, %0, %1;\n\t"
        "mbarrier.arrive.shared::cluster.b64 _, [ra];\n\t}"
        :: "r"(local_addr), "r"(target_rank) : "memory");
}
__device__ __forceinline__ void bulk_g2s(uint32_t dst, const void* src, uint32_t bytes,
                                         uint32_t mbar) {
    asm volatile(
        "cp.async.bulk.shared::cluster.global.mbarrier::complete_tx::bytes "
        "[%0], [%1], %2, [%3];"
        :: "r"(dst), "l"(src), "r"(bytes), "r"(mbar) : "memory");
}
__device__ __forceinline__ void tc_alloc_cg2(uint32_t dst_smem, uint32_t ncols) {
    asm volatile("tcgen05.alloc.cta_group::2.sync.aligned.shared::cta.b32 [%0], %1;"
                 :: "r"(dst_smem), "r"(ncols) : "memory");
}
__device__ __forceinline__ void tc_relinquish_cg2() {
    asm volatile("tcgen05.relinquish_alloc_permit.cta_group::2.sync.aligned;");
}
__device__ __forceinline__ void tc_dealloc_cg2(uint32_t tmem, uint32_t ncols) {
    asm volatile("tcgen05.dealloc.cta_group::2.sync.aligned.b32 %0, %1;"
                 :: "r"(tmem), "r"(ncols));
}
__device__ __forceinline__ void tc_commit_mc_cg2(uint32_t mbar, uint16_t mask) {
    asm volatile(
        "tcgen05.commit.cta_group::2.mbarrier::arrive::one.shared::cluster.multicast::cluster.b64 "
        "[%0], %1;"
        :: "r"(mbar), "h"(mask) : "memory");
}
__device__ __forceinline__ void tc_wait_ld() {
    asm volatile("tcgen05.wait::ld.sync.aligned;" ::: "memory");
}
__device__ __forceinline__ uint64_t sdesc(uint32_t addr) {
    return ((uint64_t)((addr >> 4) & 0x3FFF))
         | (1ULL  << 16) | (64ULL << 32) | (1ULL << 46) | (2ULL << 61);  // SW128 K-major
}
__device__ __forceinline__ void mma_f16_ss_cg2(uint32_t d_tmem, uint64_t ad, uint64_t bd,
                                               uint32_t idesc, uint32_t enable_d) {
    asm volatile(
        "{\n\t.reg .pred p;\n\t"
        "setp.ne.u32 p, %4, 0;\n\t"
        "tcgen05.mma.cta_group::2.kind::f16 [%0], %1, %2, %3, "
        "{%5,%5,%5,%5,%5,%5,%5,%5}, p;\n\t}"
        :: "r"(d_tmem), "l"(ad), "l"(bd), "r"(idesc), "r"(enable_d), "r"(0u)
        : "memory");
}
__device__ __forceinline__ void ldtm32(uint32_t* r, uint32_t ta) {
    asm volatile(
        "tcgen05.ld.sync.aligned.32x32b.x32.b32 "
        "{%0,%1,%2,%3,%4,%5,%6,%7,%8,%9,%10,%11,%12,%13,%14,%15,"
        "%16,%17,%18,%19,%20,%21,%22,%23,%24,%25,%26,%27,%28,%29,%30,%31}, [%32];"
        : "=r"(r[0]),  "=r"(r[1]),  "=r"(r[2]),  "=r"(r[3]),
          "=r"(r[4]),  "=r"(r[5]),  "=r"(r[6]),  "=r"(r[7]),
          "=r"(r[8]),  "=r"(r[9]),  "=r"(r[10]), "=r"(r[11]),
          "=r"(r[12]), "=r"(r[13]), "=r"(r[14]), "=r"(r[15]),
          "=r"(r[16]), "=r"(r[17]), "=r"(r[18]), "=r"(r[19]),
          "=r"(r[20]), "=r"(r[21]), "=r"(r[22]), "=r"(r[23]),
          "=r"(r[24]), "=r"(r[25]), "=r"(r[26]), "=r"(r[27]),
          "=r"(r[28]), "=r"(r[29]), "=r"(r[30]), "=r"(r[31])
        : "r"(ta));
}
#endif

// fallback read helpers
__device__ __forceinline__ float rd_a(const __half* buf, int KT, int m, int k) {
    const int mb = m >> 9, mm = m & 511;
    const int rank = (mm >> 7) & 1;
    const int wr = ((mm >> 8) << 7) | (mm & 127);
    const char* p = reinterpret_cast<const char*>(buf)
                  + ((size_t)mb * KT + (k >> 6)) * ATILE + rank * 32768
                  + swz((uint32_t)(wr * 128 + ((k & 63) >> 3) * 16)) + (k & 7) * 2;
    return __half2float(*reinterpret_cast<const __half*>(p));
}
__device__ __forceinline__ float rd_b(const __half* buf, int KT, int tile_b, int tr, int k,
                                      int tile_bytes, int half_rows) {
    const int half = tr / half_rows;
    const int wr   = tr - half * half_rows;
    const char* p = reinterpret_cast<const char*>(buf)
                  + ((size_t)tile_b * KT + (k >> 6)) * tile_bytes + half * (tile_bytes / 2)
                  + swz((uint32_t)(wr * 128 + ((k & 63) >> 3) * 16)) + (k & 7) * 2;
    return __half2float(*reinterpret_cast<const __half*>(p));
}

// ---------------------------------------------------------------------------
// Persistent GEMM. grid (148,1,1), cluster (2,1,1), 384 threads.
// ---------------------------------------------------------------------------
template <int MODE>
__global__ void __launch_bounds__(THREADS, 1) __cluster_dims__(2, 1, 1)
mlp_gemm(const float* __restrict__ S, float* __restrict__ Out)
{
    constexpr int KT      = (MODE == 0) ? KT1 : KT2;
    constexpr int NMMA    = (MODE == 0) ? 256 : N2;          // MMA N
    constexpr int BBYTES  = (MODE == 0) ? BB1 : BB2;         // per-CTA B bytes
    constexpr int BTILE   = (MODE == 0) ? BTILE1 : BTILE2;
    constexpr int STG_B   = A_BYTES + BBYTES;
    constexpr int CCH     = (MODE == 0) ? 4 : 7;             // epilogue 32-col chunks
    const int pair = blockIdx.x >> 1;
    const int ntp  = (MODE == 0) ? (NT1 / NPAIRS)
                                 : ((pair < NT2 - NPAIRS) ? 2 : 1);

    extern __shared__ char smem[];
    const int t    = threadIdx.x;
    const int wid  = t >> 5;
    const int lane = t & 31;

#if USE_TCGEN05
    constexpr uint32_t IDESC = (1u << 4) | ((uint32_t)(NMMA / 8) << 17) | (16u << 24);

    const uint32_t sbase     = (uint32_t)__cvta_generic_to_shared(smem);
    const uint32_t tptr_addr = sbase;
    const uint32_t bar_full  = sbase + 8;
    const uint32_t bar_empty = bar_full + NSTG * 8;
    const uint32_t bar_done  = bar_empty + NSTG * 8;
    const uint32_t bar_elo   = bar_done + 8;
    const uint32_t bar_ehi   = bar_done + 16;
    const uint32_t data_u    = (sbase + 128 + 1023) & ~1023u;
    const uint32_t rank      = ctarank();

    if (wid == 0) { tc_alloc_cg2(tptr_addr, 512); tc_relinquish_cg2(); }
    if (t == 0) {
        for (int s = 0; s < NSTG; s++) {
            mbar_init(bar_full  + s * 8, (rank == 0) ? 2u : 1u);  // tx + rank1 relay
            mbar_init(bar_empty + s * 8, 1);
        }
        mbar_init(bar_done, 1);
        mbar_init(bar_elo, 8);     // 4 warps x 2 CTAs, ONE arrive per warp
        mbar_init(bar_ehi, 8);
    }
    __syncthreads();
    asm volatile("barrier.cluster.arrive.aligned;" ::: "memory");
    asm volatile("barrier.cluster.wait.aligned;"   ::: "memory");

    uint32_t tmem;
    asm volatile("ld.shared.b32 %0, [%1];" : "=r"(tmem) : "r"(tptr_addr));

    const char* Abuf = reinterpret_cast<const char*>((MODE == 0) ? g_x16 : g_h16);
    const char* Bbuf = reinterpret_cast<const char*>((MODE == 0) ? g_wgu : g_wd);

    if (t == 32) {
        // ---------------- TMA producer (both ranks) ----------------
        uint32_t g = 0;
        for (int tl = 0; tl < ntp; tl++) {
            const int idx = tl * NPAIRS + pair;
            const int mb = idx & 7, nb = idx >> 3;
            const char* a_base = Abuf + (size_t)mb * KT * ATILE + rank * 32768;
            const char* b_base = Bbuf + (size_t)nb * KT * BTILE + rank * BBYTES;
            for (int kt = 0; kt < KT; kt++, g++) {
                const uint32_t s = g & (NSTG - 1);
                if (g >= NSTG) mbar_wait(bar_empty + s * 8, ((g >> 2) - 1) & 1);
                const uint32_t As = data_u + s * STG_B;
                mbar_expect_tx(bar_full + s * 8, STG_B);
                bulk_g2s(As,           a_base + (size_t)kt * ATILE, A_BYTES, bar_full + s * 8);
                bulk_g2s(As + A_BYTES, b_base + (size_t)kt * BTILE, BBYTES,  bar_full + s * 8);
            }
        }
    } else if (t == 64 && rank == 1) {
        // ---------------- relay: forward local full -> leader's full ----------
        const uint32_t total = (uint32_t)ntp * KT;
        for (uint32_t g = 0; g < total; g++) {
            const uint32_t s = g & (NSTG - 1);
            mbar_wait(bar_full + s * 8, (g >> 2) & 1);
            mbar_arrive_remote(bar_full + s * 8, 0);
        }
    } else if (wid == 0 && rank == 0) {
        // ---------------- MMA issuer (leader) ----------------
        if (elect_one()) {
            uint32_t g = 0;
            for (int tl = 0; tl < ntp; tl++) {
                for (int kt = 0; kt < KT; kt++, g++) {
                    const uint32_t s = g & (NSTG - 1);
                    mbar_wait(bar_full + s * 8, (g >> 2) & 1);
                    const uint32_t As = data_u + s * STG_B;
                    const uint64_t ad0 = sdesc(As);
                    const uint64_t ad1 = sdesc(As + 16384);
                    const uint64_t bd  = sdesc(As + A_BYTES);
                    if (kt == 0) {
                        if (tl > 0) mbar_wait(bar_elo, (tl - 1) & 1);
                        #pragma unroll
                        for (int kk = 0; kk < 4; kk++)
                            mma_f16_ss_cg2(tmem, ad0 + 2 * kk, bd + 2 * kk, IDESC, kk > 0);
                        if (tl > 0) mbar_wait(bar_ehi, (tl - 1) & 1);
                        #pragma unroll
                        for (int kk = 0; kk < 4; kk++)
                            mma_f16_ss_cg2(tmem + NMMA, ad1 + 2 * kk, bd + 2 * kk, IDESC, kk > 0);
                    } else {
                        #pragma unroll
                        for (int kk = 0; kk < 4; kk++) {
                            mma_f16_ss_cg2(tmem,        ad0 + 2 * kk, bd + 2 * kk, IDESC, 1);
                            mma_f16_ss_cg2(tmem + NMMA, ad1 + 2 * kk, bd + 2 * kk, IDESC, 1);
                        }
                    }
                    tc_commit_mc_cg2(bar_empty + s * 8, (uint16_t)0x3);
                }
                tc_commit_mc_cg2(bar_done, (uint16_t)0x3);
            }
        }
    } else if (wid >= 4) {
        // ---------------- epilogue warps (both ranks) ----------------
        const int mh = (wid >> 2) - 1;       // 0,1 = m-half / TMEM half
        const int sp = wid & 3;
        const uint32_t tbase = tmem + mh * NMMA;
        const uint32_t ebar  = (mh == 0) ? bar_elo : bar_ehi;
        for (int tl = 0; tl < ntp; tl++) {
            const int idx = tl * NPAIRS + pair;
            const int mb = idx & 7, nb = idx >> 3;
            mbar_wait(bar_done, tl & 1);
            asm volatile("tcgen05.fence::after_thread_sync;" ::: "memory");
            const int m = mb * 512 + mh * 256 + (int)rank * 128 + sp * 32 + lane;

            if (MODE == 0) {
                const int n0 = nb * 128;
                const int mm = m & 511;
                const int rank2 = (mm >> 7) & 1;
                const int wr2 = ((mm >> 8) << 7) | (mm & 127);
                char* hb = reinterpret_cast<char*>(g_h16)
                         + (size_t)(m >> 9) * KT2 * ATILE + rank2 * 32768;
                #pragma unroll
                for (int c = 0; c < 4; c++) {
                    const int cb = c * 32;
                    uint32_t gr[32], ur[32];
                    ldtm32(gr, tbase + cb);
                    ldtm32(ur, tbase + 128 + cb);
                    tc_wait_ld();
                    if (c == 3) {                       // TMEM half free for leader
                        if (elect_one()) mbar_arrive_remote(ebar, 0);
                    }
                    uint32_t oh[16];
                    #pragma unroll
                    for (int p = 0; p < 16; p++) {
                        const int i = 2 * p;
                        const int n = n0 + cb + i;
                        float g0 = __uint_as_float(gr[i])     * __ldg(S + n);
                        float g1 = __uint_as_float(gr[i + 1]) * __ldg(S + n + 1);
                        float u0 = __uint_as_float(ur[i])     * __ldg(S + INTER + n);
                        float u1 = __uint_as_float(ur[i + 1]) * __ldg(S + INTER + n + 1);
                        float h0 = g0 * (1.0f / (1.0f + __expf(-g0))) * u0;
                        float h1 = g1 * (1.0f / (1.0f + __expf(-g1))) * u1;
                        __half2 ph = __floats2half2_rn(h0, h1);
                        oh[p] = *reinterpret_cast<uint32_t*>(&ph);
                    }
                    #pragma unroll
                    for (int q = 0; q < 4; q++) {
                        const int col = n0 + cb + q * 8;
                        char* tb = hb + (size_t)(col >> 6) * ATILE;
                        const uint32_t off = swz((uint32_t)(wr2 * 128 + ((col & 63) >> 3) * 16));
                        *reinterpret_cast<uint4*>(tb + off) =
                            make_uint4(oh[4 * q], oh[4 * q + 1], oh[4 * q + 2], oh[4 * q + 3]);
                    }
                }
            } else {
                const int n0 = nb * N2;
                float* op = Out + (size_t)m * HIDDEN + n0;
                #pragma unroll
                for (int c = 0; c < CCH; c++) {
                    const int cb = c * 32;
                    uint32_t dr[32];
                    ldtm32(dr, tbase + cb);
                    tc_wait_ld();
                    if (c == CCH - 1) {
                        if (elect_one()) mbar_arrive_remote(ebar, 0);
                    }
                    #pragma unroll
                    for (int q = 0; q < 8; q++) {
                        float r[4];
                        #pragma unroll
                        for (int j = 0; j < 4; j++) {
                            const int i = q * 4 + j;
                            r[j] = __uint_as_float(dr[i]) * __ldg(S + n0 + cb + i);
                        }
                        reinterpret_cast<float4*>(op + cb)[q] =
                            make_float4(r[0], r[1], r[2], r[3]);
                    }
                }
            }
        }
    }

    __syncthreads();
    if (wid == 0) tc_dealloc_cg2(tmem, 512);
    asm volatile("barrier.cluster.arrive.aligned;" ::: "memory");
    asm volatile("barrier.cluster.wait.aligned;"   ::: "memory");

#else
    // non-103a compile pass only (never selected at runtime on GB300)
    (void)smem; (void)lane;
    const int rankf = blockIdx.x & 1;
    constexpr int KTOT = (MODE == 0) ? HIDDEN : INTER;
    constexpr int NCOL = (MODE == 0) ? 128 : N2;
    for (int tl = 0; tl < ntp; tl++) {
        const int idx = tl * NPAIRS + pair;
        const int mb = idx & 7, nb = idx >> 3;
        const int n0 = nb * NCOL;
        for (int o = t; o < 256 * NCOL; o += THREADS) {
            const int rr = o / NCOL, cc = o % NCOL;
            const int m = mb * 512 + (rr >> 7) * 256 + rankf * 128 + (rr & 127);
            if (MODE == 0) {
                float accg = 0.f, accu = 0.f;
                for (int k = 0; k < KTOT; k++) {
                    float a = rd_a(g_x16, KT1, m, k);
                    accg += a * rd_b(g_wgu, KT1, nb, cc, k, BTILE1, 128);
                    accu += a * rd_b(g_wgu, KT1, nb, 128 + cc, k, BTILE1, 128);
                }
                float g = accg * S[n0 + cc], u = accu * S[INTER + n0 + cc];
                float hv = g * (1.0f / (1.0f + __expf(-g))) * u;
                const int col = n0 + cc;
                const int mm = m & 511;
                const int rank2 = (mm >> 7) & 1;
                const int wr2 = ((mm >> 8) << 7) | (mm & 127);
                char* p = reinterpret_cast<char*>(g_h16)
                        + ((size_t)(m >> 9) * KT2 + (col >> 6)) * ATILE + rank2 * 32768
                        + swz((uint32_t)(wr2 * 128 + ((col & 63) >> 3) * 16)) + (col & 7) * 2;
                *reinterpret_cast<__half*>(p) = __float2half_rn(hv);
            } else {
                float acc = 0.f;
                for (int k = 0; k < KTOT; k++)
                    acc += rd_a(g_h16, KT2, m, k) * rd_b(g_wd, KT2, nb, cc, k, BTILE2, 112);
                Out[(size_t)m * HIDDEN + n0 + cc] = acc * S[n0 + cc];
            }
        }
    }
#endif
}

// ---------------------------------------------------------------------------
// launch
// ---------------------------------------------------------------------------
extern "C" void kernel_launch(void* const* d_in, const int* in_sizes, int n_in,
                              void* d_out, int out_size)
{
    const float* x = nullptr; const float* w_gu = nullptr; const float* s_gu = nullptr;
    const float* w_d = nullptr; const float* s_d = nullptr;
    for (int i = 0; i < n_in; i++) {
        long long sz = in_sizes[i];
        const float* p = (const float*)d_in[i];
        if      (sz == (long long)TOKENS * HIDDEN)    x    = p;
        else if (sz == (long long)2 * INTER * HIDDEN) w_gu = p;
        else if (sz == (long long)2 * INTER)          s_gu = p;
        else if (sz == (long long)HIDDEN * INTER)     w_d  = p;
        else if (sz == (long long)HIDDEN)             s_d  = p;
    }
    float* out = (float*)d_out;

    constexpr int SMEM0 = 1024 + NSTG * (A_BYTES + BB1);   // 197,632
    constexpr int SMEM1 = 1024 + NSTG * (A_BYTES + BB2);   // 189,440
    cudaFuncSetAttribute(mlp_gemm<0>, cudaFuncAttributeMaxDynamicSharedMemorySize, SMEM0);
    cudaFuncSetAttribute(mlp_gemm<1>, cudaFuncAttributeMaxDynamicSharedMemorySize, SMEM1);

    // prep
    conv_wgu<<<(NB1 * KT1 * 2048) / 256, 256>>>(w_gu);
    conv_wd <<<(NB2 * KT2 * 1792) / 256, 256>>>(w_d);
    conv_x  <<<((TOKENS / 512) * KT1 * 4096) / 256, 256>>>(x);

    // GEMM1: gate_up + SiLU*Mul -> g_h16 tiles (persistent, 74 pairs x 16 tiles)
    mlp_gemm<0><<<dim3(2 * NPAIRS, 1), THREADS, SMEM0>>>(s_gu, nullptr);

    // GEMM2: down -> out (persistent, N=224 tiles)
    mlp_gemm<1><<<dim3(2 * NPAIRS, 1), THREADS, SMEM1>>>(s_d, out);
}

// round 11
// speedup vs baseline: 9.7181x; 1.1171x over previous
#include <cuda_runtime.h>
#include <cuda_fp16.h>
#include <cuda_fp8.h>
#include <cstdint>

// ---------------------------------------------------------------------------
// Qwen2 FP8 MLP, fp16 tcgen05 cg2 persistent + FP8 WEIGHT DELIVERY.
//   Weights delivered as raw e4m3 (half the B bytes on the LTS-capped path),
//   dequantized to SW128 fp16 in SMEM by 2 dedicated warps per CTA (exact).
//   Dequant warps double as the cross-CTA readiness relay (arrive leader's
//   deq barrier). GEMM1 tiles ordered nb-major per pair for L2 weight reuse.
// ---------------------------------------------------------------------------

#if defined(__CUDA_ARCH_FEAT_SM103_ALL) || defined(__CUDA_ARCH_FEAT_SM100_ALL) || defined(__CUDA_ARCH_SPECIFIC__)
#define USE_TCGEN05 1
#else
#define USE_TCGEN05 0
#endif

namespace {
constexpr int HIDDEN = 3584;
constexpr int INTER  = 18944;
constexpr int TOKENS = 4096;

constexpr int KC      = 64;                   // 64 elems per stage row (128B fp16 / 64B fp8)
constexpr int NSTG    = 4;
constexpr int THREADS = 384;                  // w0 MMA, w1 producer, w2-3 dequant, w4-11 epilogue
constexpr int NPAIRS  = 74;

constexpr int A_BYTES = 32768;                // per CTA: 256 fp16 A rows
constexpr int ATILE   = 65536;                // global A tile (512 rows, both ranks)

constexpr int KT1 = HIDDEN / KC;              // 56
constexpr int KT2 = INTER  / KC;              // 296

// GEMM1: pair tile M=512 x 128 h-cols (MMA N=256: 128 gate + 128 up)
constexpr int NB1      = INTER / 128;         // 148
constexpr int BB1      = 16384;               // per-CTA fp16 B bytes (128 rows)
constexpr int BR1      = 8192;                // per-CTA raw fp8 B bytes
constexpr int BTILE1R  = 16384;               // global raw B tile (256 rows fp8)
constexpr int NT1      = (TOKENS / 512) * NB1;// 1184 = 74*16

// GEMM2: pair tile M=512 x N=224
constexpr int N2       = 224;
constexpr int NB2      = HIDDEN / N2;         // 16
constexpr int BB2      = 14336;               // per-CTA fp16 B bytes (112 rows)
constexpr int BR2      = 7168;                // per-CTA raw fp8 bytes
constexpr int BTILE2R  = 14336;               // global raw tile (224 rows fp8)
constexpr int NT2      = (TOKENS / 512) * NB2;// 128
}

// global tile buffers
__device__ __half   g_x16[(size_t)(TOKENS / 512) * KT1 * (ATILE / 2)];
__device__ uint8_t  g_wgu8[(size_t)NB1 * KT1 * BTILE1R];
__device__ uint8_t  g_wd8 [(size_t)NB2 * KT2 * BTILE2R];
__device__ __half   g_h16[(size_t)(TOKENS / 512) * KT2 * (ATILE / 2)];

__host__ __device__ __forceinline__ uint32_t swz(uint32_t off) {
    return off ^ ((off >> 3) & 0x70);
}

// fp32x2 -> packed e4m3x2 (b16), low byte = first arg
__device__ __forceinline__ uint32_t pack_e4m3_4(float f0, float f1, float f2, float f3) {
    uint32_t w;
    asm("{\n\t.reg .b16 p0, p1;\n\t"
        "cvt.rn.satfinite.e4m3x2.f32 p0, %2, %1;\n\t"   // d = {hi=f1, lo=f0}
        "cvt.rn.satfinite.e4m3x2.f32 p1, %4, %3;\n\t"
        "mov.b32 %0, {p0, p1};\n\t}"
        : "=r"(w) : "f"(f0), "f"(f1), "f"(f2), "f"(f3));
    return w;
}
// packed 4x e4m3 -> two half2 (k order preserved)
__device__ __forceinline__ void fp8x4_to_h2x2(uint32_t w, uint32_t& o0, uint32_t& o1) {
    asm("{\n\t.reg .b16 lo, hi;\n\t"
        "mov.b32 {lo, hi}, %2;\n\t"
        "cvt.rn.f16x2.e4m3x2 %0, lo;\n\t"
        "cvt.rn.f16x2.e4m3x2 %1, hi;\n\t}"
        : "=r"(o0), "=r"(o1) : "r"(w));
}

// ---------------------------------------------------------------------------
// prep kernels
// ---------------------------------------------------------------------------
// w_gu -> raw fp8 tiles: tile (nb,kt) 16KB = [rank0 gate 128x64B][rank1 up 128x64B]
__global__ void __launch_bounds__(256) conv_wgu8(const float* __restrict__ src) {
    const int gid  = blockIdx.x * 256 + threadIdx.x;     // one 16B fp8 chunk
    const int tile = gid >> 10;                          // 1024 chunks / 16KB tile
    const int c    = gid & 1023;
    const int tr   = c >> 2;                             // 0..255
    const int ch   = c & 3;                              // 16-elem chunk in 64B row
    const int kt   = tile % KT1;
    const int bb   = tile / KT1;
    const int grow = (tr < 128) ? (bb * 128 + tr) : (INTER + bb * 128 + (tr - 128));

    const float* s = src + (size_t)grow * HIDDEN + kt * KC + ch * 16;
    uint32_t w[4];
    #pragma unroll
    for (int q = 0; q < 4; q++) {
        float4 f = reinterpret_cast<const float4*>(s)[q];
        w[q] = pack_e4m3_4(f.x, f.y, f.z, f.w);
    }
    uint8_t* dst = g_wgu8 + (size_t)tile * BTILE1R
                 + (tr >> 7) * BR1 + (tr & 127) * 64 + ch * 16;
    *reinterpret_cast<uint4*>(dst) = make_uint4(w[0], w[1], w[2], w[3]);
}

// w_d -> raw fp8 tiles: tile (nb,kt) 14336B = [rank0 112x64B][rank1 112x64B]
__global__ void __launch_bounds__(256) conv_wd8(const float* __restrict__ src) {
    const int gid  = blockIdx.x * 256 + threadIdx.x;
    const int tile = gid / 896;                          // 896 chunks / tile
    const int c    = gid % 896;
    const int tr   = c >> 2;                             // 0..223
    const int ch   = c & 3;
    const int kt   = tile % KT2;
    const int bb   = tile / KT2;
    const int grow = bb * N2 + tr;

    const float* s = src + (size_t)grow * INTER + kt * KC + ch * 16;
    uint32_t w[4];
    #pragma unroll
    for (int q = 0; q < 4; q++) {
        float4 f = reinterpret_cast<const float4*>(s)[q];
        w[q] = pack_e4m3_4(f.x, f.y, f.z, f.w);
    }
    const int half = tr / 112;
    const int wr   = tr - half * 112;
    uint8_t* dst = g_wd8 + (size_t)tile * BTILE2R + half * BR2 + wr * 64 + ch * 16;
    *reinterpret_cast<uint4*>(dst) = make_uint4(w[0], w[1], w[2], w[3]);
}

// x -> fp16 swizzled tiles (unchanged layout)
__global__ void __launch_bounds__(256) conv_x(const float* __restrict__ src) {
    const int gid  = blockIdx.x * 256 + threadIdx.x;
    const int tile = gid >> 12;
    const int c    = gid & 4095;
    const int sr   = c >> 3;
    const int ch   = c & 7;
    const int kt   = tile % KT1;
    const int mb   = tile / KT1;
    const int rank = sr >> 8;
    const int wr   = sr & 255;
    const int m    = mb * 512 + (wr >> 7) * 256 + rank * 128 + (wr & 127);

    const float* s = src + (size_t)m * HIDDEN + kt * KC + ch * 8;
    float4 a = *reinterpret_cast<const float4*>(s);
    float4 b = *reinterpret_cast<const float4*>(s + 4);
    __half2 p0 = __floats2half2_rn(a.x, a.y);
    __half2 p1 = __floats2half2_rn(a.z, a.w);
    __half2 p2 = __floats2half2_rn(b.x, b.y);
    __half2 p3 = __floats2half2_rn(b.z, b.w);
    uint4 v = make_uint4(*reinterpret_cast<uint32_t*>(&p0), *reinterpret_cast<uint32_t*>(&p1),
                         *reinterpret_cast<uint32_t*>(&p2), *reinterpret_cast<uint32_t*>(&p3));
    char* dst = reinterpret_cast<char*>(g_x16) + (size_t)tile * ATILE
              + rank * 32768 + swz((uint32_t)(wr * 128 + ch * 16));
    *reinterpret_cast<uint4*>(dst) = v;
}

// ---------------------------------------------------------------------------
// device helpers
// ---------------------------------------------------------------------------
#if USE_TCGEN05
__device__ __forceinline__ bool elect_one() {
    uint32_t p;
    asm volatile("{\n\t.reg .pred p;\n\telect.sync _|p, 0xFFFFFFFF;\n\t"
                 "selp.b32 %0, 1, 0, p;\n\t}" : "=r"(p));
    return p != 0;
}
__device__ __forceinline__ uint32_t ctarank() {
    uint32_t r;
    asm("mov.u32 %0, %%cluster_ctarank;" : "=r"(r));
    return r;
}
__device__ __forceinline__ void mbar_init(uint32_t addr, uint32_t count) {
    asm volatile("mbarrier.init.shared.b64 [%0], %1;" :: "r"(addr), "r"(count) : "memory");
}
__device__ __forceinline__ void mbar_wait(uint32_t addr, uint32_t parity) {
    asm volatile(
        "{\n\t.reg .pred P;\n\t"
        "WL_%=:\n\t"
        "mbarrier.try_wait.parity.acquire.cta.shared::cta.b64 P, [%0], %1, 0x989680;\n\t"
        "@P bra.uni WD_%=;\n\t"
        "bra.uni WL_%=;\n\t"
        "WD_%=:\n\t}"
        :: "r"(addr), "r"(parity) : "memory");
}
__device__ __forceinline__ void mbar_expect_tx(uint32_t addr, uint32_t bytes) {
    asm volatile("mbarrier.arrive.expect_tx.shared.b64 _, [%0], %1;"
                 :: "r"(addr), "r"(bytes) : "memory");
}
__device__ __forceinline__ void mbar_arrive(uint32_t addr) {
    asm volatile("mbarrier.arrive.shared.b64 _, [%0];" :: "r"(addr) : "memory");
}
__device__ __forceinline__ void mbar_arrive_remote(uint32_t local_addr, uint32_t target_rank) {
    asm volatile(
        "{\n\t.reg .b32 ra;\n\t"
        "mapa.shared::cluster.u32 ra, %0, %1;\n\t"
        "mbarrier.arrive.shared::cluster.b64 _, [ra];\n\t}"
        :: "r"(local_addr), "r"(target_rank) : "memory");
}
__device__ __forceinline__ void bulk_g2s(uint32_t dst, const void* src, uint32_t bytes,
                                         uint32_t mbar) {
    asm volatile(
        "cp.async.bulk.shared::cluster.global.mbarrier::complete_tx::bytes "
        "[%0], [%1], %2, [%3];"
        :: "r"(dst), "l"(src), "r"(bytes), "r"(mbar) : "memory");
}
__device__ __forceinline__ void tc_alloc_cg2(uint32_t dst_smem, uint32_t ncols) {
    asm volatile("tcgen05.alloc.cta_group::2.sync.aligned.shared::cta.b32 [%0], %1;"
                 :: "r"(dst_smem), "r"(ncols) : "memory");
}
__device__ __forceinline__ void tc_relinquish_cg2() {
    asm volatile("tcgen05.relinquish_alloc_permit.cta_group::2.sync.aligned;");
}
__device__ __forceinline__ void tc_dealloc_cg2(uint32_t tmem, uint32_t ncols) {
    asm volatile("tcgen05.dealloc.cta_group::2.sync.aligned.b32 %0, %1;"
                 :: "r"(tmem), "r"(ncols));
}
__device__ __forceinline__ void tc_commit_mc_cg2(uint32_t mbar, uint16_t mask) {
    asm volatile(
        "tcgen05.commit.cta_group::2.mbarrier::arrive::one.shared::cluster.multicast::cluster.b64 "
        "[%0], %1;"
        :: "r"(mbar), "h"(mask) : "memory");
}
__device__ __forceinline__ void tc_wait_ld() {
    asm volatile("tcgen05.wait::ld.sync.aligned;" ::: "memory");
}
__device__ __forceinline__ uint64_t sdesc(uint32_t addr) {
    return ((uint64_t)((addr >> 4) & 0x3FFF))
         | (1ULL  << 16) | (64ULL << 32) | (1ULL << 46) | (2ULL << 61);  // SW128 K-major
}
__device__ __forceinline__ void mma_f16_ss_cg2(uint32_t d_tmem, uint64_t ad, uint64_t bd,
                                               uint32_t idesc, uint32_t enable_d) {
    asm volatile(
        "{\n\t.reg .pred p;\n\t"
        "setp.ne.u32 p, %4, 0;\n\t"
        "tcgen05.mma.cta_group::2.kind::f16 [%0], %1, %2, %3, "
        "{%5,%5,%5,%5,%5,%5,%5,%5}, p;\n\t}"
        :: "r"(d_tmem), "l"(ad), "l"(bd), "r"(idesc), "r"(enable_d), "r"(0u)
        : "memory");
}
__device__ __forceinline__ void ldtm32(uint32_t* r, uint32_t ta) {
    asm volatile(
        "tcgen05.ld.sync.aligned.32x32b.x32.b32 "
        "{%0,%1,%2,%3,%4,%5,%6,%7,%8,%9,%10,%11,%12,%13,%14,%15,"
        "%16,%17,%18,%19,%20,%21,%22,%23,%24,%25,%26,%27,%28,%29,%30,%31}, [%32];"
        : "=r"(r[0]),  "=r"(r[1]),  "=r"(r[2]),  "=r"(r[3]),
          "=r"(r[4]),  "=r"(r[5]),  "=r"(r[6]),  "=r"(r[7]),
          "=r"(r[8]),  "=r"(r[9]),  "=r"(r[10]), "=r"(r[11]),
          "=r"(r[12]), "=r"(r[13]), "=r"(r[14]), "=r"(r[15]),
          "=r"(r[16]), "=r"(r[17]), "=r"(r[18]), "=r"(r[19]),
          "=r"(r[20]), "=r"(r[21]), "=r"(r[22]), "=r"(r[23]),
          "=r"(r[24]), "=r"(r[25]), "=r"(r[26]), "=r"(r[27]),
          "=r"(r[28]), "=r"(r[29]), "=r"(r[30]), "=r"(r[31])
        : "r"(ta));
}
#endif

// fallback read helpers
__device__ __forceinline__ float rd_a(const __half* buf, int KT, int m, int k) {
    const int mb = m >> 9, mm = m & 511;
    const int rank = (mm >> 7) & 1;
    const int wr = ((mm >> 8) << 7) | (mm & 127);
    const char* p = reinterpret_cast<const char*>(buf)
                  + ((size_t)mb * KT + (k >> 6)) * ATILE + rank * 32768
                  + swz((uint32_t)(wr * 128 + ((k & 63) >> 3) * 16)) + (k & 7) * 2;
    return __half2float(*reinterpret_cast<const __half*>(p));
}
__device__ __forceinline__ float rd_b8(const uint8_t* buf, int KT, int tile_b, int tr, int k,
                                       int tile_bytes, int half_rows) {
    const int half = tr / half_rows;
    const int wr   = tr - half * half_rows;
    const uint8_t* p = buf + ((size_t)tile_b * KT + (k >> 6)) * tile_bytes
                     + half * (tile_bytes / 2) + wr * 64 + (k & 63);
    __nv_fp8_e4m3 v;
    *reinterpret_cast<uint8_t*>(&v) = *p;
    return float(v);
}

// ---------------------------------------------------------------------------
// Persistent GEMM. grid (148,1,1), cluster (2,1,1), 384 threads.
// ---------------------------------------------------------------------------
template <int MODE>
__global__ void __launch_bounds__(THREADS, 1) __cluster_dims__(2, 1, 1)
mlp_gemm(const float* __restrict__ S, float* __restrict__ Out)
{
    constexpr int KT      = (MODE == 0) ? KT1 : KT2;
    constexpr int NMMA    = (MODE == 0) ? 256 : N2;
    constexpr int BBYTES  = (MODE == 0) ? BB1 : BB2;     // per-CTA fp16 B bytes
    constexpr int BRAW    = (MODE == 0) ? BR1 : BR2;     // per-CTA raw fp8 bytes
    constexpr int BTILER  = (MODE == 0) ? BTILE1R : BTILE2R;
    constexpr int STG_B   = A_BYTES + BBYTES + BRAW;     // per-CTA stage bytes
    constexpr int CCH     = (MODE == 0) ? 4 : 7;
    constexpr int DQU     = (MODE == 0) ? 8 : 7;         // dequant units/thread (64 thr)
    const int pair = blockIdx.x >> 1;
    const int ntp  = (MODE == 0) ? (NT1 / NPAIRS)
                                 : ((pair < NT2 - NPAIRS) ? 2 : 1);

    extern __shared__ char smem[];
    const int t    = threadIdx.x;
    const int wid  = t >> 5;
    const int lane = t & 31;

#if USE_TCGEN05
    constexpr uint32_t IDESC = (1u << 4) | ((uint32_t)(NMMA / 8) << 17) | (16u << 24);

    const uint32_t sbase     = (uint32_t)__cvta_generic_to_shared(smem);
    const uint32_t tptr_addr = sbase;
    const uint32_t bar_full  = sbase + 8;                 // raw + A resident (local)
    const uint32_t bar_empty = bar_full + NSTG * 8;
    const uint32_t bar_deq   = bar_empty + NSTG * 8;      // fp16 B ready (leader waits)
    const uint32_t bar_done  = bar_deq + NSTG * 8;
    const uint32_t bar_elo   = bar_done + 8;
    const uint32_t bar_ehi   = bar_done + 16;
    const uint32_t data_u    = (sbase + 256 + 1023) & ~1023u;
    const uint32_t rank      = ctarank();

    // tile index helper
    auto tile_mb_nb = [&](int tl, int& mb, int& nb) {
        if (MODE == 0) { nb = 2 * pair + (tl >> 3); mb = tl & 7; }
        else { const int idx = tl * NPAIRS + pair; mb = idx & 7; nb = idx >> 3; }
    };

    if (wid == 0) { tc_alloc_cg2(tptr_addr, 512); tc_relinquish_cg2(); }
    if (t == 0) {
        for (int s = 0; s < NSTG; s++) {
            mbar_init(bar_full  + s * 8, 1);   // expect_tx only
            mbar_init(bar_empty + s * 8, 1);   // leader commit (mc)
            mbar_init(bar_deq   + s * 8, 4);   // 2 warps x 2 CTAs (rank0's is used)
        }
        mbar_init(bar_done, 1);
        mbar_init(bar_elo, 8);
        mbar_init(bar_ehi, 8);
    }
    __syncthreads();
    asm volatile("barrier.cluster.arrive.aligned;" ::: "memory");
    asm volatile("barrier.cluster.wait.aligned;"   ::: "memory");

    uint32_t tmem;
    asm volatile("ld.shared.b32 %0, [%1];" : "=r"(tmem) : "r"(tptr_addr));

    const char*    Abuf = reinterpret_cast<const char*>((MODE == 0) ? g_x16 : g_h16);
    const uint8_t* Bbuf = (MODE == 0) ? g_wgu8 : g_wd8;

    if (t == 32) {
        // ---------------- TMA producer (both ranks) ----------------
        uint32_t g = 0;
        for (int tl = 0; tl < ntp; tl++) {
            int mb, nb; tile_mb_nb(tl, mb, nb);
            const char*    a_base = Abuf + (size_t)mb * KT * ATILE + rank * 32768;
            const uint8_t* b_base = Bbuf + (size_t)nb * KT * BTILER + rank * BRAW;
            for (int kt = 0; kt < KT; kt++, g++) {
                const uint32_t s = g & (NSTG - 1);
                if (g >= NSTG) mbar_wait(bar_empty + s * 8, ((g >> 2) - 1) & 1);
                const uint32_t As = data_u + s * STG_B;
                mbar_expect_tx(bar_full + s * 8, A_BYTES + BRAW);
                bulk_g2s(As, a_base + (size_t)kt * ATILE, A_BYTES, bar_full + s * 8);
                bulk_g2s(As + A_BYTES + BBYTES, b_base + (size_t)kt * BTILER, BRAW,
                         bar_full + s * 8);
            }
        }
    } else if (wid == 2 || wid == 3) {
        // ---------------- dequant warps (both ranks): fp8 raw -> fp16 SW128 ----
        const int wt = t - 64;                      // 0..63
        const uint32_t total = (uint32_t)ntp * KT;
        for (uint32_t g = 0; g < total; g++) {
            const uint32_t s = g & (NSTG - 1);
            mbar_wait(bar_full + s * 8, (g >> 2) & 1);
            const uint32_t As  = data_u + s * STG_B;
            const uint32_t dst = As + A_BYTES;           // fp16 B region
            const uint32_t raw = dst + BBYTES;           // fp8 raw region
            #pragma unroll
            for (int j = 0; j < DQU; j++) {
                const int u   = wt + 64 * j;             // unit: (row, 16-elem chunk)
                const int row = u >> 2;
                const int ch  = u & 3;
                uint4 r;
                asm volatile("ld.shared.v4.u32 {%0,%1,%2,%3}, [%4];"
                             : "=r"(r.x), "=r"(r.y), "=r"(r.z), "=r"(r.w)
                             : "r"(raw + row * 64 + ch * 16));
                uint32_t o0, o1, o2, o3, o4, o5, o6, o7;
                fp8x4_to_h2x2(r.x, o0, o1);
                fp8x4_to_h2x2(r.y, o2, o3);
                fp8x4_to_h2x2(r.z, o4, o5);
                fp8x4_to_h2x2(r.w, o6, o7);
                const uint32_t ob = (uint32_t)(row * 128 + ch * 32);
                asm volatile("st.shared.v4.b32 [%0], {%1,%2,%3,%4};"
                             :: "r"(dst + swz(ob)), "r"(o0), "r"(o1), "r"(o2), "r"(o3)
                             : "memory");
                asm volatile("st.shared.v4.b32 [%0], {%1,%2,%3,%4};"
                             :: "r"(dst + swz(ob + 16)), "r"(o4), "r"(o5), "r"(o6), "r"(o7)
                             : "memory");
            }
            asm volatile("fence.proxy.async.shared::cta;" ::: "memory");
            if (elect_one()) {
                if (rank == 0) mbar_arrive(bar_deq + s * 8);
                else           mbar_arrive_remote(bar_deq + s * 8, 0);
            }
        }
    } else if (wid == 0 && rank == 0) {
        // ---------------- MMA issuer (leader) ----------------
        if (elect_one()) {
            uint32_t g = 0;
            for (int tl = 0; tl < ntp; tl++) {
                for (int kt = 0; kt < KT; kt++, g++) {
                    const uint32_t s = g & (NSTG - 1);
                    mbar_wait(bar_deq + s * 8, (g >> 2) & 1);
                    const uint32_t As = data_u + s * STG_B;
                    const uint64_t ad0 = sdesc(As);
                    const uint64_t ad1 = sdesc(As + 16384);
                    const uint64_t bd  = sdesc(As + A_BYTES);
                    if (kt == 0) {
                        if (tl > 0) mbar_wait(bar_elo, (tl - 1) & 1);
                        #pragma unroll
                        for (int kk = 0; kk < 4; kk++)
                            mma_f16_ss_cg2(tmem, ad0 + 2 * kk, bd + 2 * kk, IDESC, kk > 0);
                        if (tl > 0) mbar_wait(bar_ehi, (tl - 1) & 1);
                        #pragma unroll
                        for (int kk = 0; kk < 4; kk++)
                            mma_f16_ss_cg2(tmem + NMMA, ad1 + 2 * kk, bd + 2 * kk, IDESC, kk > 0);
                    } else {
                        #pragma unroll
                        for (int kk = 0; kk < 4; kk++) {
                            mma_f16_ss_cg2(tmem,        ad0 + 2 * kk, bd + 2 * kk, IDESC, 1);
                            mma_f16_ss_cg2(tmem + NMMA, ad1 + 2 * kk, bd + 2 * kk, IDESC, 1);
                        }
                    }
                    tc_commit_mc_cg2(bar_empty + s * 8, (uint16_t)0x3);
                }
                tc_commit_mc_cg2(bar_done, (uint16_t)0x3);
            }
        }
    } else if (wid >= 4) {
        // ---------------- epilogue warps (both ranks) ----------------
        const int mh = (wid >> 2) - 1;
        const int sp = wid & 3;
        const uint32_t tbase = tmem + mh * NMMA;
        const uint32_t ebar  = (mh == 0) ? bar_elo : bar_ehi;
        for (int tl = 0; tl < ntp; tl++) {
            int mb, nb; tile_mb_nb(tl, mb, nb);
            mbar_wait(bar_done, tl & 1);
            asm volatile("tcgen05.fence::after_thread_sync;" ::: "memory");
            const int m = mb * 512 + mh * 256 + (int)rank * 128 + sp * 32 + lane;

            if (MODE == 0) {
                const int n0 = nb * 128;
                const int mm = m & 511;
                const int rank2 = (mm >> 7) & 1;
                const int wr2 = ((mm >> 8) << 7) | (mm & 127);
                char* hb = reinterpret_cast<char*>(g_h16)
                         + (size_t)(m >> 9) * KT2 * ATILE + rank2 * 32768;
                #pragma unroll
                for (int c = 0; c < 4; c++) {
                    const int cb = c * 32;
                    uint32_t gr[32], ur[32];
                    ldtm32(gr, tbase + cb);
                    ldtm32(ur, tbase + 128 + cb);
                    tc_wait_ld();
                    if (c == 3) {
                        if (elect_one()) mbar_arrive_remote(ebar, 0);
                    }
                    uint32_t oh[16];
                    #pragma unroll
                    for (int p = 0; p < 16; p++) {
                        const int i = 2 * p;
                        const int n = n0 + cb + i;
                        float g0 = __uint_as_float(gr[i])     * __ldg(S + n);
                        float g1 = __uint_as_float(gr[i + 1]) * __ldg(S + n + 1);
                        float u0 = __uint_as_float(ur[i])     * __ldg(S + INTER + n);
                        float u1 = __uint_as_float(ur[i + 1]) * __ldg(S + INTER + n + 1);
                        float h0 = __fdividef(g0, 1.0f + __expf(-g0)) * u0;
                        float h1 = __fdividef(g1, 1.0f + __expf(-g1)) * u1;
                        __half2 ph = __floats2half2_rn(h0, h1);
                        oh[p] = *reinterpret_cast<uint32_t*>(&ph);
                    }
                    #pragma unroll
                    for (int q = 0; q < 4; q++) {
                        const int col = n0 + cb + q * 8;
                        char* tb = hb + (size_t)(col >> 6) * ATILE;
                        const uint32_t off = swz((uint32_t)(wr2 * 128 + ((col & 63) >> 3) * 16));
                        *reinterpret_cast<uint4*>(tb + off) =
                            make_uint4(oh[4 * q], oh[4 * q + 1], oh[4 * q + 2], oh[4 * q + 3]);
                    }
                }
            } else {
                const int n0 = nb * N2;
                float* op = Out + (size_t)m * HIDDEN + n0;
                #pragma unroll
                for (int c = 0; c < CCH; c++) {
                    const int cb = c * 32;
                    uint32_t dr[32];
                    ldtm32(dr, tbase + cb);
                    tc_wait_ld();
                    if (c == CCH - 1) {
                        if (elect_one()) mbar_arrive_remote(ebar, 0);
                    }
                    #pragma unroll
                    for (int q = 0; q < 8; q++) {
                        float r[4];
                        #pragma unroll
                        for (int j = 0; j < 4; j++) {
                            const int i = q * 4 + j;
                            r[j] = __uint_as_float(dr[i]) * __ldg(S + n0 + cb + i);
                        }
                        reinterpret_cast<float4*>(op + cb)[q] =
                            make_float4(r[0], r[1], r[2], r[3]);
                    }
                }
            }
        }
    }

    __syncthreads();
    if (wid == 0) tc_dealloc_cg2(tmem, 512);
    asm volatile("barrier.cluster.arrive.aligned;" ::: "memory");
    asm volatile("barrier.cluster.wait.aligned;"   ::: "memory");

#else
    // non-103a compile pass only (never selected at runtime on GB300)
    (void)smem; (void)lane;
    const int rankf = blockIdx.x & 1;
    constexpr int KTOT = (MODE == 0) ? HIDDEN : INTER;
    constexpr int NCOL = (MODE == 0) ? 128 : N2;
    for (int tl = 0; tl < ntp; tl++) {
        int mb, nb;
        if (MODE == 0) { nb = 2 * pair + (tl >> 3); mb = tl & 7; }
        else { const int idx = tl * NPAIRS + pair; mb = idx & 7; nb = idx >> 3; }
        const int n0 = nb * NCOL;
        for (int o = t; o < 256 * NCOL; o += THREADS) {
            const int rr = o / NCOL, cc = o % NCOL;
            const int m = mb * 512 + (rr >> 7) * 256 + rankf * 128 + (rr & 127);
            if (MODE == 0) {
                float accg = 0.f, accu = 0.f;
                for (int k = 0; k < KTOT; k++) {
                    float a = rd_a(g_x16, KT1, m, k);
                    accg += a * rd_b8(g_wgu8, KT1, nb, cc, k, BTILE1R, 128);
                    accu += a * rd_b8(g_wgu8, KT1, nb, 128 + cc, k, BTILE1R, 128);
                }
                float g = accg * S[n0 + cc], u = accu * S[INTER + n0 + cc];
                float hv = g / (1.0f + __expf(-g)) * u;
                const int col = n0 + cc;
                const int mm = m & 511;
                const int rank2 = (mm >> 7) & 1;
                const int wr2 = ((mm >> 8) << 7) | (mm & 127);
                char* p = reinterpret_cast<char*>(g_h16)
                        + ((size_t)(m >> 9) * KT2 + (col >> 6)) * ATILE + rank2 * 32768
                        + swz((uint32_t)(wr2 * 128 + ((col & 63) >> 3) * 16)) + (col & 7) * 2;
                *reinterpret_cast<__half*>(p) = __float2half_rn(hv);
            } else {
                float acc = 0.f;
                for (int k = 0; k < KTOT; k++)
                    acc += rd_a(g_h16, KT2, m, k) * rd_b8(g_wd8, KT2, nb, cc, k, BTILE2R, 112);
                Out[(size_t)m * HIDDEN + n0 + cc] = acc * S[n0 + cc];
            }
        }
    }
#endif
}

// ---------------------------------------------------------------------------
// launch
// ---------------------------------------------------------------------------
extern "C" void kernel_launch(void* const* d_in, const int* in_sizes, int n_in,
                              void* d_out, int out_size)
{
    const float* x = nullptr; const float* w_gu = nullptr; const float* s_gu = nullptr;
    const float* w_d = nullptr; const float* s_d = nullptr;
    for (int i = 0; i < n_in; i++) {
        long long sz = in_sizes[i];
        const float* p = (const float*)d_in[i];
        if      (sz == (long long)TOKENS * HIDDEN)    x    = p;
        else if (sz == (long long)2 * INTER * HIDDEN) w_gu = p;
        else if (sz == (long long)2 * INTER)          s_gu = p;
        else if (sz == (long long)HIDDEN * INTER)     w_d  = p;
        else if (sz == (long long)HIDDEN)             s_d  = p;
    }
    float* out = (float*)d_out;

    constexpr int SMEM0 = 1024 + NSTG * (A_BYTES + BB1 + BR1);  // 230,400
    constexpr int SMEM1 = 1024 + NSTG * (A_BYTES + BB2 + BR2);  // 218,112
    cudaFuncSetAttribute(mlp_gemm<0>, cudaFuncAttributeMaxDynamicSharedMemorySize, SMEM0);
    cudaFuncSetAttribute(mlp_gemm<1>, cudaFuncAttributeMaxDynamicSharedMemorySize, SMEM1);

    // prep: weights -> raw fp8 tiles (exact), x -> fp16 tiles
    conv_wgu8<<<(NB1 * KT1 * 1024) / 256, 256>>>(w_gu);
    conv_wd8 <<<(NB2 * KT2 * 896) / 256, 256>>>(w_d);
    conv_x   <<<((TOKENS / 512) * KT1 * 4096) / 256, 256>>>(x);

    // GEMM1: gate_up + SiLU*Mul -> g_h16 tiles
    mlp_gemm<0><<<dim3(2 * NPAIRS, 1), THREADS, SMEM0>>>(s_gu, nullptr);

    // GEMM2: down -> out
    mlp_gemm<1><<<dim3(2 * NPAIRS, 1), THREADS, SMEM1>>>(s_d, out);
}

// round 12
// speedup vs baseline: 9.9659x; 1.0255x over previous
#include <cuda_runtime.h>
#include <cuda_fp16.h>
#include <cuda_fp8.h>
#include <cstdint>

// ---------------------------------------------------------------------------
// Qwen2 FP8 MLP, fp16 tcgen05 cg2 persistent + fp8 weight delivery (R11)
//   + R12: conv_wd8 fused into GEMM1 as background warps (w12-13); merged
//     wgu8/x prep kernel. GEMM1 is at the cg2 fp16 dispatch floor; GEMM2 at
//     its crit-path floor; this round removes serialized prep time.
// ---------------------------------------------------------------------------

#if defined(__CUDA_ARCH_FEAT_SM103_ALL) || defined(__CUDA_ARCH_FEAT_SM100_ALL) || defined(__CUDA_ARCH_SPECIFIC__)
#define USE_TCGEN05 1
#else
#define USE_TCGEN05 0
#endif

namespace {
constexpr int HIDDEN = 3584;
constexpr int INTER  = 18944;
constexpr int TOKENS = 4096;

constexpr int KC      = 64;
constexpr int NSTG    = 4;
constexpr int THREADS = 448;      // w0 MMA, w1 prod, w2-3 dequant, w4-11 epi, w12-13 wd8conv
constexpr int NPAIRS  = 74;

constexpr int A_BYTES = 32768;
constexpr int ATILE   = 65536;

constexpr int KT1 = HIDDEN / KC;              // 56
constexpr int KT2 = INTER  / KC;              // 296

constexpr int NB1      = INTER / 128;         // 148
constexpr int BB1      = 16384;
constexpr int BR1      = 8192;
constexpr int BTILE1R  = 16384;
constexpr int NT1      = (TOKENS / 512) * NB1;

constexpr int N2       = 224;
constexpr int NB2      = HIDDEN / N2;         // 16
constexpr int BB2      = 14336;
constexpr int BR2      = 7168;
constexpr int BTILE2R  = 14336;
constexpr int NT2      = (TOKENS / 512) * NB2;

constexpr int WGU_CHUNKS = NB1 * KT1 * 1024;        // 16B chunks in g_wgu8
constexpr int X_CHUNKS   = (TOKENS / 512) * KT1 * 4096;
constexpr int WD_CHUNKS  = NB2 * KT2 * 896;         // 4,243,456
}

__device__ __half   g_x16[(size_t)(TOKENS / 512) * KT1 * (ATILE / 2)];
__device__ uint8_t  g_wgu8[(size_t)NB1 * KT1 * BTILE1R];
__device__ uint8_t  g_wd8 [(size_t)NB2 * KT2 * BTILE2R];
__device__ __half   g_h16[(size_t)(TOKENS / 512) * KT2 * (ATILE / 2)];

__host__ __device__ __forceinline__ uint32_t swz(uint32_t off) {
    return off ^ ((off >> 3) & 0x70);
}

__device__ __forceinline__ uint32_t pack_e4m3_4(float f0, float f1, float f2, float f3) {
    uint32_t w;
    asm("{\n\t.reg .b16 p0, p1;\n\t"
        "cvt.rn.satfinite.e4m3x2.f32 p0, %2, %1;\n\t"
        "cvt.rn.satfinite.e4m3x2.f32 p1, %4, %3;\n\t"
        "mov.b32 %0, {p0, p1};\n\t}"
        : "=r"(w) : "f"(f0), "f"(f1), "f"(f2), "f"(f3));
    return w;
}
__device__ __forceinline__ void fp8x4_to_h2x2(uint32_t w, uint32_t& o0, uint32_t& o1) {
    asm("{\n\t.reg .b16 lo, hi;\n\t"
        "mov.b32 {lo, hi}, %2;\n\t"
        "cvt.rn.f16x2.e4m3x2 %0, lo;\n\t"
        "cvt.rn.f16x2.e4m3x2 %1, hi;\n\t}"
        : "=r"(o0), "=r"(o1) : "r"(w));
}

// wd8 conversion for one 16-elem chunk index (shared by prep fallback + fused warps)
__device__ __forceinline__ void conv_wd8_chunk(const float* __restrict__ src, int gid) {
    const int tile = gid / 896;
    const int c    = gid % 896;
    const int tr   = c >> 2;
    const int ch   = c & 3;
    const int kt   = tile % KT2;
    const int bb   = tile / KT2;
    const int grow = bb * N2 + tr;

    const float* s = src + (size_t)grow * INTER + kt * KC + ch * 16;
    uint32_t w[4];
    #pragma unroll
    for (int q = 0; q < 4; q++) {
        float4 f = reinterpret_cast<const float4*>(s)[q];
        w[q] = pack_e4m3_4(f.x, f.y, f.z, f.w);
    }
    const int half = tr / 112;
    const int wr   = tr - half * 112;
    uint8_t* dst = g_wd8 + (size_t)tile * BTILE2R + half * BR2 + wr * 64 + ch * 16;
    *reinterpret_cast<uint4*>(dst) = make_uint4(w[0], w[1], w[2], w[3]);
}

// ---------------------------------------------------------------------------
// merged prep: blocks [0, WGU_CHUNKS/256) convert w_gu; rest convert x
// ---------------------------------------------------------------------------
__global__ void __launch_bounds__(256) conv_prep(const float* __restrict__ w_gu,
                                                 const float* __restrict__ x) {
    int gid = blockIdx.x * 256 + threadIdx.x;
    if (gid < WGU_CHUNKS) {
        const int tile = gid >> 10;
        const int c    = gid & 1023;
        const int tr   = c >> 2;
        const int ch   = c & 3;
        const int kt   = tile % KT1;
        const int bb   = tile / KT1;
        const int grow = (tr < 128) ? (bb * 128 + tr) : (INTER + bb * 128 + (tr - 128));
        const float* s = w_gu + (size_t)grow * HIDDEN + kt * KC + ch * 16;
        uint32_t w[4];
        #pragma unroll
        for (int q = 0; q < 4; q++) {
            float4 f = reinterpret_cast<const float4*>(s)[q];
            w[q] = pack_e4m3_4(f.x, f.y, f.z, f.w);
        }
        uint8_t* dst = g_wgu8 + (size_t)tile * BTILE1R
                     + (tr >> 7) * BR1 + (tr & 127) * 64 + ch * 16;
        *reinterpret_cast<uint4*>(dst) = make_uint4(w[0], w[1], w[2], w[3]);
    } else {
        gid -= WGU_CHUNKS;
        const int tile = gid >> 12;
        const int c    = gid & 4095;
        const int sr   = c >> 3;
        const int ch   = c & 7;
        const int kt   = tile % KT1;
        const int mb   = tile / KT1;
        const int rank = sr >> 8;
        const int wr   = sr & 255;
        const int m    = mb * 512 + (wr >> 7) * 256 + rank * 128 + (wr & 127);
        const float* s = x + (size_t)m * HIDDEN + kt * KC + ch * 8;
        float4 a = *reinterpret_cast<const float4*>(s);
        float4 b = *reinterpret_cast<const float4*>(s + 4);
        __half2 p0 = __floats2half2_rn(a.x, a.y);
        __half2 p1 = __floats2half2_rn(a.z, a.w);
        __half2 p2 = __floats2half2_rn(b.x, b.y);
        __half2 p3 = __floats2half2_rn(b.z, b.w);
        uint4 v = make_uint4(*reinterpret_cast<uint32_t*>(&p0), *reinterpret_cast<uint32_t*>(&p1),
                             *reinterpret_cast<uint32_t*>(&p2), *reinterpret_cast<uint32_t*>(&p3));
        char* dst = reinterpret_cast<char*>(g_x16) + (size_t)tile * ATILE
                  + rank * 32768 + swz((uint32_t)(wr * 128 + ch * 16));
        *reinterpret_cast<uint4*>(dst) = v;
    }
}

// ---------------------------------------------------------------------------
// device helpers
// ---------------------------------------------------------------------------
#if USE_TCGEN05
__device__ __forceinline__ bool elect_one() {
    uint32_t p;
    asm volatile("{\n\t.reg .pred p;\n\telect.sync _|p, 0xFFFFFFFF;\n\t"
                 "selp.b32 %0, 1, 0, p;\n\t}" : "=r"(p));
    return p != 0;
}
__device__ __forceinline__ uint32_t ctarank() {
    uint32_t r;
    asm("mov.u32 %0, %%cluster_ctarank;" : "=r"(r));
    return r;
}
__device__ __forceinline__ void mbar_init(uint32_t addr, uint32_t count) {
    asm volatile("mbarrier.init.shared.b64 [%0], %1;" :: "r"(addr), "r"(count) : "memory");
}
__device__ __forceinline__ void mbar_wait(uint32_t addr, uint32_t parity) {
    asm volatile(
        "{\n\t.reg .pred P;\n\t"
        "WL_%=:\n\t"
        "mbarrier.try_wait.parity.acquire.cta.shared::cta.b64 P, [%0], %1, 0x989680;\n\t"
        "@P bra.uni WD_%=;\n\t"
        "bra.uni WL_%=;\n\t"
        "WD_%=:\n\t}"
        :: "r"(addr), "r"(parity) : "memory");
}
__device__ __forceinline__ void mbar_expect_tx(uint32_t addr, uint32_t bytes) {
    asm volatile("mbarrier.arrive.expect_tx.shared.b64 _, [%0], %1;"
                 :: "r"(addr), "r"(bytes) : "memory");
}
__device__ __forceinline__ void mbar_arrive(uint32_t addr) {
    asm volatile("mbarrier.arrive.shared.b64 _, [%0];" :: "r"(addr) : "memory");
}
__device__ __forceinline__ void mbar_arrive_remote(uint32_t local_addr, uint32_t target_rank) {
    asm volatile(
        "{\n\t.reg .b32 ra;\n\t"
        "mapa.shared::cluster.u32 ra, %0, %1;\n\t"
        "mbarrier.arrive.shared::cluster.b64 _, [ra];\n\t}"
        :: "r"(local_addr), "r"(target_rank) : "memory");
}
__device__ __forceinline__ void bulk_g2s(uint32_t dst, const void* src, uint32_t bytes,
                                         uint32_t mbar) {
    asm volatile(
        "cp.async.bulk.shared::cluster.global.mbarrier::complete_tx::bytes "
        "[%0], [%1], %2, [%3];"
        :: "r"(dst), "l"(src), "r"(bytes), "r"(mbar) : "memory");
}
__device__ __forceinline__ void tc_alloc_cg2(uint32_t dst_smem, uint32_t ncols) {
    asm volatile("tcgen05.alloc.cta_group::2.sync.aligned.shared::cta.b32 [%0], %1;"
                 :: "r"(dst_smem), "r"(ncols) : "memory");
}
__device__ __forceinline__ void tc_relinquish_cg2() {
    asm volatile("tcgen05.relinquish_alloc_permit.cta_group::2.sync.aligned;");
}
__device__ __forceinline__ void tc_dealloc_cg2(uint32_t tmem, uint32_t ncols) {
    asm volatile("tcgen05.dealloc.cta_group::2.sync.aligned.b32 %0, %1;"
                 :: "r"(tmem), "r"(ncols));
}
__device__ __forceinline__ void tc_commit_mc_cg2(uint32_t mbar, uint16_t mask) {
    asm volatile(
        "tcgen05.commit.cta_group::2.mbarrier::arrive::one.shared::cluster.multicast::cluster.b64 "
        "[%0], %1;"
        :: "r"(mbar), "h"(mask) : "memory");
}
__device__ __forceinline__ void tc_wait_ld() {
    asm volatile("tcgen05.wait::ld.sync.aligned;" ::: "memory");
}
__device__ __forceinline__ uint64_t sdesc(uint32_t addr) {
    return ((uint64_t)((addr >> 4) & 0x3FFF))
         | (1ULL  << 16) | (64ULL << 32) | (1ULL << 46) | (2ULL << 61);
}
__device__ __forceinline__ void mma_f16_ss_cg2(uint32_t d_tmem, uint64_t ad, uint64_t bd,
                                               uint32_t idesc, uint32_t enable_d) {
    asm volatile(
        "{\n\t.reg .pred p;\n\t"
        "setp.ne.u32 p, %4, 0;\n\t"
        "tcgen05.mma.cta_group::2.kind::f16 [%0], %1, %2, %3, "
        "{%5,%5,%5,%5,%5,%5,%5,%5}, p;\n\t}"
        :: "r"(d_tmem), "l"(ad), "l"(bd), "r"(idesc), "r"(enable_d), "r"(0u)
        : "memory");
}
__device__ __forceinline__ void ldtm32(uint32_t* r, uint32_t ta) {
    asm volatile(
        "tcgen05.ld.sync.aligned.32x32b.x32.b32 "
        "{%0,%1,%2,%3,%4,%5,%6,%7,%8,%9,%10,%11,%12,%13,%14,%15,"
        "%16,%17,%18,%19,%20,%21,%22,%23,%24,%25,%26,%27,%28,%29,%30,%31}, [%32];"
        : "=r"(r[0]),  "=r"(r[1]),  "=r"(r[2]),  "=r"(r[3]),
          "=r"(r[4]),  "=r"(r[5]),  "=r"(r[6]),  "=r"(r[7]),
          "=r"(r[8]),  "=r"(r[9]),  "=r"(r[10]), "=r"(r[11]),
          "=r"(r[12]), "=r"(r[13]), "=r"(r[14]), "=r"(r[15]),
          "=r"(r[16]), "=r"(r[17]), "=r"(r[18]), "=r"(r[19]),
          "=r"(r[20]), "=r"(r[21]), "=r"(r[22]), "=r"(r[23]),
          "=r"(r[24]), "=r"(r[25]), "=r"(r[26]), "=r"(r[27]),
          "=r"(r[28]), "=r"(r[29]), "=r"(r[30]), "=r"(r[31])
        : "r"(ta));
}
#endif

// fallback read helpers
__device__ __forceinline__ float rd_a(const __half* buf, int KT, int m, int k) {
    const int mb = m >> 9, mm = m & 511;
    const int rank = (mm >> 7) & 1;
    const int wr = ((mm >> 8) << 7) | (mm & 127);
    const char* p = reinterpret_cast<const char*>(buf)
                  + ((size_t)mb * KT + (k >> 6)) * ATILE + rank * 32768
                  + swz((uint32_t)(wr * 128 + ((k & 63) >> 3) * 16)) + (k & 7) * 2;
    return __half2float(*reinterpret_cast<const __half*>(p));
}
__device__ __forceinline__ float rd_b8(const uint8_t* buf, int KT, int tile_b, int tr, int k,
                                       int tile_bytes, int half_rows) {
    const int half = tr / half_rows;
    const int wr   = tr - half * half_rows;
    const uint8_t* p = buf + ((size_t)tile_b * KT + (k >> 6)) * tile_bytes
                     + half * (tile_bytes / 2) + wr * 64 + (k & 63);
    __nv_fp8_e4m3 v;
    *reinterpret_cast<uint8_t*>(&v) = *p;
    return float(v);
}

// ---------------------------------------------------------------------------
// Persistent GEMM. grid (148,1,1), cluster (2,1,1), 448 threads.
// MODE 0 additionally streams the w_d fp32->fp8 conversion on warps 12-13.
// ---------------------------------------------------------------------------
template <int MODE>
__global__ void __launch_bounds__(THREADS, 1) __cluster_dims__(2, 1, 1)
mlp_gemm(const float* __restrict__ S, float* __restrict__ Out,
         const float* __restrict__ Wd32)
{
    constexpr int KT      = (MODE == 0) ? KT1 : KT2;
    constexpr int NMMA    = (MODE == 0) ? 256 : N2;
    constexpr int BBYTES  = (MODE == 0) ? BB1 : BB2;
    constexpr int BRAW    = (MODE == 0) ? BR1 : BR2;
    constexpr int BTILER  = (MODE == 0) ? BTILE1R : BTILE2R;
    constexpr int STG_B   = A_BYTES + BBYTES + BRAW;
    constexpr int CCH     = (MODE == 0) ? 4 : 7;
    constexpr int DQU     = (MODE == 0) ? 8 : 7;
    const int pair = blockIdx.x >> 1;
    const int ntp  = (MODE == 0) ? (NT1 / NPAIRS)
                                 : ((pair < NT2 - NPAIRS) ? 2 : 1);

    extern __shared__ char smem[];
    const int t    = threadIdx.x;
    const int wid  = t >> 5;
    const int lane = t & 31;

#if USE_TCGEN05
    constexpr uint32_t IDESC = (1u << 4) | ((uint32_t)(NMMA / 8) << 17) | (16u << 24);

    const uint32_t sbase     = (uint32_t)__cvta_generic_to_shared(smem);
    const uint32_t tptr_addr = sbase;
    const uint32_t bar_full  = sbase + 8;
    const uint32_t bar_empty = bar_full + NSTG * 8;
    const uint32_t bar_deq   = bar_empty + NSTG * 8;
    const uint32_t bar_done  = bar_deq + NSTG * 8;
    const uint32_t bar_elo   = bar_done + 8;
    const uint32_t bar_ehi   = bar_done + 16;
    const uint32_t data_u    = (sbase + 256 + 1023) & ~1023u;
    const uint32_t rank      = ctarank();

    auto tile_mb_nb = [&](int tl, int& mb, int& nb) {
        if (MODE == 0) { nb = 2 * pair + (tl >> 3); mb = tl & 7; }
        else { const int idx = tl * NPAIRS + pair; mb = idx & 7; nb = idx >> 3; }
    };

    if (wid == 0) { tc_alloc_cg2(tptr_addr, 512); tc_relinquish_cg2(); }
    if (t == 0) {
        for (int s = 0; s < NSTG; s++) {
            mbar_init(bar_full  + s * 8, 1);
            mbar_init(bar_empty + s * 8, 1);
            mbar_init(bar_deq   + s * 8, 4);
        }
        mbar_init(bar_done, 1);
        mbar_init(bar_elo, 8);
        mbar_init(bar_ehi, 8);
    }
    __syncthreads();
    asm volatile("barrier.cluster.arrive.aligned;" ::: "memory");
    asm volatile("barrier.cluster.wait.aligned;"   ::: "memory");

    uint32_t tmem;
    asm volatile("ld.shared.b32 %0, [%1];" : "=r"(tmem) : "r"(tptr_addr));

    const char*    Abuf = reinterpret_cast<const char*>((MODE == 0) ? g_x16 : g_h16);
    const uint8_t* Bbuf = (MODE == 0) ? g_wgu8 : g_wd8;

    if (t == 32) {
        // ---------------- TMA producer ----------------
        uint32_t g = 0;
        for (int tl = 0; tl < ntp; tl++) {
            int mb, nb; tile_mb_nb(tl, mb, nb);
            const char*    a_base = Abuf + (size_t)mb * KT * ATILE + rank * 32768;
            const uint8_t* b_base = Bbuf + (size_t)nb * KT * BTILER + rank * BRAW;
            for (int kt = 0; kt < KT; kt++, g++) {
                const uint32_t s = g & (NSTG - 1);
                if (g >= NSTG) mbar_wait(bar_empty + s * 8, ((g >> 2) - 1) & 1);
                const uint32_t As = data_u + s * STG_B;
                mbar_expect_tx(bar_full + s * 8, A_BYTES + BRAW);
                bulk_g2s(As, a_base + (size_t)kt * ATILE, A_BYTES, bar_full + s * 8);
                bulk_g2s(As + A_BYTES + BBYTES, b_base + (size_t)kt * BTILER, BRAW,
                         bar_full + s * 8);
            }
        }
    } else if (wid == 2 || wid == 3) {
        // ---------------- dequant warps ----------------
        const int wt = t - 64;
        const uint32_t total = (uint32_t)ntp * KT;
        for (uint32_t g = 0; g < total; g++) {
            const uint32_t s = g & (NSTG - 1);
            mbar_wait(bar_full + s * 8, (g >> 2) & 1);
            const uint32_t As  = data_u + s * STG_B;
            const uint32_t dst = As + A_BYTES;
            const uint32_t raw = dst + BBYTES;
            #pragma unroll
            for (int j = 0; j < DQU; j++) {
                const int u   = wt + 64 * j;
                const int row = u >> 2;
                const int ch  = u & 3;
                uint4 r;
                asm volatile("ld.shared.v4.u32 {%0,%1,%2,%3}, [%4];"
                             : "=r"(r.x), "=r"(r.y), "=r"(r.z), "=r"(r.w)
                             : "r"(raw + row * 64 + ch * 16));
                uint32_t o0, o1, o2, o3, o4, o5, o6, o7;
                fp8x4_to_h2x2(r.x, o0, o1);
                fp8x4_to_h2x2(r.y, o2, o3);
                fp8x4_to_h2x2(r.z, o4, o5);
                fp8x4_to_h2x2(r.w, o6, o7);
                const uint32_t ob = (uint32_t)(row * 128 + ch * 32);
                asm volatile("st.shared.v4.b32 [%0], {%1,%2,%3,%4};"
                             :: "r"(dst + swz(ob)), "r"(o0), "r"(o1), "r"(o2), "r"(o3)
                             : "memory");
                asm volatile("st.shared.v4.b32 [%0], {%1,%2,%3,%4};"
                             :: "r"(dst + swz(ob + 16)), "r"(o4), "r"(o5), "r"(o6), "r"(o7)
                             : "memory");
            }
            asm volatile("fence.proxy.async.shared::cta;" ::: "memory");
            if (elect_one()) {
                if (rank == 0) mbar_arrive(bar_deq + s * 8);
                else           mbar_arrive_remote(bar_deq + s * 8, 0);
            }
        }
    } else if (wid == 0 && rank == 0) {
        // ---------------- MMA issuer (leader) ----------------
        if (elect_one()) {
            uint32_t g = 0;
            for (int tl = 0; tl < ntp; tl++) {
                for (int kt = 0; kt < KT; kt++, g++) {
                    const uint32_t s = g & (NSTG - 1);
                    mbar_wait(bar_deq + s * 8, (g >> 2) & 1);
                    const uint32_t As = data_u + s * STG_B;
                    const uint64_t ad0 = sdesc(As);
                    const uint64_t ad1 = sdesc(As + 16384);
                    const uint64_t bd  = sdesc(As + A_BYTES);
                    if (kt == 0) {
                        if (tl > 0) mbar_wait(bar_elo, (tl - 1) & 1);
                        #pragma unroll
                        for (int kk = 0; kk < 4; kk++)
                            mma_f16_ss_cg2(tmem, ad0 + 2 * kk, bd + 2 * kk, IDESC, kk > 0);
                        if (tl > 0) mbar_wait(bar_ehi, (tl - 1) & 1);
                        #pragma unroll
                        for (int kk = 0; kk < 4; kk++)
                            mma_f16_ss_cg2(tmem + NMMA, ad1 + 2 * kk, bd + 2 * kk, IDESC, kk > 0);
                    } else {
                        #pragma unroll
                        for (int kk = 0; kk < 4; kk++) {
                            mma_f16_ss_cg2(tmem,        ad0 + 2 * kk, bd + 2 * kk, IDESC, 1);
                            mma_f16_ss_cg2(tmem + NMMA, ad1 + 2 * kk, bd + 2 * kk, IDESC, 1);
                        }
                    }
                    tc_commit_mc_cg2(bar_empty + s * 8, (uint16_t)0x3);
                }
                tc_commit_mc_cg2(bar_done, (uint16_t)0x3);
            }
        }
    } else if (wid >= 4 && wid < 12) {
        // ---------------- epilogue warps ----------------
        const int mh = (wid >> 2) - 1;
        const int sp = wid & 3;
        const uint32_t tbase = tmem + mh * NMMA;
        const uint32_t ebar  = (mh == 0) ? bar_elo : bar_ehi;
        for (int tl = 0; tl < ntp; tl++) {
            int mb, nb; tile_mb_nb(tl, mb, nb);
            mbar_wait(bar_done, tl & 1);
            asm volatile("tcgen05.fence::after_thread_sync;" ::: "memory");
            const int m = mb * 512 + mh * 256 + (int)rank * 128 + sp * 32 + lane;

            if (MODE == 0) {
                const int n0 = nb * 128;
                const int mm = m & 511;
                const int rank2 = (mm >> 7) & 1;
                const int wr2 = ((mm >> 8) << 7) | (mm & 127);
                char* hb = reinterpret_cast<char*>(g_h16)
                         + (size_t)(m >> 9) * KT2 * ATILE + rank2 * 32768;
                #pragma unroll
                for (int c = 0; c < 4; c++) {
                    const int cb = c * 32;
                    uint32_t gr[32], ur[32];
                    ldtm32(gr, tbase + cb);
                    ldtm32(ur, tbase + 128 + cb);
                    tc_wait_ld();
                    if (c == 3) {
                        if (elect_one()) mbar_arrive_remote(ebar, 0);
                    }
                    uint32_t oh[16];
                    #pragma unroll
                    for (int p = 0; p < 16; p++) {
                        const int i = 2 * p;
                        const int n = n0 + cb + i;
                        float g0 = __uint_as_float(gr[i])     * __ldg(S + n);
                        float g1 = __uint_as_float(gr[i + 1]) * __ldg(S + n + 1);
                        float u0 = __uint_as_float(ur[i])     * __ldg(S + INTER + n);
                        float u1 = __uint_as_float(ur[i + 1]) * __ldg(S + INTER + n + 1);
                        float h0 = __fdividef(g0, 1.0f + __expf(-g0)) * u0;
                        float h1 = __fdividef(g1, 1.0f + __expf(-g1)) * u1;
                        __half2 ph = __floats2half2_rn(h0, h1);
                        oh[p] = *reinterpret_cast<uint32_t*>(&ph);
                    }
                    #pragma unroll
                    for (int q = 0; q < 4; q++) {
                        const int col = n0 + cb + q * 8;
                        char* tb = hb + (size_t)(col >> 6) * ATILE;
                        const uint32_t off = swz((uint32_t)(wr2 * 128 + ((col & 63) >> 3) * 16));
                        *reinterpret_cast<uint4*>(tb + off) =
                            make_uint4(oh[4 * q], oh[4 * q + 1], oh[4 * q + 2], oh[4 * q + 3]);
                    }
                }
            } else {
                const int n0 = nb * N2;
                float* op = Out + (size_t)m * HIDDEN + n0;
                #pragma unroll
                for (int c = 0; c < CCH; c++) {
                    const int cb = c * 32;
                    uint32_t dr[32];
                    ldtm32(dr, tbase + cb);
                    tc_wait_ld();
                    if (c == CCH - 1) {
                        if (elect_one()) mbar_arrive_remote(ebar, 0);
                    }
                    #pragma unroll
                    for (int q = 0; q < 8; q++) {
                        float r[4];
                        #pragma unroll
                        for (int j = 0; j < 4; j++) {
                            const int i = q * 4 + j;
                            r[j] = __uint_as_float(dr[i]) * __ldg(S + n0 + cb + i);
                        }
                        reinterpret_cast<float4*>(op + cb)[q] =
                            make_float4(r[0], r[1], r[2], r[3]);
                    }
                }
            }
        }
    } else if (MODE == 0 && wid >= 12) {
        // ---------------- background w_d fp32 -> fp8 conversion ----------------
        // 148 CTAs x 64 threads, grid-strided over WD_CHUNKS
        const int  wt     = t - 384;                         // 0..63
        const int  stride = 148 * 64;
        for (int g = (int)blockIdx.x * 64 + wt; g < WD_CHUNKS; g += stride)
            conv_wd8_chunk(Wd32, g);
    }

    __syncthreads();
    if (wid == 0) tc_dealloc_cg2(tmem, 512);
    asm volatile("barrier.cluster.arrive.aligned;" ::: "memory");
    asm volatile("barrier.cluster.wait.aligned;"   ::: "memory");

#else
    // non-103a compile pass only (never selected at runtime on GB300)
    (void)smem; (void)lane;
    const int rankf = blockIdx.x & 1;
    constexpr int KTOT = (MODE == 0) ? HIDDEN : INTER;
    constexpr int NCOL = (MODE == 0) ? 128 : N2;
    if (MODE == 0) {
        // background w_d conversion (fallback does it serially up front)
        for (int g = (int)blockIdx.x * THREADS + t; g < WD_CHUNKS; g += 148 * THREADS)
            conv_wd8_chunk(Wd32, g);
    }
    for (int tl = 0; tl < ntp; tl++) {
        int mb, nb;
        if (MODE == 0) { nb = 2 * pair + (tl >> 3); mb = tl & 7; }
        else { const int idx = tl * NPAIRS + pair; mb = idx & 7; nb = idx >> 3; }
        const int n0 = nb * NCOL;
        for (int o = t; o < 256 * NCOL; o += THREADS) {
            const int rr = o / NCOL, cc = o % NCOL;
            const int m = mb * 512 + (rr >> 7) * 256 + rankf * 128 + (rr & 127);
            if (MODE == 0) {
                float accg = 0.f, accu = 0.f;
                for (int k = 0; k < KTOT; k++) {
                    float a = rd_a(g_x16, KT1, m, k);
                    accg += a * rd_b8(g_wgu8, KT1, nb, cc, k, BTILE1R, 128);
                    accu += a * rd_b8(g_wgu8, KT1, nb, 128 + cc, k, BTILE1R, 128);
                }
                float g = accg * S[n0 + cc], u = accu * S[INTER + n0 + cc];
                float hv = g / (1.0f + __expf(-g)) * u;
                const int col = n0 + cc;
                const int mm = m & 511;
                const int rank2 = (mm >> 7) & 1;
                const int wr2 = ((mm >> 8) << 7) | (mm & 127);
                char* p = reinterpret_cast<char*>(g_h16)
                        + ((size_t)(m >> 9) * KT2 + (col >> 6)) * ATILE + rank2 * 32768
                        + swz((uint32_t)(wr2 * 128 + ((col & 63) >> 3) * 16)) + (col & 7) * 2;
                *reinterpret_cast<__half*>(p) = __float2half_rn(hv);
            } else {
                float acc = 0.f;
                for (int k = 0; k < KTOT; k++)
                    acc += rd_a(g_h16, KT2, m, k) * rd_b8(g_wd8, KT2, nb, cc, k, BTILE2R, 112);
                Out[(size_t)m * HIDDEN + n0 + cc] = acc * S[n0 + cc];
            }
        }
    }
#endif
}

// ---------------------------------------------------------------------------
// launch
// ---------------------------------------------------------------------------
extern "C" void kernel_launch(void* const* d_in, const int* in_sizes, int n_in,
                              void* d_out, int out_size)
{
    const float* x = nullptr; const float* w_gu = nullptr; const float* s_gu = nullptr;
    const float* w_d = nullptr; const float* s_d = nullptr;
    for (int i = 0; i < n_in; i++) {
        long long sz = in_sizes[i];
        const float* p = (const float*)d_in[i];
        if      (sz == (long long)TOKENS * HIDDEN)    x    = p;
        else if (sz == (long long)2 * INTER * HIDDEN) w_gu = p;
        else if (sz == (long long)2 * INTER)          s_gu = p;
        else if (sz == (long long)HIDDEN * INTER)     w_d  = p;
        else if (sz == (long long)HIDDEN)             s_d  = p;
    }
    float* out = (float*)d_out;

    constexpr int SMEM0 = 1024 + NSTG * (A_BYTES + BB1 + BR1);  // 230,400
    constexpr int SMEM1 = 1024 + NSTG * (A_BYTES + BB2 + BR2);  // 218,112
    cudaFuncSetAttribute(mlp_gemm<0>, cudaFuncAttributeMaxDynamicSharedMemorySize, SMEM0);
    cudaFuncSetAttribute(mlp_gemm<1>, cudaFuncAttributeMaxDynamicSharedMemorySize, SMEM1);

    // prep: w_gu -> fp8 tiles + x -> fp16 tiles, one launch
    conv_prep<<<(WGU_CHUNKS + X_CHUNKS) / 256, 256>>>(w_gu, x);

    // GEMM1: gate_up + SiLU*Mul -> g_h16 tiles; w_d conversion rides along
    mlp_gemm<0><<<dim3(2 * NPAIRS, 1), THREADS, SMEM0>>>(s_gu, nullptr, w_d);

    // GEMM2: down -> out
    mlp_gemm<1><<<dim3(2 * NPAIRS, 1), THREADS, SMEM1>>>(s_d, out, nullptr);
}